// round 5
// baseline (speedup 1.0000x reference)
#include <cuda_runtime.h>
#include <cuda_bf16.h>
#include <math.h>

#define BB    2
#define NN    2048
#define DIM   512
#define HH    8
#define DH    64
#define INNER 512
#define QKV3  1536
#define MROWS (BB*NN)      // 4096

typedef __nv_bfloat16 bf16;

// ---------------- device scratch (no allocation allowed) ----------------
__device__ bf16 g_x_h[MROWS * DIM],    g_x_l[MROWS * DIM];
__device__ bf16 g_wqkv_h[DIM * QKV3],  g_wqkv_l[DIM * QKV3];
__device__ bf16 g_wout_h[INNER * DIM], g_wout_l[INNER * DIM];
__device__ bf16 g_qkv_h[MROWS * QKV3], g_qkv_l[MROWS * QKV3];
__device__ bf16 g_att_h[MROWS * INNER], g_att_l[MROWS * INNER];

// ---------------- helpers ----------------
__device__ __forceinline__ unsigned s2u(const void* p) {
    return (unsigned)__cvta_generic_to_shared(p);
}
__device__ __forceinline__ void ldsm4(unsigned* r, const void* p) {
    asm volatile("ldmatrix.sync.aligned.m8n8.x4.shared.b16 {%0,%1,%2,%3}, [%4];"
        : "=r"(r[0]), "=r"(r[1]), "=r"(r[2]), "=r"(r[3]) : "r"(s2u(p)));
}
__device__ __forceinline__ void ldsm4t(unsigned* r, const void* p) {
    asm volatile("ldmatrix.sync.aligned.m8n8.x4.trans.shared.b16 {%0,%1,%2,%3}, [%4];"
        : "=r"(r[0]), "=r"(r[1]), "=r"(r[2]), "=r"(r[3]) : "r"(s2u(p)));
}
__device__ __forceinline__ void cp16(void* s, const void* g) {
    asm volatile("cp.async.cg.shared.global [%0], [%1], 16;" :: "r"(s2u(s)), "l"(g));
}
__device__ __forceinline__ void cp_commit() { asm volatile("cp.async.commit_group;"); }
template<int N> __device__ __forceinline__ void cp_wait() {
    asm volatile("cp.async.wait_group %0;" :: "n"(N));
}
__device__ __forceinline__ void mma_bf16(float* c, const unsigned* a, unsigned b0, unsigned b1) {
    asm volatile(
        "mma.sync.aligned.m16n8k16.row.col.f32.bf16.bf16.f32 "
        "{%0,%1,%2,%3}, {%4,%5,%6,%7}, {%8,%9}, {%0,%1,%2,%3};"
        : "+f"(c[0]), "+f"(c[1]), "+f"(c[2]), "+f"(c[3])
        : "r"(a[0]), "r"(a[1]), "r"(a[2]), "r"(a[3]), "r"(b0), "r"(b1));
}
__device__ __forceinline__ unsigned pack2(bf16 a, bf16 b) {
    __nv_bfloat162 v; v.x = a; v.y = b;
    return *reinterpret_cast<unsigned*>(&v);
}
__device__ __forceinline__ void split1(float v, bf16& h, bf16& l) {
    h = __float2bfloat16(v);
    l = __float2bfloat16(v - __bfloat162float(h));
}

// ---------------- prep: fp32 -> bf16 hi/lo split ----------------
__global__ void split_kernel(const float* __restrict__ src, bf16* __restrict__ hi,
                             bf16* __restrict__ lo, int n)
{
    for (int i = blockIdx.x * blockDim.x + threadIdx.x; i < n; i += gridDim.x * blockDim.x) {
        float v = src[i];
        bf16 h, l; split1(v, h, l);
        hi[i] = h; lo[i] = l;
    }
}

// ---------------------------------------------------------------------------
// bf16x3 GEMM, 128x128 block, BK=32, 256 thr (8 warps; warp tile 32x64).
// cp.async double-buffered; ldmatrix fragments; pass-major MMA ordering so
// dependent MMAs to the same accumulator are 16 apart.
// ---------------------------------------------------------------------------
#define GALD 40
#define GBLD 136
#define G_SA(buf,hl) (sm + ((buf)*2 + (hl)) * (128*GALD))
#define G_SB(buf,hl) (sm + 4*128*GALD + ((buf)*2 + (hl)) * (32*GBLD))
#define GEMM_SMEM_BYTES ((4*128*GALD + 4*32*GBLD) * 2)

__global__ __launch_bounds__(256, 1) void gemm_mma(const bf16* __restrict__ Ah,
                                                   const bf16* __restrict__ Al,
                                                   const bf16* __restrict__ Bh,
                                                   const bf16* __restrict__ Bl,
                                                   const float* __restrict__ bias,
                                                   float* __restrict__ outf,
                                                   bf16* __restrict__ outh,
                                                   bf16* __restrict__ outl,
                                                   int M, int N, int K, int mode)
{
    extern __shared__ bf16 sm[];

    const int bm = blockIdx.y * 128;
    const int bn = blockIdx.x * 128;
    const int tid = threadIdx.x;
    const int warp = tid >> 5;
    const int lane = tid & 31;
    const int g = lane >> 2;
    const int t = lane & 3;
    const int rowbase = (warp & 3) * 32;
    const int colbase = (warp >> 2) * 64;

    float acc[2][8][4];
#pragma unroll
    for (int mt = 0; mt < 2; mt++)
#pragma unroll
        for (int nt = 0; nt < 8; nt++)
#pragma unroll
            for (int i = 0; i < 4; i++) acc[mt][nt][i] = 0.0f;

    const int tile = lane >> 3;
    const int trow = lane & 7;

    auto prefetch = [&](int buf, int k0) {
#pragma unroll
        for (int j = 0; j < 2; j++) {
            int c = tid * 2 + j;                 // 0..511
            int row = c >> 2, kch = (c & 3) * 8;
            size_t go = (size_t)(bm + row) * K + k0 + kch;
            cp16(&G_SA(buf, 0)[row * GALD + kch], &Ah[go]);
            cp16(&G_SA(buf, 1)[row * GALD + kch], &Al[go]);
        }
#pragma unroll
        for (int j = 0; j < 2; j++) {
            int c = tid * 2 + j;
            int kr = c >> 4, nch = (c & 15) * 8;
            size_t go = (size_t)(k0 + kr) * N + bn + nch;
            cp16(&G_SB(buf, 0)[kr * GBLD + nch], &Bh[go]);
            cp16(&G_SB(buf, 1)[kr * GBLD + nch], &Bl[go]);
        }
    };

    prefetch(0, 0);
    cp_commit();

    const int NIT = K / 32;
    int buf = 0;
    for (int it = 0; it < NIT; it++) {
        if (it + 1 < NIT) { prefetch(buf ^ 1, (it + 1) * 32); cp_commit(); cp_wait<1>(); }
        else cp_wait<0>();
        __syncthreads();

        const bf16* As_h = G_SA(buf, 0);
        const bf16* As_l = G_SA(buf, 1);
        const bf16* Bs_h = G_SB(buf, 0);
        const bf16* Bs_l = G_SB(buf, 1);

#pragma unroll
        for (int kc = 0; kc < 2; kc++) {
            unsigned ah[2][4], al[2][4];
            const int amrow = (tile & 1) * 8 + trow;
            const int akoff = kc * 16 + (tile >> 1) * 8;
#pragma unroll
            for (int mt = 0; mt < 2; mt++) {
                ldsm4(ah[mt], &As_h[(rowbase + mt * 16 + amrow) * GALD + akoff]);
                ldsm4(al[mt], &As_l[(rowbase + mt * 16 + amrow) * GALD + akoff]);
            }
            const int bkrow = kc * 16 + (tile & 1) * 8 + trow;
            unsigned bh[4][4], bl[4][4];
#pragma unroll
            for (int ntp = 0; ntp < 4; ntp++) {
                const int bncol = colbase + ntp * 16 + (tile >> 1) * 8;
                ldsm4t(bh[ntp], &Bs_h[bkrow * GBLD + bncol]);
                ldsm4t(bl[ntp], &Bs_l[bkrow * GBLD + bncol]);
            }
            // pass 1: Ah*Bh  (16 independent accumulators)
#pragma unroll
            for (int mt = 0; mt < 2; mt++)
#pragma unroll
                for (int ntp = 0; ntp < 4; ntp++)
#pragma unroll
                    for (int q = 0; q < 2; q++)
                        mma_bf16(acc[mt][ntp * 2 + q], ah[mt], bh[ntp][q * 2], bh[ntp][q * 2 + 1]);
            // pass 2: Ah*Bl
#pragma unroll
            for (int mt = 0; mt < 2; mt++)
#pragma unroll
                for (int ntp = 0; ntp < 4; ntp++)
#pragma unroll
                    for (int q = 0; q < 2; q++)
                        mma_bf16(acc[mt][ntp * 2 + q], ah[mt], bl[ntp][q * 2], bl[ntp][q * 2 + 1]);
            // pass 3: Al*Bh
#pragma unroll
            for (int mt = 0; mt < 2; mt++)
#pragma unroll
                for (int ntp = 0; ntp < 4; ntp++)
#pragma unroll
                    for (int q = 0; q < 2; q++)
                        mma_bf16(acc[mt][ntp * 2 + q], al[mt], bh[ntp][q * 2], bh[ntp][q * 2 + 1]);
        }
        __syncthreads();
        buf ^= 1;
    }

    // epilogue
#pragma unroll
    for (int mt = 0; mt < 2; mt++) {
        const int r0 = bm + rowbase + mt * 16 + g;
        const int r1 = r0 + 8;
#pragma unroll
        for (int nt = 0; nt < 8; nt++) {
            const int c0 = bn + colbase + nt * 8 + 2 * t;
            float v0 = acc[mt][nt][0], v1 = acc[mt][nt][1];
            float v2 = acc[mt][nt][2], v3 = acc[mt][nt][3];
            if (mode == 0) {
                float b0 = bias[c0], b1 = bias[c0 + 1];
                *reinterpret_cast<float2*>(&outf[(size_t)r0 * N + c0]) = make_float2(v0 + b0, v1 + b1);
                *reinterpret_cast<float2*>(&outf[(size_t)r1 * N + c0]) = make_float2(v2 + b0, v3 + b1);
            } else {
                bf16 h0, l0, h1, l1, h2, l2, h3, l3;
                split1(v0, h0, l0); split1(v1, h1, l1);
                split1(v2, h2, l2); split1(v3, h3, l3);
                *reinterpret_cast<unsigned*>(&outh[(size_t)r0 * N + c0]) = pack2(h0, h1);
                *reinterpret_cast<unsigned*>(&outl[(size_t)r0 * N + c0]) = pack2(l0, l1);
                *reinterpret_cast<unsigned*>(&outh[(size_t)r1 * N + c0]) = pack2(h2, h3);
                *reinterpret_cast<unsigned*>(&outl[(size_t)r1 * N + c0]) = pack2(l2, l3);
            }
        }
    }
}

// ---------------------------------------------------------------------------
// Attention: 128 q-rows/block, 64-key tiles, cp.async double-buffered K/V,
// ldmatrix fragments, register-resident P, pass-major MMA ordering.
// ---------------------------------------------------------------------------
#define ASLD 72
#define A_Q(hl)     (sm + (hl) * (128 * ASLD))
#define A_KV(buf,m) (sm + 2 * 128 * ASLD + ((buf) * 4 + (m)) * (64 * ASLD))
#define ATT_BF16_TOT (2 * 128 * ASLD + 8 * 64 * ASLD)
#define ATT_SMEM_BYTES (ATT_BF16_TOT * 2 + 2 * 2 * 64 * 4)

__global__ __launch_bounds__(256, 1) void attn_mma(const bf16* __restrict__ qh,
                                                   const bf16* __restrict__ ql,
                                                   const int* __restrict__ mask_np,
                                                   const int* __restrict__ mask_bert,
                                                   bf16* __restrict__ outh,
                                                   bf16* __restrict__ outl)
{
    extern __shared__ char smraw[];
    bf16* sm = reinterpret_cast<bf16*>(smraw);
    int* mint = reinterpret_cast<int*>(smraw + ATT_BF16_TOT * 2);
    auto m_np = [&](int buf) { return mint + buf * 128; };
    auto m_bt = [&](int buf) { return mint + buf * 128 + 64; };

    const int b  = blockIdx.y >> 3;
    const int h  = blockIdx.y & 7;
    const int q0 = blockIdx.x * 128;
    const int tid = threadIdx.x;
    const int warp = tid >> 5;
    const int lane = tid & 31;
    const int g = lane >> 2;
    const int t = lane & 3;
    const int rb = warp * 16;
    const float scale = 0.125f;
    const int tile = lane >> 3;
    const int trow = lane & 7;

    // Q prefetch (group 0)
#pragma unroll
    for (int j = 0; j < 4; j++) {
        int c = tid * 4 + j;                  // 0..1023
        int row = c >> 3, dch = (c & 7) * 8;
        size_t base = (size_t)(b * NN + q0 + row) * QKV3 + h * 64 + dch;
        cp16(&A_Q(0)[row * ASLD + dch], &qh[base]);
        cp16(&A_Q(1)[row * ASLD + dch], &ql[base]);
    }
    cp_commit();

    auto pref = [&](int buf, int kt0) {
#pragma unroll
        for (int j = 0; j < 2; j++) {
            int c = tid * 2 + j;              // 0..511
            int row = c >> 3, dch = (c & 7) * 8;
            size_t kb = (size_t)(b * NN + kt0 + row) * QKV3 + INNER + h * 64 + dch;
            size_t vb = kb + INNER;
            cp16(&A_KV(buf, 0)[row * ASLD + dch], &qh[kb]);
            cp16(&A_KV(buf, 1)[row * ASLD + dch], &ql[kb]);
            cp16(&A_KV(buf, 2)[row * ASLD + dch], &qh[vb]);
            cp16(&A_KV(buf, 3)[row * ASLD + dch], &ql[vb]);
        }
        if (tid < 16) {
            cp16(&m_np(buf)[tid * 4], &mask_np[b * NN + kt0 + tid * 4]);
            cp16(&m_bt(buf)[tid * 4], &mask_bert[b * NN + kt0 + tid * 4]);
        }
    };
    pref(0, 0);
    cp_commit();

    const int rowbad0 = (mask_np[b * NN + q0 + rb + g] == 0);
    const int rowbad8 = (mask_np[b * NN + q0 + rb + g + 8] == 0);
    const float shift0 = rowbad0 ? 1000.0f : 0.0f;
    const float shift8 = rowbad8 ? 1000.0f : 0.0f;

    float O[8][4];
#pragma unroll
    for (int nt = 0; nt < 8; nt++)
#pragma unroll
        for (int i = 0; i < 4; i++) O[nt][i] = 0.0f;
    float lsum0 = 0.0f, lsum8 = 0.0f;

    unsigned aqh[4][4], aql[4][4];

    int buf = 0;
    for (int kt = 0; kt < NN / 64; kt++) {
        if (kt + 1 < NN / 64) { pref(buf ^ 1, (kt + 1) * 64); cp_commit(); cp_wait<1>(); }
        else cp_wait<0>();
        __syncthreads();

        if (kt == 0) {
            const int qr = rb + (tile & 1) * 8 + trow;
#pragma unroll
            for (int kc = 0; kc < 4; kc++) {
                ldsm4(aqh[kc], &A_Q(0)[qr * ASLD + kc * 16 + (tile >> 1) * 8]);
                ldsm4(aql[kc], &A_Q(1)[qr * ASLD + kc * 16 + (tile >> 1) * 8]);
            }
        }

        const bf16* KHs = A_KV(buf, 0);
        const bf16* KLs = A_KV(buf, 1);
        const bf16* VHs = A_KV(buf, 2);
        const bf16* VLs = A_KV(buf, 3);
        const int* np = m_np(buf);
        const int* bt = m_bt(buf);

        // ---- QK: kc-outer, pass-major (8 independent score accumulators) ----
        float sc[8][4];
#pragma unroll
        for (int nt = 0; nt < 8; nt++)
#pragma unroll
            for (int i = 0; i < 4; i++) sc[nt][i] = 0.0f;

#pragma unroll
        for (int kc = 0; kc < 4; kc++) {
            const int koff = kc * 16 + (tile & 1) * 8;
            unsigned kbh[4][4], kbl[4][4];
#pragma unroll
            for (int ntp = 0; ntp < 4; ntp++) {
                const int nrow = ntp * 16 + (tile >> 1) * 8 + trow;
                ldsm4(kbh[ntp], &KHs[nrow * ASLD + koff]);
                ldsm4(kbl[ntp], &KLs[nrow * ASLD + koff]);
            }
#pragma unroll
            for (int ntp = 0; ntp < 4; ntp++)
#pragma unroll
                for (int q = 0; q < 2; q++)
                    mma_bf16(sc[ntp * 2 + q], aqh[kc], kbh[ntp][q * 2], kbh[ntp][q * 2 + 1]);
#pragma unroll
            for (int ntp = 0; ntp < 4; ntp++)
#pragma unroll
                for (int q = 0; q < 2; q++)
                    mma_bf16(sc[ntp * 2 + q], aqh[kc], kbl[ntp][q * 2], kbl[ntp][q * 2 + 1]);
#pragma unroll
            for (int ntp = 0; ntp < 4; ntp++)
#pragma unroll
                for (int q = 0; q < 2; q++)
                    mma_bf16(sc[ntp * 2 + q], aql[kc], kbh[ntp][q * 2], kbh[ntp][q * 2 + 1]);
        }

        // ---- softmax -> register P fragments ----
        unsigned pah[4][4], pal[4][4];
#pragma unroll
        for (int nt = 0; nt < 8; nt++) {
            const int ntp = nt >> 1, q = nt & 1;
            const int col0 = nt * 8 + 2 * t;
            const int cb0 = (np[col0] == 0) | (bt[col0] == 1);
            const int cb1 = (np[col0 + 1] == 0) | (bt[col0 + 1] == 1);
            float x0 = (cb0 | rowbad0) ? -1000.0f : sc[nt][0] * scale;
            float x1 = (cb1 | rowbad0) ? -1000.0f : sc[nt][1] * scale;
            float x2 = (cb0 | rowbad8) ? -1000.0f : sc[nt][2] * scale;
            float x3 = (cb1 | rowbad8) ? -1000.0f : sc[nt][3] * scale;
            float p0 = __expf(x0 + shift0);
            float p1 = __expf(x1 + shift0);
            float p2 = __expf(x2 + shift8);
            float p3 = __expf(x3 + shift8);
            lsum0 += p0 + p1;
            lsum8 += p2 + p3;
            bf16 h0, l0, h1, l1, h2, l2, h3, l3;
            split1(p0, h0, l0); split1(p1, h1, l1);
            split1(p2, h2, l2); split1(p3, h3, l3);
            pah[ntp][q * 2 + 0] = pack2(h0, h1);
            pah[ntp][q * 2 + 1] = pack2(h2, h3);
            pal[ntp][q * 2 + 0] = pack2(l0, l1);
            pal[ntp][q * 2 + 1] = pack2(l2, l3);
        }

        // ---- PV: kch-outer, pass-major (8 independent O accumulators) ----
#pragma unroll
        for (int kch = 0; kch < 4; kch++) {
            const int keyrow = kch * 16 + (tile & 1) * 8 + trow;
            unsigned vh[4][4], vl[4][4];
#pragma unroll
            for (int dp = 0; dp < 4; dp++) {
                const int dcol = dp * 16 + (tile >> 1) * 8;
                ldsm4t(vh[dp], &VHs[keyrow * ASLD + dcol]);
                ldsm4t(vl[dp], &VLs[keyrow * ASLD + dcol]);
            }
#pragma unroll
            for (int dp = 0; dp < 4; dp++)
#pragma unroll
                for (int q = 0; q < 2; q++)
                    mma_bf16(O[dp * 2 + q], pah[kch], vh[dp][q * 2], vh[dp][q * 2 + 1]);
#pragma unroll
            for (int dp = 0; dp < 4; dp++)
#pragma unroll
                for (int q = 0; q < 2; q++)
                    mma_bf16(O[dp * 2 + q], pah[kch], vl[dp][q * 2], vl[dp][q * 2 + 1]);
#pragma unroll
            for (int dp = 0; dp < 4; dp++)
#pragma unroll
                for (int q = 0; q < 2; q++)
                    mma_bf16(O[dp * 2 + q], pal[kch], vh[dp][q * 2], vh[dp][q * 2 + 1]);
        }
        __syncthreads();
        buf ^= 1;
    }

    // epilogue: quad-reduce l, normalize, split-store
    lsum0 += __shfl_xor_sync(0xffffffffu, lsum0, 1);
    lsum0 += __shfl_xor_sync(0xffffffffu, lsum0, 2);
    lsum8 += __shfl_xor_sync(0xffffffffu, lsum8, 1);
    lsum8 += __shfl_xor_sync(0xffffffffu, lsum8, 2);
    const float inv0 = 1.0f / lsum0;
    const float inv8 = 1.0f / lsum8;

    const size_t row0 = (size_t)(b * NN + q0 + rb + g);
    const size_t row8 = row0 + 8;
#pragma unroll
    for (int nt = 0; nt < 8; nt++) {
        const int d = h * 64 + nt * 8 + 2 * t;
        float v0 = O[nt][0] * inv0, v1 = O[nt][1] * inv0;
        float v2 = O[nt][2] * inv8, v3 = O[nt][3] * inv8;
        bf16 h0, l0, h1, l1, h2, l2, h3, l3;
        split1(v0, h0, l0); split1(v1, h1, l1);
        split1(v2, h2, l2); split1(v3, h3, l3);
        *reinterpret_cast<unsigned*>(&outh[row0 * INNER + d]) = pack2(h0, h1);
        *reinterpret_cast<unsigned*>(&outl[row0 * INNER + d]) = pack2(l0, l1);
        *reinterpret_cast<unsigned*>(&outh[row8 * INNER + d]) = pack2(h2, h3);
        *reinterpret_cast<unsigned*>(&outl[row8 * INNER + d]) = pack2(l2, l3);
    }
}

// ---------------------------------------------------------------------------
extern "C" void kernel_launch(void* const* d_in, const int* in_sizes, int n_in,
                              void* d_out, int out_size)
{
    const float* x     = (const float*)d_in[0];
    const int*   mnp   = (const int*)d_in[1];
    const int*   mbert = (const int*)d_in[2];
    const float* Wqkv  = (const float*)d_in[3];
    const float* Wout  = (const float*)d_in[4];
    const float* bout  = (const float*)d_in[5];
    float* out = (float*)d_out;

    bf16 *xh, *xl, *wqh, *wql, *woh, *wol, *qkvh, *qkvl, *ath, *atl;
    cudaGetSymbolAddress((void**)&xh,   g_x_h);
    cudaGetSymbolAddress((void**)&xl,   g_x_l);
    cudaGetSymbolAddress((void**)&wqh,  g_wqkv_h);
    cudaGetSymbolAddress((void**)&wql,  g_wqkv_l);
    cudaGetSymbolAddress((void**)&woh,  g_wout_h);
    cudaGetSymbolAddress((void**)&wol,  g_wout_l);
    cudaGetSymbolAddress((void**)&qkvh, g_qkv_h);
    cudaGetSymbolAddress((void**)&qkvl, g_qkv_l);
    cudaGetSymbolAddress((void**)&ath,  g_att_h);
    cudaGetSymbolAddress((void**)&atl,  g_att_l);

    cudaFuncSetAttribute(gemm_mma, cudaFuncAttributeMaxDynamicSharedMemorySize,
                         GEMM_SMEM_BYTES);
    cudaFuncSetAttribute(attn_mma, cudaFuncAttributeMaxDynamicSharedMemorySize,
                         ATT_SMEM_BYTES);

    // prep: split inputs into bf16 hi/lo
    split_kernel<<<512, 256>>>(x,    xh,  xl,  MROWS * DIM);
    split_kernel<<<512, 256>>>(Wqkv, wqh, wql, DIM * QKV3);
    split_kernel<<<256, 256>>>(Wout, woh, wol, INNER * DIM);

    // 1) qkv = x @ W_qkv  -> bf16 hi/lo
    gemm_mma<<<dim3(QKV3 / 128, MROWS / 128), 256, GEMM_SMEM_BYTES>>>(
        xh, xl, wqh, wql, nullptr, nullptr, qkvh, qkvl, MROWS, QKV3, DIM, 1);

    // 2) masked attention -> bf16 hi/lo
    attn_mma<<<dim3(NN / 128, BB * HH), 256, ATT_SMEM_BYTES>>>(
        qkvh, qkvl, mnp, mbert, ath, atl);

    // 3) out = att @ W_out + b_out  -> fp32
    gemm_mma<<<dim3(DIM / 128, MROWS / 128), 256, GEMM_SMEM_BYTES>>>(
        ath, atl, woh, wol, bout, out, nullptr, nullptr, MROWS, DIM, INNER, 0);
}

// round 6
// speedup vs baseline: 1.0657x; 1.0657x over previous
#include <cuda_runtime.h>
#include <cuda_bf16.h>
#include <math.h>

#define BB    2
#define NN    2048
#define DIM   512
#define HH    8
#define DH    64
#define INNER 512
#define QKV3  1536
#define MROWS (BB*NN)      // 4096

typedef __nv_bfloat16 bf16;

// ---------------- device scratch (no allocation allowed) ----------------
__device__ bf16 g_x_h[MROWS * DIM],    g_x_l[MROWS * DIM];
__device__ bf16 g_wqkv_h[DIM * QKV3],  g_wqkv_l[DIM * QKV3];
__device__ bf16 g_wout_h[INNER * DIM], g_wout_l[INNER * DIM];
__device__ bf16 g_qkv_h[MROWS * QKV3], g_qkv_l[MROWS * QKV3];
__device__ bf16 g_att_h[MROWS * INNER], g_att_l[MROWS * INNER];

// ---------------- helpers ----------------
__device__ __forceinline__ unsigned s2u(const void* p) {
    return (unsigned)__cvta_generic_to_shared(p);
}
__device__ __forceinline__ void ldsm4(unsigned* r, const void* p) {
    asm volatile("ldmatrix.sync.aligned.m8n8.x4.shared.b16 {%0,%1,%2,%3}, [%4];"
        : "=r"(r[0]), "=r"(r[1]), "=r"(r[2]), "=r"(r[3]) : "r"(s2u(p)));
}
__device__ __forceinline__ void ldsm4t(unsigned* r, const void* p) {
    asm volatile("ldmatrix.sync.aligned.m8n8.x4.trans.shared.b16 {%0,%1,%2,%3}, [%4];"
        : "=r"(r[0]), "=r"(r[1]), "=r"(r[2]), "=r"(r[3]) : "r"(s2u(p)));
}
__device__ __forceinline__ void cp16(void* s, const void* g) {
    asm volatile("cp.async.cg.shared.global [%0], [%1], 16;" :: "r"(s2u(s)), "l"(g));
}
__device__ __forceinline__ void cp_commit() { asm volatile("cp.async.commit_group;"); }
template<int N> __device__ __forceinline__ void cp_wait() {
    asm volatile("cp.async.wait_group %0;" :: "n"(N));
}
__device__ __forceinline__ void mma_bf16(float* c, const unsigned* a, unsigned b0, unsigned b1) {
    asm volatile(
        "mma.sync.aligned.m16n8k16.row.col.f32.bf16.bf16.f32 "
        "{%0,%1,%2,%3}, {%4,%5,%6,%7}, {%8,%9}, {%0,%1,%2,%3};"
        : "+f"(c[0]), "+f"(c[1]), "+f"(c[2]), "+f"(c[3])
        : "r"(a[0]), "r"(a[1]), "r"(a[2]), "r"(a[3]), "r"(b0), "r"(b1));
}
__device__ __forceinline__ unsigned pack2(bf16 a, bf16 b) {
    __nv_bfloat162 v; v.x = a; v.y = b;
    return *reinterpret_cast<unsigned*>(&v);
}
__device__ __forceinline__ void split1(float v, bf16& h, bf16& l) {
    h = __float2bfloat16(v);
    l = __float2bfloat16(v - __bfloat162float(h));
}

// ---------------- prep: fp32 -> bf16 hi/lo split ----------------
__global__ void split_kernel(const float* __restrict__ src, bf16* __restrict__ hi,
                             bf16* __restrict__ lo, int n)
{
    for (int i = blockIdx.x * blockDim.x + threadIdx.x; i < n; i += gridDim.x * blockDim.x) {
        float v = src[i];
        bf16 h, l; split1(v, h, l);
        hi[i] = h; lo[i] = l;
    }
}

// ---------------------------------------------------------------------------
// bf16x3 GEMM, 128x128 block, BK=32, 512 thr (16 warps; warp tile 32x32).
// cp.async double-buffered; ldmatrix fragments.
// ---------------------------------------------------------------------------
#define GALD 40
#define GBLD 136
#define G_SA(buf,hl) (sm + ((buf)*2 + (hl)) * (128*GALD))
#define G_SB(buf,hl) (sm + 4*128*GALD + ((buf)*2 + (hl)) * (32*GBLD))
#define GEMM_SMEM_BYTES ((4*128*GALD + 4*32*GBLD) * 2)

__global__ __launch_bounds__(512, 1) void gemm_mma(const bf16* __restrict__ Ah,
                                                   const bf16* __restrict__ Al,
                                                   const bf16* __restrict__ Bh,
                                                   const bf16* __restrict__ Bl,
                                                   const float* __restrict__ bias,
                                                   float* __restrict__ outf,
                                                   bf16* __restrict__ outh,
                                                   bf16* __restrict__ outl,
                                                   int M, int N, int K, int mode)
{
    extern __shared__ bf16 sm[];

    const int bm = blockIdx.y * 128;
    const int bn = blockIdx.x * 128;
    const int tid = threadIdx.x;
    const int warp = tid >> 5;
    const int lane = tid & 31;
    const int g = lane >> 2;
    const int t = lane & 3;
    const int rowbase = (warp & 3) * 32;      // 4 row groups of 32
    const int colbase = (warp >> 2) * 32;     // 4 col groups of 32

    float acc[2][4][4];
#pragma unroll
    for (int mt = 0; mt < 2; mt++)
#pragma unroll
        for (int nt = 0; nt < 4; nt++)
#pragma unroll
            for (int i = 0; i < 4; i++) acc[mt][nt][i] = 0.0f;

    const int tile = lane >> 3;
    const int trow = lane & 7;

    auto prefetch = [&](int buf, int k0) {
        {
            int c = tid;                         // 0..511
            int row = c >> 2, kch = (c & 3) * 8;
            size_t go = (size_t)(bm + row) * K + k0 + kch;
            cp16(&G_SA(buf, 0)[row * GALD + kch], &Ah[go]);
            cp16(&G_SA(buf, 1)[row * GALD + kch], &Al[go]);
        }
        {
            int c = tid;
            int kr = c >> 4, nch = (c & 15) * 8;
            size_t go = (size_t)(k0 + kr) * N + bn + nch;
            cp16(&G_SB(buf, 0)[kr * GBLD + nch], &Bh[go]);
            cp16(&G_SB(buf, 1)[kr * GBLD + nch], &Bl[go]);
        }
    };

    prefetch(0, 0);
    cp_commit();

    const int NIT = K / 32;
    int buf = 0;
    for (int it = 0; it < NIT; it++) {
        if (it + 1 < NIT) { prefetch(buf ^ 1, (it + 1) * 32); cp_commit(); cp_wait<1>(); }
        else cp_wait<0>();
        __syncthreads();

        const bf16* As_h = G_SA(buf, 0);
        const bf16* As_l = G_SA(buf, 1);
        const bf16* Bs_h = G_SB(buf, 0);
        const bf16* Bs_l = G_SB(buf, 1);

#pragma unroll
        for (int kc = 0; kc < 2; kc++) {
            unsigned ah[2][4], al[2][4];
            const int amrow = (tile & 1) * 8 + trow;
            const int akoff = kc * 16 + (tile >> 1) * 8;
#pragma unroll
            for (int mt = 0; mt < 2; mt++) {
                ldsm4(ah[mt], &As_h[(rowbase + mt * 16 + amrow) * GALD + akoff]);
                ldsm4(al[mt], &As_l[(rowbase + mt * 16 + amrow) * GALD + akoff]);
            }
            const int bkrow = kc * 16 + (tile & 1) * 8 + trow;
            unsigned bh[2][4], bl[2][4];
#pragma unroll
            for (int ntp = 0; ntp < 2; ntp++) {
                const int bncol = colbase + ntp * 16 + (tile >> 1) * 8;
                ldsm4t(bh[ntp], &Bs_h[bkrow * GBLD + bncol]);
                ldsm4t(bl[ntp], &Bs_l[bkrow * GBLD + bncol]);
            }
#pragma unroll
            for (int mt = 0; mt < 2; mt++)
#pragma unroll
                for (int ntp = 0; ntp < 2; ntp++)
#pragma unroll
                    for (int q = 0; q < 2; q++)
                        mma_bf16(acc[mt][ntp * 2 + q], ah[mt], bh[ntp][q * 2], bh[ntp][q * 2 + 1]);
#pragma unroll
            for (int mt = 0; mt < 2; mt++)
#pragma unroll
                for (int ntp = 0; ntp < 2; ntp++)
#pragma unroll
                    for (int q = 0; q < 2; q++)
                        mma_bf16(acc[mt][ntp * 2 + q], ah[mt], bl[ntp][q * 2], bl[ntp][q * 2 + 1]);
#pragma unroll
            for (int mt = 0; mt < 2; mt++)
#pragma unroll
                for (int ntp = 0; ntp < 2; ntp++)
#pragma unroll
                    for (int q = 0; q < 2; q++)
                        mma_bf16(acc[mt][ntp * 2 + q], al[mt], bh[ntp][q * 2], bh[ntp][q * 2 + 1]);
        }
        __syncthreads();
        buf ^= 1;
    }

    // epilogue
#pragma unroll
    for (int mt = 0; mt < 2; mt++) {
        const int r0 = bm + rowbase + mt * 16 + g;
        const int r1 = r0 + 8;
#pragma unroll
        for (int nt = 0; nt < 4; nt++) {
            const int c0 = bn + colbase + nt * 8 + 2 * t;
            float v0 = acc[mt][nt][0], v1 = acc[mt][nt][1];
            float v2 = acc[mt][nt][2], v3 = acc[mt][nt][3];
            if (mode == 0) {
                float b0 = bias[c0], b1 = bias[c0 + 1];
                *reinterpret_cast<float2*>(&outf[(size_t)r0 * N + c0]) = make_float2(v0 + b0, v1 + b1);
                *reinterpret_cast<float2*>(&outf[(size_t)r1 * N + c0]) = make_float2(v2 + b0, v3 + b1);
            } else {
                bf16 h0, l0, h1, l1, h2, l2, h3, l3;
                split1(v0, h0, l0); split1(v1, h1, l1);
                split1(v2, h2, l2); split1(v3, h3, l3);
                *reinterpret_cast<unsigned*>(&outh[(size_t)r0 * N + c0]) = pack2(h0, h1);
                *reinterpret_cast<unsigned*>(&outl[(size_t)r0 * N + c0]) = pack2(l0, l1);
                *reinterpret_cast<unsigned*>(&outh[(size_t)r1 * N + c0]) = pack2(h2, h3);
                *reinterpret_cast<unsigned*>(&outl[(size_t)r1 * N + c0]) = pack2(l2, l3);
            }
        }
    }
}

// ---------------------------------------------------------------------------
// Attention: 512 thr (16 warps), 256 q-rows/block, 64-key tiles,
// cp.async double-buffered K/V, register-resident P, Q frags reloaded per kc.
// ---------------------------------------------------------------------------
#define ASLD 72
#define A_Q(hl)     (sm + (hl) * (256 * ASLD))
#define A_KV(buf,m) (sm + 2 * 256 * ASLD + ((buf) * 4 + (m)) * (64 * ASLD))
#define ATT_BF16_TOT (2 * 256 * ASLD + 8 * 64 * ASLD)
#define ATT_SMEM_BYTES (ATT_BF16_TOT * 2 + 2 * 2 * 64 * 4)

__global__ __launch_bounds__(512, 1) void attn_mma(const bf16* __restrict__ qh,
                                                   const bf16* __restrict__ ql,
                                                   const int* __restrict__ mask_np,
                                                   const int* __restrict__ mask_bert,
                                                   bf16* __restrict__ outh,
                                                   bf16* __restrict__ outl)
{
    extern __shared__ char smraw[];
    bf16* sm = reinterpret_cast<bf16*>(smraw);
    int* mint = reinterpret_cast<int*>(smraw + ATT_BF16_TOT * 2);
    auto m_np = [&](int buf) { return mint + buf * 128; };
    auto m_bt = [&](int buf) { return mint + buf * 128 + 64; };

    const int b  = blockIdx.y >> 3;
    const int h  = blockIdx.y & 7;
    const int q0 = blockIdx.x * 256;
    const int tid = threadIdx.x;
    const int warp = tid >> 5;
    const int lane = tid & 31;
    const int g = lane >> 2;
    const int t = lane & 3;
    const int rb = warp * 16;
    const float scale = 0.125f;
    const int tile = lane >> 3;
    const int trow = lane & 7;

    // Q prefetch: 256 rows x 64 dims, hi+lo
#pragma unroll
    for (int j = 0; j < 4; j++) {
        int c = tid * 4 + j;                  // 0..2047
        int row = c >> 3, dch = (c & 7) * 8;
        size_t base = (size_t)(b * NN + q0 + row) * QKV3 + h * 64 + dch;
        cp16(&A_Q(0)[row * ASLD + dch], &qh[base]);
        cp16(&A_Q(1)[row * ASLD + dch], &ql[base]);
    }
    cp_commit();

    auto pref = [&](int buf, int kt0) {
        {
            int c = tid;                      // 0..511
            int row = c >> 3, dch = (c & 7) * 8;
            size_t kb = (size_t)(b * NN + kt0 + row) * QKV3 + INNER + h * 64 + dch;
            size_t vb = kb + INNER;
            cp16(&A_KV(buf, 0)[row * ASLD + dch], &qh[kb]);
            cp16(&A_KV(buf, 1)[row * ASLD + dch], &ql[kb]);
            cp16(&A_KV(buf, 2)[row * ASLD + dch], &qh[vb]);
            cp16(&A_KV(buf, 3)[row * ASLD + dch], &ql[vb]);
        }
        if (tid < 16) {
            cp16(&m_np(buf)[tid * 4], &mask_np[b * NN + kt0 + tid * 4]);
            cp16(&m_bt(buf)[tid * 4], &mask_bert[b * NN + kt0 + tid * 4]);
        }
    };
    pref(0, 0);
    cp_commit();

    const int rowbad0 = (mask_np[b * NN + q0 + rb + g] == 0);
    const int rowbad8 = (mask_np[b * NN + q0 + rb + g + 8] == 0);
    const float shift0 = rowbad0 ? 1000.0f : 0.0f;
    const float shift8 = rowbad8 ? 1000.0f : 0.0f;

    float O[8][4];
#pragma unroll
    for (int nt = 0; nt < 8; nt++)
#pragma unroll
        for (int i = 0; i < 4; i++) O[nt][i] = 0.0f;
    float lsum0 = 0.0f, lsum8 = 0.0f;

    int buf = 0;
    for (int kt = 0; kt < NN / 64; kt++) {
        if (kt + 1 < NN / 64) { pref(buf ^ 1, (kt + 1) * 64); cp_commit(); cp_wait<1>(); }
        else cp_wait<0>();
        __syncthreads();

        const bf16* QHs = A_Q(0);
        const bf16* QLs = A_Q(1);
        const bf16* KHs = A_KV(buf, 0);
        const bf16* KLs = A_KV(buf, 1);
        const bf16* VHs = A_KV(buf, 2);
        const bf16* VLs = A_KV(buf, 3);
        const int* np = m_np(buf);
        const int* bt = m_bt(buf);

        unsigned pah[4][4], pal[4][4];    // P fragments per 16-key chunk

        const int qr = rb + (tile & 1) * 8 + trow;

        // two halves of 32 keys each: scores + softmax -> P frags
#pragma unroll
        for (int half = 0; half < 2; half++) {
            float sc[4][4];
#pragma unroll
            for (int nt = 0; nt < 4; nt++)
#pragma unroll
                for (int i = 0; i < 4; i++) sc[nt][i] = 0.0f;

#pragma unroll
            for (int kc = 0; kc < 4; kc++) {
                unsigned aqh[4], aql[4];
                ldsm4(aqh, &QHs[qr * ASLD + kc * 16 + (tile >> 1) * 8]);
                ldsm4(aql, &QLs[qr * ASLD + kc * 16 + (tile >> 1) * 8]);
                const int koff = kc * 16 + (tile & 1) * 8;
                unsigned kbh[2][4], kbl[2][4];
#pragma unroll
                for (int ntp = 0; ntp < 2; ntp++) {
                    const int nrow = (half * 2 + ntp) * 16 + (tile >> 1) * 8 + trow;
                    ldsm4(kbh[ntp], &KHs[nrow * ASLD + koff]);
                    ldsm4(kbl[ntp], &KLs[nrow * ASLD + koff]);
                }
#pragma unroll
                for (int ntp = 0; ntp < 2; ntp++)
#pragma unroll
                    for (int q = 0; q < 2; q++)
                        mma_bf16(sc[ntp * 2 + q], aqh, kbh[ntp][q * 2], kbh[ntp][q * 2 + 1]);
#pragma unroll
                for (int ntp = 0; ntp < 2; ntp++)
#pragma unroll
                    for (int q = 0; q < 2; q++)
                        mma_bf16(sc[ntp * 2 + q], aqh, kbl[ntp][q * 2], kbl[ntp][q * 2 + 1]);
#pragma unroll
                for (int ntp = 0; ntp < 2; ntp++)
#pragma unroll
                    for (int q = 0; q < 2; q++)
                        mma_bf16(sc[ntp * 2 + q], aql, kbh[ntp][q * 2], kbh[ntp][q * 2 + 1]);
            }

            // softmax on this half
#pragma unroll
            for (int ntl = 0; ntl < 4; ntl++) {
                const int nt = half * 4 + ntl;
                const int kch = nt >> 1, q = nt & 1;
                const int col0 = nt * 8 + 2 * t;
                const int cb0 = (np[col0] == 0) | (bt[col0] == 1);
                const int cb1 = (np[col0 + 1] == 0) | (bt[col0 + 1] == 1);
                float x0 = (cb0 | rowbad0) ? -1000.0f : sc[ntl][0] * scale;
                float x1 = (cb1 | rowbad0) ? -1000.0f : sc[ntl][1] * scale;
                float x2 = (cb0 | rowbad8) ? -1000.0f : sc[ntl][2] * scale;
                float x3 = (cb1 | rowbad8) ? -1000.0f : sc[ntl][3] * scale;
                float p0 = __expf(x0 + shift0);
                float p1 = __expf(x1 + shift0);
                float p2 = __expf(x2 + shift8);
                float p3 = __expf(x3 + shift8);
                lsum0 += p0 + p1;
                lsum8 += p2 + p3;
                bf16 h0, l0, h1, l1, h2, l2, h3, l3;
                split1(p0, h0, l0); split1(p1, h1, l1);
                split1(p2, h2, l2); split1(p3, h3, l3);
                pah[kch][q * 2 + 0] = pack2(h0, h1);
                pah[kch][q * 2 + 1] = pack2(h2, h3);
                pal[kch][q * 2 + 0] = pack2(l0, l1);
                pal[kch][q * 2 + 1] = pack2(l2, l3);
            }
        }

        // ---- PV: kch-outer (8 independent O accumulators) ----
#pragma unroll
        for (int kch = 0; kch < 4; kch++) {
            const int keyrow = kch * 16 + (tile & 1) * 8 + trow;
            unsigned vh[4][4], vl[4][4];
#pragma unroll
            for (int dp = 0; dp < 4; dp++) {
                const int dcol = dp * 16 + (tile >> 1) * 8;
                ldsm4t(vh[dp], &VHs[keyrow * ASLD + dcol]);
                ldsm4t(vl[dp], &VLs[keyrow * ASLD + dcol]);
            }
#pragma unroll
            for (int dp = 0; dp < 4; dp++)
#pragma unroll
                for (int q = 0; q < 2; q++)
                    mma_bf16(O[dp * 2 + q], pah[kch], vh[dp][q * 2], vh[dp][q * 2 + 1]);
#pragma unroll
            for (int dp = 0; dp < 4; dp++)
#pragma unroll
                for (int q = 0; q < 2; q++)
                    mma_bf16(O[dp * 2 + q], pah[kch], vl[dp][q * 2], vl[dp][q * 2 + 1]);
#pragma unroll
            for (int dp = 0; dp < 4; dp++)
#pragma unroll
                for (int q = 0; q < 2; q++)
                    mma_bf16(O[dp * 2 + q], pal[kch], vh[dp][q * 2], vh[dp][q * 2 + 1]);
        }
        __syncthreads();
        buf ^= 1;
    }

    // epilogue: quad-reduce l, normalize, split-store
    lsum0 += __shfl_xor_sync(0xffffffffu, lsum0, 1);
    lsum0 += __shfl_xor_sync(0xffffffffu, lsum0, 2);
    lsum8 += __shfl_xor_sync(0xffffffffu, lsum8, 1);
    lsum8 += __shfl_xor_sync(0xffffffffu, lsum8, 2);
    const float inv0 = 1.0f / lsum0;
    const float inv8 = 1.0f / lsum8;

    const size_t row0 = (size_t)(b * NN + q0 + rb + g);
    const size_t row8 = row0 + 8;
#pragma unroll
    for (int nt = 0; nt < 8; nt++) {
        const int d = h * 64 + nt * 8 + 2 * t;
        float v0 = O[nt][0] * inv0, v1 = O[nt][1] * inv0;
        float v2 = O[nt][2] * inv8, v3 = O[nt][3] * inv8;
        bf16 h0, l0, h1, l1, h2, l2, h3, l3;
        split1(v0, h0, l0); split1(v1, h1, l1);
        split1(v2, h2, l2); split1(v3, h3, l3);
        *reinterpret_cast<unsigned*>(&outh[row0 * INNER + d]) = pack2(h0, h1);
        *reinterpret_cast<unsigned*>(&outl[row0 * INNER + d]) = pack2(l0, l1);
        *reinterpret_cast<unsigned*>(&outh[row8 * INNER + d]) = pack2(h2, h3);
        *reinterpret_cast<unsigned*>(&outl[row8 * INNER + d]) = pack2(l2, l3);
    }
}

// ---------------------------------------------------------------------------
extern "C" void kernel_launch(void* const* d_in, const int* in_sizes, int n_in,
                              void* d_out, int out_size)
{
    const float* x     = (const float*)d_in[0];
    const int*   mnp   = (const int*)d_in[1];
    const int*   mbert = (const int*)d_in[2];
    const float* Wqkv  = (const float*)d_in[3];
    const float* Wout  = (const float*)d_in[4];
    const float* bout  = (const float*)d_in[5];
    float* out = (float*)d_out;

    bf16 *xh, *xl, *wqh, *wql, *woh, *wol, *qkvh, *qkvl, *ath, *atl;
    cudaGetSymbolAddress((void**)&xh,   g_x_h);
    cudaGetSymbolAddress((void**)&xl,   g_x_l);
    cudaGetSymbolAddress((void**)&wqh,  g_wqkv_h);
    cudaGetSymbolAddress((void**)&wql,  g_wqkv_l);
    cudaGetSymbolAddress((void**)&woh,  g_wout_h);
    cudaGetSymbolAddress((void**)&wol,  g_wout_l);
    cudaGetSymbolAddress((void**)&qkvh, g_qkv_h);
    cudaGetSymbolAddress((void**)&qkvl, g_qkv_l);
    cudaGetSymbolAddress((void**)&ath,  g_att_h);
    cudaGetSymbolAddress((void**)&atl,  g_att_l);

    cudaFuncSetAttribute(gemm_mma, cudaFuncAttributeMaxDynamicSharedMemorySize,
                         GEMM_SMEM_BYTES);
    cudaFuncSetAttribute(attn_mma, cudaFuncAttributeMaxDynamicSharedMemorySize,
                         ATT_SMEM_BYTES);

    // prep: split inputs into bf16 hi/lo
    split_kernel<<<512, 256>>>(x,    xh,  xl,  MROWS * DIM);
    split_kernel<<<512, 256>>>(Wqkv, wqh, wql, DIM * QKV3);
    split_kernel<<<256, 256>>>(Wout, woh, wol, INNER * DIM);

    // 1) qkv = x @ W_qkv  -> bf16 hi/lo
    gemm_mma<<<dim3(QKV3 / 128, MROWS / 128), 512, GEMM_SMEM_BYTES>>>(
        xh, xl, wqh, wql, nullptr, nullptr, qkvh, qkvl, MROWS, QKV3, DIM, 1);

    // 2) masked attention -> bf16 hi/lo
    attn_mma<<<dim3(NN / 256, BB * HH), 512, ATT_SMEM_BYTES>>>(
        qkvh, qkvl, mnp, mbert, ath, atl);

    // 3) out = att @ W_out + b_out  -> fp32
    gemm_mma<<<dim3(DIM / 128, MROWS / 128), 512, GEMM_SMEM_BYTES>>>(
        ath, atl, woh, wol, bout, out, nullptr, nullptr, MROWS, DIM, INNER, 0);
}

// round 7
// speedup vs baseline: 1.1670x; 1.0951x over previous
#include <cuda_runtime.h>
#include <cuda_bf16.h>
#include <math.h>

#define BB    2
#define NN    2048
#define DIM   512
#define HH    8
#define DH    64
#define INNER 512
#define QKV3  1536
#define MROWS (BB*NN)      // 4096

typedef __nv_bfloat16 bf16;

// ---------------- device scratch (no allocation allowed) ----------------
__device__ bf16 g_x_h[MROWS * DIM],    g_x_l[MROWS * DIM];
__device__ bf16 g_wqkv_h[DIM * QKV3],  g_wqkv_l[DIM * QKV3];
__device__ bf16 g_wout_h[INNER * DIM], g_wout_l[INNER * DIM];
__device__ bf16 g_qkv_h[MROWS * QKV3], g_qkv_l[MROWS * QKV3];
__device__ bf16 g_att_h[MROWS * INNER], g_att_l[MROWS * INNER];

// compaction structures
__device__ int  g_cnt[BB];
__device__ int  g_idx[BB * NN];
__device__ bf16 g_kc_h[BB * NN * INNER], g_kc_l[BB * NN * INNER];
__device__ bf16 g_vc_h[BB * NN * INNER], g_vc_l[BB * NN * INNER];
__device__ float g_vmean[BB * INNER];

// ---------------- helpers ----------------
__device__ __forceinline__ unsigned s2u(const void* p) {
    return (unsigned)__cvta_generic_to_shared(p);
}
__device__ __forceinline__ void ldsm4(unsigned* r, const void* p) {
    asm volatile("ldmatrix.sync.aligned.m8n8.x4.shared.b16 {%0,%1,%2,%3}, [%4];"
        : "=r"(r[0]), "=r"(r[1]), "=r"(r[2]), "=r"(r[3]) : "r"(s2u(p)));
}
__device__ __forceinline__ void ldsm4t(unsigned* r, const void* p) {
    asm volatile("ldmatrix.sync.aligned.m8n8.x4.trans.shared.b16 {%0,%1,%2,%3}, [%4];"
        : "=r"(r[0]), "=r"(r[1]), "=r"(r[2]), "=r"(r[3]) : "r"(s2u(p)));
}
__device__ __forceinline__ void cp16(void* s, const void* g) {
    asm volatile("cp.async.cg.shared.global [%0], [%1], 16;" :: "r"(s2u(s)), "l"(g));
}
__device__ __forceinline__ void cp_commit() { asm volatile("cp.async.commit_group;"); }
template<int N> __device__ __forceinline__ void cp_wait() {
    asm volatile("cp.async.wait_group %0;" :: "n"(N));
}
__device__ __forceinline__ void mma_bf16(float* c, const unsigned* a, unsigned b0, unsigned b1) {
    asm volatile(
        "mma.sync.aligned.m16n8k16.row.col.f32.bf16.bf16.f32 "
        "{%0,%1,%2,%3}, {%4,%5,%6,%7}, {%8,%9}, {%0,%1,%2,%3};"
        : "+f"(c[0]), "+f"(c[1]), "+f"(c[2]), "+f"(c[3])
        : "r"(a[0]), "r"(a[1]), "r"(a[2]), "r"(a[3]), "r"(b0), "r"(b1));
}
__device__ __forceinline__ unsigned pack2(bf16 a, bf16 b) {
    __nv_bfloat162 v; v.x = a; v.y = b;
    return *reinterpret_cast<unsigned*>(&v);
}
__device__ __forceinline__ void split1(float v, bf16& h, bf16& l) {
    h = __float2bfloat16(v);
    l = __float2bfloat16(v - __bfloat162float(h));
}

// ---------------- prep: fp32 -> bf16 hi/lo split ----------------
__global__ void split_kernel(const float* __restrict__ src, bf16* __restrict__ hi,
                             bf16* __restrict__ lo, int n)
{
    for (int i = blockIdx.x * blockDim.x + threadIdx.x; i < n; i += gridDim.x * blockDim.x) {
        float v = src[i];
        bf16 h, l; split1(v, h, l);
        hi[i] = h; lo[i] = l;
    }
}

// ---------------- compaction: surviving key columns (stable order) ----------
__global__ void build_compact(const int* __restrict__ mnp, const int* __restrict__ mbert)
{
    const int b = blockIdx.x;
    const int tid = threadIdx.x;            // 256 threads, 8 elems each
    __shared__ int cnts[256];
    __shared__ int offs[256];
    int flags[8];
    int local = 0;
#pragma unroll
    for (int k = 0; k < 8; k++) {
        int j = tid * 8 + k;
        int f = (mnp[b * NN + j] == 1) && (mbert[b * NN + j] == 0);
        flags[k] = f; local += f;
    }
    cnts[tid] = local;
    __syncthreads();
    if (tid == 0) {
        int s = 0;
        for (int i = 0; i < 256; i++) { offs[i] = s; s += cnts[i]; }
        g_cnt[b] = s;
    }
    __syncthreads();
    int o = offs[tid];
#pragma unroll
    for (int k = 0; k < 8; k++) {
        if (flags[k]) g_idx[b * NN + (o++)] = tid * 8 + k;
    }
}

// ---------------- gather compacted K/V (zero-fill pad to 64-multiple) -------
__global__ void gather_kv(const bf16* __restrict__ qh, const bf16* __restrict__ ql)
{
    const int b = blockIdx.y;
    const int i = blockIdx.x;
    const int cnt = g_cnt[b];
    const int pad = (cnt + 63) & ~63;
    if (i >= pad) return;
    const int tid = threadIdx.x;            // 128 threads x 4 elems
    const size_t dst = ((size_t)(b * NN + i)) * INNER + tid * 4;
    if (i < cnt) {
        const int j = g_idx[b * NN + i];
        const size_t ks = ((size_t)(b * NN + j)) * QKV3 + INNER + tid * 4;
        const size_t vs = ks + INNER;
        *reinterpret_cast<uint2*>(&g_kc_h[dst]) = *reinterpret_cast<const uint2*>(&qh[ks]);
        *reinterpret_cast<uint2*>(&g_kc_l[dst]) = *reinterpret_cast<const uint2*>(&ql[ks]);
        *reinterpret_cast<uint2*>(&g_vc_h[dst]) = *reinterpret_cast<const uint2*>(&qh[vs]);
        *reinterpret_cast<uint2*>(&g_vc_l[dst]) = *reinterpret_cast<const uint2*>(&ql[vs]);
    } else {
        uint2 z; z.x = 0u; z.y = 0u;
        *reinterpret_cast<uint2*>(&g_kc_h[dst]) = z;
        *reinterpret_cast<uint2*>(&g_kc_l[dst]) = z;
        *reinterpret_cast<uint2*>(&g_vc_h[dst]) = z;
        *reinterpret_cast<uint2*>(&g_vc_l[dst]) = z;
    }
}

// ---------------- mean of V over all rows (deterministic reduction) ---------
__global__ void meanv_kernel(const bf16* __restrict__ qh, const bf16* __restrict__ ql)
{
    const int b = blockIdx.y;
    const int d = blockIdx.x * 64 + threadIdx.x;
    const int yg = threadIdx.y;             // 8 row groups
    float s = 0.0f;
    for (int j = yg; j < NN; j += 8) {
        const size_t idx = ((size_t)(b * NN + j)) * QKV3 + 2 * INNER + d;
        s += __bfloat162float(qh[idx]) + __bfloat162float(ql[idx]);
    }
    __shared__ float red[8][64];
    red[yg][threadIdx.x] = s;
    __syncthreads();
    if (yg == 0) {
        float tot = 0.0f;
#pragma unroll
        for (int i = 0; i < 8; i++) tot += red[i][threadIdx.x];
        g_vmean[b * INNER + d] = tot * (1.0f / NN);
    }
}

// ---------------------------------------------------------------------------
// bf16x3 GEMM, 128x128 block, BK=32, 512 thr (16 warps; warp tile 32x32).
// ---------------------------------------------------------------------------
#define GALD 40
#define GBLD 136
#define G_SA(buf,hl) (sm + ((buf)*2 + (hl)) * (128*GALD))
#define G_SB(buf,hl) (sm + 4*128*GALD + ((buf)*2 + (hl)) * (32*GBLD))
#define GEMM_SMEM_BYTES ((4*128*GALD + 4*32*GBLD) * 2)

__global__ __launch_bounds__(512, 1) void gemm_mma(const bf16* __restrict__ Ah,
                                                   const bf16* __restrict__ Al,
                                                   const bf16* __restrict__ Bh,
                                                   const bf16* __restrict__ Bl,
                                                   const float* __restrict__ bias,
                                                   float* __restrict__ outf,
                                                   bf16* __restrict__ outh,
                                                   bf16* __restrict__ outl,
                                                   int M, int N, int K, int mode)
{
    extern __shared__ bf16 sm[];

    const int bm = blockIdx.y * 128;
    const int bn = blockIdx.x * 128;
    const int tid = threadIdx.x;
    const int warp = tid >> 5;
    const int lane = tid & 31;
    const int g = lane >> 2;
    const int t = lane & 3;
    const int rowbase = (warp & 3) * 32;
    const int colbase = (warp >> 2) * 32;

    float acc[2][4][4];
#pragma unroll
    for (int mt = 0; mt < 2; mt++)
#pragma unroll
        for (int nt = 0; nt < 4; nt++)
#pragma unroll
            for (int i = 0; i < 4; i++) acc[mt][nt][i] = 0.0f;

    const int tile = lane >> 3;
    const int trow = lane & 7;

    auto prefetch = [&](int buf, int k0) {
        {
            int c = tid;
            int row = c >> 2, kch = (c & 3) * 8;
            size_t go = (size_t)(bm + row) * K + k0 + kch;
            cp16(&G_SA(buf, 0)[row * GALD + kch], &Ah[go]);
            cp16(&G_SA(buf, 1)[row * GALD + kch], &Al[go]);
        }
        {
            int c = tid;
            int kr = c >> 4, nch = (c & 15) * 8;
            size_t go = (size_t)(k0 + kr) * N + bn + nch;
            cp16(&G_SB(buf, 0)[kr * GBLD + nch], &Bh[go]);
            cp16(&G_SB(buf, 1)[kr * GBLD + nch], &Bl[go]);
        }
    };

    prefetch(0, 0);
    cp_commit();

    const int NIT = K / 32;
    int buf = 0;
    for (int it = 0; it < NIT; it++) {
        if (it + 1 < NIT) { prefetch(buf ^ 1, (it + 1) * 32); cp_commit(); cp_wait<1>(); }
        else cp_wait<0>();
        __syncthreads();

        const bf16* As_h = G_SA(buf, 0);
        const bf16* As_l = G_SA(buf, 1);
        const bf16* Bs_h = G_SB(buf, 0);
        const bf16* Bs_l = G_SB(buf, 1);

#pragma unroll
        for (int kc = 0; kc < 2; kc++) {
            unsigned ah[2][4], al[2][4];
            const int amrow = (tile & 1) * 8 + trow;
            const int akoff = kc * 16 + (tile >> 1) * 8;
#pragma unroll
            for (int mt = 0; mt < 2; mt++) {
                ldsm4(ah[mt], &As_h[(rowbase + mt * 16 + amrow) * GALD + akoff]);
                ldsm4(al[mt], &As_l[(rowbase + mt * 16 + amrow) * GALD + akoff]);
            }
            const int bkrow = kc * 16 + (tile & 1) * 8 + trow;
            unsigned bh[2][4], bl[2][4];
#pragma unroll
            for (int ntp = 0; ntp < 2; ntp++) {
                const int bncol = colbase + ntp * 16 + (tile >> 1) * 8;
                ldsm4t(bh[ntp], &Bs_h[bkrow * GBLD + bncol]);
                ldsm4t(bl[ntp], &Bs_l[bkrow * GBLD + bncol]);
            }
#pragma unroll
            for (int mt = 0; mt < 2; mt++)
#pragma unroll
                for (int ntp = 0; ntp < 2; ntp++)
#pragma unroll
                    for (int q = 0; q < 2; q++)
                        mma_bf16(acc[mt][ntp * 2 + q], ah[mt], bh[ntp][q * 2], bh[ntp][q * 2 + 1]);
#pragma unroll
            for (int mt = 0; mt < 2; mt++)
#pragma unroll
                for (int ntp = 0; ntp < 2; ntp++)
#pragma unroll
                    for (int q = 0; q < 2; q++)
                        mma_bf16(acc[mt][ntp * 2 + q], ah[mt], bl[ntp][q * 2], bl[ntp][q * 2 + 1]);
#pragma unroll
            for (int mt = 0; mt < 2; mt++)
#pragma unroll
                for (int ntp = 0; ntp < 2; ntp++)
#pragma unroll
                    for (int q = 0; q < 2; q++)
                        mma_bf16(acc[mt][ntp * 2 + q], al[mt], bh[ntp][q * 2], bh[ntp][q * 2 + 1]);
        }
        __syncthreads();
        buf ^= 1;
    }

#pragma unroll
    for (int mt = 0; mt < 2; mt++) {
        const int r0 = bm + rowbase + mt * 16 + g;
        const int r1 = r0 + 8;
#pragma unroll
        for (int nt = 0; nt < 4; nt++) {
            const int c0 = bn + colbase + nt * 8 + 2 * t;
            float v0 = acc[mt][nt][0], v1 = acc[mt][nt][1];
            float v2 = acc[mt][nt][2], v3 = acc[mt][nt][3];
            if (mode == 0) {
                float b0 = bias[c0], b1 = bias[c0 + 1];
                *reinterpret_cast<float2*>(&outf[(size_t)r0 * N + c0]) = make_float2(v0 + b0, v1 + b1);
                *reinterpret_cast<float2*>(&outf[(size_t)r1 * N + c0]) = make_float2(v2 + b0, v3 + b1);
            } else {
                bf16 h0, l0, h1, l1, h2, l2, h3, l3;
                split1(v0, h0, l0); split1(v1, h1, l1);
                split1(v2, h2, l2); split1(v3, h3, l3);
                *reinterpret_cast<unsigned*>(&outh[(size_t)r0 * N + c0]) = pack2(h0, h1);
                *reinterpret_cast<unsigned*>(&outl[(size_t)r0 * N + c0]) = pack2(l0, l1);
                *reinterpret_cast<unsigned*>(&outh[(size_t)r1 * N + c0]) = pack2(h2, h3);
                *reinterpret_cast<unsigned*>(&outl[(size_t)r1 * N + c0]) = pack2(l2, l3);
            }
        }
    }
}

// ---------------------------------------------------------------------------
// Attention over COMPACTED keys: 512 thr, 256 q-rows/block, 64-key tiles.
// No per-column masks (all compacted keys alive); dead q-rows -> mean(V).
// ---------------------------------------------------------------------------
#define ASLD 72
#define A_Q(hl)     (sm + (hl) * (256 * ASLD))
#define A_KV(buf,m) (sm + 2 * 256 * ASLD + ((buf) * 4 + (m)) * (64 * ASLD))
#define ATT_BF16_TOT (2 * 256 * ASLD + 8 * 64 * ASLD)
#define ATT_SMEM_BYTES (ATT_BF16_TOT * 2)

__global__ __launch_bounds__(512, 1) void attn_mma(const bf16* __restrict__ qh,
                                                   const bf16* __restrict__ ql,
                                                   const int* __restrict__ mask_np,
                                                   bf16* __restrict__ outh,
                                                   bf16* __restrict__ outl)
{
    extern __shared__ char smraw[];
    bf16* sm = reinterpret_cast<bf16*>(smraw);

    const int b  = blockIdx.y >> 3;
    const int h  = blockIdx.y & 7;
    const int q0 = blockIdx.x * 256;
    const int tid = threadIdx.x;
    const int warp = tid >> 5;
    const int lane = tid & 31;
    const int g = lane >> 2;
    const int t = lane & 3;
    const int rb = warp * 16;
    const float scale = 0.125f;
    const int tile = lane >> 3;
    const int trow = lane & 7;

    const int cnt = g_cnt[b];
    const int ntiles = (cnt + 63) >> 6;

    // Q prefetch: 256 rows x 64 dims, hi+lo
#pragma unroll
    for (int j = 0; j < 4; j++) {
        int c = tid * 4 + j;
        int row = c >> 3, dch = (c & 7) * 8;
        size_t base = (size_t)(b * NN + q0 + row) * QKV3 + h * 64 + dch;
        cp16(&A_Q(0)[row * ASLD + dch], &qh[base]);
        cp16(&A_Q(1)[row * ASLD + dch], &ql[base]);
    }
    cp_commit();

    auto pref = [&](int buf, int kt0) {
        int c = tid;
        int row = c >> 3, dch = (c & 7) * 8;
        size_t base = ((size_t)(b * NN + kt0 + row)) * INNER + h * 64 + dch;
        cp16(&A_KV(buf, 0)[row * ASLD + dch], &g_kc_h[base]);
        cp16(&A_KV(buf, 1)[row * ASLD + dch], &g_kc_l[base]);
        cp16(&A_KV(buf, 2)[row * ASLD + dch], &g_vc_h[base]);
        cp16(&A_KV(buf, 3)[row * ASLD + dch], &g_vc_l[base]);
    };

    if (ntiles > 0) { pref(0, 0); }
    cp_commit();

    const int rowbad0 = (mask_np[b * NN + q0 + rb + g] == 0);
    const int rowbad8 = (mask_np[b * NN + q0 + rb + g + 8] == 0);

    float O[8][4];
#pragma unroll
    for (int nt = 0; nt < 8; nt++)
#pragma unroll
        for (int i = 0; i < 4; i++) O[nt][i] = 0.0f;
    float lsum0 = 0.0f, lsum8 = 0.0f;

    int buf = 0;
    for (int kt = 0; kt < ntiles; kt++) {
        const int kt0 = kt * 64;
        if (kt + 1 < ntiles) { pref(buf ^ 1, (kt + 1) * 64); cp_commit(); cp_wait<1>(); }
        else cp_wait<0>();
        __syncthreads();

        const bf16* QHs = A_Q(0);
        const bf16* QLs = A_Q(1);
        const bf16* KHs = A_KV(buf, 0);
        const bf16* KLs = A_KV(buf, 1);
        const bf16* VHs = A_KV(buf, 2);
        const bf16* VLs = A_KV(buf, 3);

        unsigned pah[4][4], pal[4][4];
        const int qr = rb + (tile & 1) * 8 + trow;

#pragma unroll
        for (int half = 0; half < 2; half++) {
            float sc[4][4];
#pragma unroll
            for (int nt = 0; nt < 4; nt++)
#pragma unroll
                for (int i = 0; i < 4; i++) sc[nt][i] = 0.0f;

#pragma unroll
            for (int kc = 0; kc < 4; kc++) {
                unsigned aqh[4], aql[4];
                ldsm4(aqh, &QHs[qr * ASLD + kc * 16 + (tile >> 1) * 8]);
                ldsm4(aql, &QLs[qr * ASLD + kc * 16 + (tile >> 1) * 8]);
                const int koff = kc * 16 + (tile & 1) * 8;
                unsigned kbh[2][4], kbl[2][4];
#pragma unroll
                for (int ntp = 0; ntp < 2; ntp++) {
                    const int nrow = (half * 2 + ntp) * 16 + (tile >> 1) * 8 + trow;
                    ldsm4(kbh[ntp], &KHs[nrow * ASLD + koff]);
                    ldsm4(kbl[ntp], &KLs[nrow * ASLD + koff]);
                }
#pragma unroll
                for (int ntp = 0; ntp < 2; ntp++)
#pragma unroll
                    for (int q = 0; q < 2; q++)
                        mma_bf16(sc[ntp * 2 + q], aqh, kbh[ntp][q * 2], kbh[ntp][q * 2 + 1]);
#pragma unroll
                for (int ntp = 0; ntp < 2; ntp++)
#pragma unroll
                    for (int q = 0; q < 2; q++)
                        mma_bf16(sc[ntp * 2 + q], aqh, kbl[ntp][q * 2], kbl[ntp][q * 2 + 1]);
#pragma unroll
                for (int ntp = 0; ntp < 2; ntp++)
#pragma unroll
                    for (int q = 0; q < 2; q++)
                        mma_bf16(sc[ntp * 2 + q], aql, kbh[ntp][q * 2], kbh[ntp][q * 2 + 1]);
            }

            // softmax (column validity = compacted index < cnt)
#pragma unroll
            for (int ntl = 0; ntl < 4; ntl++) {
                const int nt = half * 4 + ntl;
                const int kch = nt >> 1, q = nt & 1;
                const int colg = kt0 + nt * 8 + 2 * t;
                const bool v0c = colg < cnt;
                const bool v1c = colg + 1 < cnt;
                float p0 = v0c ? __expf(sc[ntl][0] * scale) : 0.0f;
                float p1 = v1c ? __expf(sc[ntl][1] * scale) : 0.0f;
                float p2 = v0c ? __expf(sc[ntl][2] * scale) : 0.0f;
                float p3 = v1c ? __expf(sc[ntl][3] * scale) : 0.0f;
                lsum0 += p0 + p1;
                lsum8 += p2 + p3;
                bf16 h0, l0, h1, l1, h2, l2, h3, l3;
                split1(p0, h0, l0); split1(p1, h1, l1);
                split1(p2, h2, l2); split1(p3, h3, l3);
                pah[kch][q * 2 + 0] = pack2(h0, h1);
                pah[kch][q * 2 + 1] = pack2(h2, h3);
                pal[kch][q * 2 + 0] = pack2(l0, l1);
                pal[kch][q * 2 + 1] = pack2(l2, l3);
            }
        }

        // ---- PV ----
#pragma unroll
        for (int kch = 0; kch < 4; kch++) {
            const int keyrow = kch * 16 + (tile & 1) * 8 + trow;
            unsigned vh[4][4], vl[4][4];
#pragma unroll
            for (int dp = 0; dp < 4; dp++) {
                const int dcol = dp * 16 + (tile >> 1) * 8;
                ldsm4t(vh[dp], &VHs[keyrow * ASLD + dcol]);
                ldsm4t(vl[dp], &VLs[keyrow * ASLD + dcol]);
            }
#pragma unroll
            for (int dp = 0; dp < 4; dp++)
#pragma unroll
                for (int q = 0; q < 2; q++)
                    mma_bf16(O[dp * 2 + q], pah[kch], vh[dp][q * 2], vh[dp][q * 2 + 1]);
#pragma unroll
            for (int dp = 0; dp < 4; dp++)
#pragma unroll
                for (int q = 0; q < 2; q++)
                    mma_bf16(O[dp * 2 + q], pah[kch], vl[dp][q * 2], vl[dp][q * 2 + 1]);
#pragma unroll
            for (int dp = 0; dp < 4; dp++)
#pragma unroll
                for (int q = 0; q < 2; q++)
                    mma_bf16(O[dp * 2 + q], pal[kch], vh[dp][q * 2], vh[dp][q * 2 + 1]);
        }
        __syncthreads();
        buf ^= 1;
    }

    // epilogue: quad-reduce l, normalize (or mean-V for dead rows), store
    lsum0 += __shfl_xor_sync(0xffffffffu, lsum0, 1);
    lsum0 += __shfl_xor_sync(0xffffffffu, lsum0, 2);
    lsum8 += __shfl_xor_sync(0xffffffffu, lsum8, 1);
    lsum8 += __shfl_xor_sync(0xffffffffu, lsum8, 2);
    const bool bad0 = rowbad0 || (cnt == 0);
    const bool bad8 = rowbad8 || (cnt == 0);
    const float inv0 = 1.0f / lsum0;
    const float inv8 = 1.0f / lsum8;

    const size_t row0 = (size_t)(b * NN + q0 + rb + g);
    const size_t row8 = row0 + 8;
#pragma unroll
    for (int nt = 0; nt < 8; nt++) {
        const int d = h * 64 + nt * 8 + 2 * t;
        const float mv0 = g_vmean[b * INNER + d];
        const float mv1 = g_vmean[b * INNER + d + 1];
        float v0 = bad0 ? mv0 : O[nt][0] * inv0;
        float v1 = bad0 ? mv1 : O[nt][1] * inv0;
        float v2 = bad8 ? mv0 : O[nt][2] * inv8;
        float v3 = bad8 ? mv1 : O[nt][3] * inv8;
        bf16 h0, l0, h1, l1, h2, l2, h3, l3;
        split1(v0, h0, l0); split1(v1, h1, l1);
        split1(v2, h2, l2); split1(v3, h3, l3);
        *reinterpret_cast<unsigned*>(&outh[row0 * INNER + d]) = pack2(h0, h1);
        *reinterpret_cast<unsigned*>(&outl[row0 * INNER + d]) = pack2(l0, l1);
        *reinterpret_cast<unsigned*>(&outh[row8 * INNER + d]) = pack2(h2, h3);
        *reinterpret_cast<unsigned*>(&outl[row8 * INNER + d]) = pack2(l2, l3);
    }
}

// ---------------------------------------------------------------------------
extern "C" void kernel_launch(void* const* d_in, const int* in_sizes, int n_in,
                              void* d_out, int out_size)
{
    const float* x     = (const float*)d_in[0];
    const int*   mnp   = (const int*)d_in[1];
    const int*   mbert = (const int*)d_in[2];
    const float* Wqkv  = (const float*)d_in[3];
    const float* Wout  = (const float*)d_in[4];
    const float* bout  = (const float*)d_in[5];
    float* out = (float*)d_out;

    bf16 *xh, *xl, *wqh, *wql, *woh, *wol, *qkvh, *qkvl, *ath, *atl;
    cudaGetSymbolAddress((void**)&xh,   g_x_h);
    cudaGetSymbolAddress((void**)&xl,   g_x_l);
    cudaGetSymbolAddress((void**)&wqh,  g_wqkv_h);
    cudaGetSymbolAddress((void**)&wql,  g_wqkv_l);
    cudaGetSymbolAddress((void**)&woh,  g_wout_h);
    cudaGetSymbolAddress((void**)&wol,  g_wout_l);
    cudaGetSymbolAddress((void**)&qkvh, g_qkv_h);
    cudaGetSymbolAddress((void**)&qkvl, g_qkv_l);
    cudaGetSymbolAddress((void**)&ath,  g_att_h);
    cudaGetSymbolAddress((void**)&atl,  g_att_l);

    cudaFuncSetAttribute(gemm_mma, cudaFuncAttributeMaxDynamicSharedMemorySize,
                         GEMM_SMEM_BYTES);
    cudaFuncSetAttribute(attn_mma, cudaFuncAttributeMaxDynamicSharedMemorySize,
                         ATT_SMEM_BYTES);

    // prep: split inputs into bf16 hi/lo
    split_kernel<<<512, 256>>>(x,    xh,  xl,  MROWS * DIM);
    split_kernel<<<512, 256>>>(Wqkv, wqh, wql, DIM * QKV3);
    split_kernel<<<256, 256>>>(Wout, woh, wol, INNER * DIM);

    // 1) qkv = x @ W_qkv  -> bf16 hi/lo
    gemm_mma<<<dim3(QKV3 / 128, MROWS / 128), 512, GEMM_SMEM_BYTES>>>(
        xh, xl, wqh, wql, nullptr, nullptr, qkvh, qkvl, MROWS, QKV3, DIM, 1);

    // 2a) compaction of surviving key columns + gather + mean(V)
    build_compact<<<BB, 256>>>(mnp, mbert);
    gather_kv<<<dim3(NN, BB), 128>>>(qkvh, qkvl);
    meanv_kernel<<<dim3(INNER / 64, BB), dim3(64, 8)>>>(qkvh, qkvl);

    // 2b) masked attention over compacted keys -> bf16 hi/lo
    attn_mma<<<dim3(NN / 256, BB * HH), 512, ATT_SMEM_BYTES>>>(
        qkvh, qkvl, mnp, ath, atl);

    // 3) out = att @ W_out + b_out  -> fp32
    gemm_mma<<<dim3(DIM / 128, MROWS / 128), 512, GEMM_SMEM_BYTES>>>(
        ath, atl, woh, wol, bout, out, nullptr, nullptr, MROWS, DIM, INNER, 0);
}

// round 8
// speedup vs baseline: 1.1879x; 1.0179x over previous
#include <cuda_runtime.h>
#include <cuda_bf16.h>
#include <math.h>

#define BB    2
#define NN    2048
#define DIM   512
#define HH    8
#define DH    64
#define INNER 512
#define QKV3  1536
#define MROWS (BB*NN)      // 4096

typedef __nv_bfloat16 bf16;

// ---------------- device scratch (no allocation allowed) ----------------
__device__ bf16 g_x_h[MROWS * DIM],    g_x_l[MROWS * DIM];
__device__ bf16 g_wqkv_h[DIM * QKV3],  g_wqkv_l[DIM * QKV3];
__device__ bf16 g_wout_h[INNER * DIM], g_wout_l[INNER * DIM];
__device__ bf16 g_qkv_h[MROWS * QKV3], g_qkv_l[MROWS * QKV3];
__device__ bf16 g_att_h[MROWS * INNER], g_att_l[MROWS * INNER];

// key compaction
__device__ int  g_cnt[BB];
__device__ int  g_idx[BB * NN];
__device__ bf16 g_kc_h[BB * NN * INNER], g_kc_l[BB * NN * INNER];
__device__ bf16 g_vc_h[BB * NN * INNER], g_vc_l[BB * NN * INNER];
__device__ float g_vmean[BB * INNER];

// query compaction
__device__ int  g_qcnt[BB];
__device__ int  g_qidx[BB * NN];
__device__ int  g_qpos[BB * NN];
__device__ bf16 g_qc_h[BB * NN * INNER], g_qc_l[BB * NN * INNER];
__device__ bf16 g_atc_h[BB * NN * INNER], g_atc_l[BB * NN * INNER];

// ---------------- helpers ----------------
__device__ __forceinline__ unsigned s2u(const void* p) {
    return (unsigned)__cvta_generic_to_shared(p);
}
__device__ __forceinline__ void ldsm4(unsigned* r, const void* p) {
    asm volatile("ldmatrix.sync.aligned.m8n8.x4.shared.b16 {%0,%1,%2,%3}, [%4];"
        : "=r"(r[0]), "=r"(r[1]), "=r"(r[2]), "=r"(r[3]) : "r"(s2u(p)));
}
__device__ __forceinline__ void ldsm4t(unsigned* r, const void* p) {
    asm volatile("ldmatrix.sync.aligned.m8n8.x4.trans.shared.b16 {%0,%1,%2,%3}, [%4];"
        : "=r"(r[0]), "=r"(r[1]), "=r"(r[2]), "=r"(r[3]) : "r"(s2u(p)));
}
__device__ __forceinline__ void cp16(void* s, const void* g) {
    asm volatile("cp.async.cg.shared.global [%0], [%1], 16;" :: "r"(s2u(s)), "l"(g));
}
__device__ __forceinline__ void cp_commit() { asm volatile("cp.async.commit_group;"); }
template<int N> __device__ __forceinline__ void cp_wait() {
    asm volatile("cp.async.wait_group %0;" :: "n"(N));
}
__device__ __forceinline__ void mma_bf16(float* c, const unsigned* a, unsigned b0, unsigned b1) {
    asm volatile(
        "mma.sync.aligned.m16n8k16.row.col.f32.bf16.bf16.f32 "
        "{%0,%1,%2,%3}, {%4,%5,%6,%7}, {%8,%9}, {%0,%1,%2,%3};"
        : "+f"(c[0]), "+f"(c[1]), "+f"(c[2]), "+f"(c[3])
        : "r"(a[0]), "r"(a[1]), "r"(a[2]), "r"(a[3]), "r"(b0), "r"(b1));
}
__device__ __forceinline__ unsigned pack2(bf16 a, bf16 b) {
    __nv_bfloat162 v; v.x = a; v.y = b;
    return *reinterpret_cast<unsigned*>(&v);
}
__device__ __forceinline__ void split1(float v, bf16& h, bf16& l) {
    h = __float2bfloat16(v);
    l = __float2bfloat16(v - __bfloat162float(h));
}

// ---------------- prep: fp32 -> bf16 hi/lo split ----------------
__global__ void split_kernel(const float* __restrict__ src, bf16* __restrict__ hi,
                             bf16* __restrict__ lo, int n)
{
    for (int i = blockIdx.x * blockDim.x + threadIdx.x; i < n; i += gridDim.x * blockDim.x) {
        float v = src[i];
        bf16 h, l; split1(v, h, l);
        hi[i] = h; lo[i] = l;
    }
}

// ---------------- compaction: surviving key columns (stable order) ----------
__global__ void build_compact(const int* __restrict__ mnp, const int* __restrict__ mbert)
{
    const int b = blockIdx.x;
    const int tid = threadIdx.x;            // 256 threads, 8 elems each
    __shared__ int cnts[256];
    __shared__ int offs[256];
    int flags[8];
    int local = 0;
#pragma unroll
    for (int k = 0; k < 8; k++) {
        int j = tid * 8 + k;
        int f = (mnp[b * NN + j] == 1) && (mbert[b * NN + j] == 0);
        flags[k] = f; local += f;
    }
    cnts[tid] = local;
    __syncthreads();
    if (tid == 0) {
        int s = 0;
        for (int i = 0; i < 256; i++) { offs[i] = s; s += cnts[i]; }
        g_cnt[b] = s;
    }
    __syncthreads();
    int o = offs[tid];
#pragma unroll
    for (int k = 0; k < 8; k++) {
        if (flags[k]) g_idx[b * NN + (o++)] = tid * 8 + k;
    }
}

// ---------------- compaction: alive query rows (stable order) ---------------
__global__ void build_qcompact(const int* __restrict__ mnp)
{
    const int b = blockIdx.x;
    const int tid = threadIdx.x;            // 256 threads, 8 elems each
    __shared__ int cnts[256];
    __shared__ int offs[256];
    int flags[8];
    int local = 0;
#pragma unroll
    for (int k = 0; k < 8; k++) {
        int j = tid * 8 + k;
        int f = (mnp[b * NN + j] == 1);
        flags[k] = f; local += f;
    }
    cnts[tid] = local;
    __syncthreads();
    if (tid == 0) {
        int s = 0;
        for (int i = 0; i < 256; i++) { offs[i] = s; s += cnts[i]; }
        g_qcnt[b] = s;
    }
    __syncthreads();
    int o = offs[tid];
#pragma unroll
    for (int k = 0; k < 8; k++) {
        int j = tid * 8 + k;
        if (flags[k]) { g_qidx[b * NN + o] = j; g_qpos[b * NN + j] = o; o++; }
        else g_qpos[b * NN + j] = -1;
    }
}

// ---------------- gather compacted K/V (zero-fill pad to 64-multiple) -------
__global__ void gather_kv(const bf16* __restrict__ qh, const bf16* __restrict__ ql)
{
    const int b = blockIdx.y;
    const int i = blockIdx.x;
    const int cnt = g_cnt[b];
    const int pad = (cnt + 63) & ~63;
    if (i >= pad) return;
    const int tid = threadIdx.x;            // 128 threads x 4 elems
    const size_t dst = ((size_t)(b * NN + i)) * INNER + tid * 4;
    if (i < cnt) {
        const int j = g_idx[b * NN + i];
        const size_t ks = ((size_t)(b * NN + j)) * QKV3 + INNER + tid * 4;
        const size_t vs = ks + INNER;
        *reinterpret_cast<uint2*>(&g_kc_h[dst]) = *reinterpret_cast<const uint2*>(&qh[ks]);
        *reinterpret_cast<uint2*>(&g_kc_l[dst]) = *reinterpret_cast<const uint2*>(&ql[ks]);
        *reinterpret_cast<uint2*>(&g_vc_h[dst]) = *reinterpret_cast<const uint2*>(&qh[vs]);
        *reinterpret_cast<uint2*>(&g_vc_l[dst]) = *reinterpret_cast<const uint2*>(&ql[vs]);
    } else {
        uint2 z; z.x = 0u; z.y = 0u;
        *reinterpret_cast<uint2*>(&g_kc_h[dst]) = z;
        *reinterpret_cast<uint2*>(&g_kc_l[dst]) = z;
        *reinterpret_cast<uint2*>(&g_vc_h[dst]) = z;
        *reinterpret_cast<uint2*>(&g_vc_l[dst]) = z;
    }
}

// ---------------- gather compacted Q rows (zero-fill pad to 128-multiple) ---
__global__ void gather_q(const bf16* __restrict__ qh, const bf16* __restrict__ ql)
{
    const int b = blockIdx.y;
    const int i = blockIdx.x;
    const int qcnt = g_qcnt[b];
    const int qpad = (qcnt + 127) & ~127;
    if (i >= qpad) return;
    const int tid = threadIdx.x;            // 128 threads x 4 elems
    const size_t dst = ((size_t)(b * NN + i)) * INNER + tid * 4;
    if (i < qcnt) {
        const int j = g_qidx[b * NN + i];
        const size_t qs = ((size_t)(b * NN + j)) * QKV3 + tid * 4;
        *reinterpret_cast<uint2*>(&g_qc_h[dst]) = *reinterpret_cast<const uint2*>(&qh[qs]);
        *reinterpret_cast<uint2*>(&g_qc_l[dst]) = *reinterpret_cast<const uint2*>(&ql[qs]);
    } else {
        uint2 z; z.x = 0u; z.y = 0u;
        *reinterpret_cast<uint2*>(&g_qc_h[dst]) = z;
        *reinterpret_cast<uint2*>(&g_qc_l[dst]) = z;
    }
}

// ---------------- scatter compacted attention rows back ---------------------
__global__ void scatter_att(bf16* __restrict__ outh, bf16* __restrict__ outl)
{
    const int b = blockIdx.y;
    const int i = blockIdx.x;
    const int tid = threadIdx.x;            // 128 threads x 4 elems
    const int cnt = g_cnt[b];
    const int pos = g_qpos[b * NN + i];
    const size_t dst = ((size_t)(b * NN + i)) * INNER + tid * 4;
    if (pos >= 0 && cnt > 0) {
        const size_t src = ((size_t)(b * NN + pos)) * INNER + tid * 4;
        *reinterpret_cast<uint2*>(&outh[dst]) = *reinterpret_cast<const uint2*>(&g_atc_h[src]);
        *reinterpret_cast<uint2*>(&outl[dst]) = *reinterpret_cast<const uint2*>(&g_atc_l[src]);
    } else {
        bf16 hh[4], ll[4];
#pragma unroll
        for (int e = 0; e < 4; e++) {
            float mv = g_vmean[b * INNER + tid * 4 + e];
            split1(mv, hh[e], ll[e]);
        }
        *reinterpret_cast<unsigned*>(&outh[dst])     = pack2(hh[0], hh[1]);
        *reinterpret_cast<unsigned*>(&outh[dst + 2]) = pack2(hh[2], hh[3]);
        *reinterpret_cast<unsigned*>(&outl[dst])     = pack2(ll[0], ll[1]);
        *reinterpret_cast<unsigned*>(&outl[dst + 2]) = pack2(ll[2], ll[3]);
    }
}

// ---------------- mean of V over all rows (deterministic reduction) ---------
__global__ void meanv_kernel(const bf16* __restrict__ qh, const bf16* __restrict__ ql)
{
    const int b = blockIdx.y;
    const int d = blockIdx.x * 64 + threadIdx.x;
    const int yg = threadIdx.y;             // 8 row groups
    float s = 0.0f;
    for (int j = yg; j < NN; j += 8) {
        const size_t idx = ((size_t)(b * NN + j)) * QKV3 + 2 * INNER + d;
        s += __bfloat162float(qh[idx]) + __bfloat162float(ql[idx]);
    }
    __shared__ float red[8][64];
    red[yg][threadIdx.x] = s;
    __syncthreads();
    if (yg == 0) {
        float tot = 0.0f;
#pragma unroll
        for (int i = 0; i < 8; i++) tot += red[i][threadIdx.x];
        g_vmean[b * INNER + d] = tot * (1.0f / NN);
    }
}

// ---------------------------------------------------------------------------
// bf16x3 GEMM, 128x128 block, BK=32, 512 thr (16 warps; warp tile 32x32).
// ---------------------------------------------------------------------------
#define GALD 40
#define GBLD 136
#define G_SA(buf,hl) (sm + ((buf)*2 + (hl)) * (128*GALD))
#define G_SB(buf,hl) (sm + 4*128*GALD + ((buf)*2 + (hl)) * (32*GBLD))
#define GEMM_SMEM_BYTES ((4*128*GALD + 4*32*GBLD) * 2)

__global__ __launch_bounds__(512, 1) void gemm_mma(const bf16* __restrict__ Ah,
                                                   const bf16* __restrict__ Al,
                                                   const bf16* __restrict__ Bh,
                                                   const bf16* __restrict__ Bl,
                                                   const float* __restrict__ bias,
                                                   float* __restrict__ outf,
                                                   bf16* __restrict__ outh,
                                                   bf16* __restrict__ outl,
                                                   int M, int N, int K, int mode)
{
    extern __shared__ bf16 sm[];

    const int bm = blockIdx.y * 128;
    const int bn = blockIdx.x * 128;
    const int tid = threadIdx.x;
    const int warp = tid >> 5;
    const int lane = tid & 31;
    const int g = lane >> 2;
    const int t = lane & 3;
    const int rowbase = (warp & 3) * 32;
    const int colbase = (warp >> 2) * 32;

    float acc[2][4][4];
#pragma unroll
    for (int mt = 0; mt < 2; mt++)
#pragma unroll
        for (int nt = 0; nt < 4; nt++)
#pragma unroll
            for (int i = 0; i < 4; i++) acc[mt][nt][i] = 0.0f;

    const int tile = lane >> 3;
    const int trow = lane & 7;

    auto prefetch = [&](int buf, int k0) {
        {
            int c = tid;
            int row = c >> 2, kch = (c & 3) * 8;
            size_t go = (size_t)(bm + row) * K + k0 + kch;
            cp16(&G_SA(buf, 0)[row * GALD + kch], &Ah[go]);
            cp16(&G_SA(buf, 1)[row * GALD + kch], &Al[go]);
        }
        {
            int c = tid;
            int kr = c >> 4, nch = (c & 15) * 8;
            size_t go = (size_t)(k0 + kr) * N + bn + nch;
            cp16(&G_SB(buf, 0)[kr * GBLD + nch], &Bh[go]);
            cp16(&G_SB(buf, 1)[kr * GBLD + nch], &Bl[go]);
        }
    };

    prefetch(0, 0);
    cp_commit();

    const int NIT = K / 32;
    int buf = 0;
    for (int it = 0; it < NIT; it++) {
        if (it + 1 < NIT) { prefetch(buf ^ 1, (it + 1) * 32); cp_commit(); cp_wait<1>(); }
        else cp_wait<0>();
        __syncthreads();

        const bf16* As_h = G_SA(buf, 0);
        const bf16* As_l = G_SA(buf, 1);
        const bf16* Bs_h = G_SB(buf, 0);
        const bf16* Bs_l = G_SB(buf, 1);

#pragma unroll
        for (int kc = 0; kc < 2; kc++) {
            unsigned ah[2][4], al[2][4];
            const int amrow = (tile & 1) * 8 + trow;
            const int akoff = kc * 16 + (tile >> 1) * 8;
#pragma unroll
            for (int mt = 0; mt < 2; mt++) {
                ldsm4(ah[mt], &As_h[(rowbase + mt * 16 + amrow) * GALD + akoff]);
                ldsm4(al[mt], &As_l[(rowbase + mt * 16 + amrow) * GALD + akoff]);
            }
            const int bkrow = kc * 16 + (tile & 1) * 8 + trow;
            unsigned bh[2][4], bl[2][4];
#pragma unroll
            for (int ntp = 0; ntp < 2; ntp++) {
                const int bncol = colbase + ntp * 16 + (tile >> 1) * 8;
                ldsm4t(bh[ntp], &Bs_h[bkrow * GBLD + bncol]);
                ldsm4t(bl[ntp], &Bs_l[bkrow * GBLD + bncol]);
            }
#pragma unroll
            for (int mt = 0; mt < 2; mt++)
#pragma unroll
                for (int ntp = 0; ntp < 2; ntp++)
#pragma unroll
                    for (int q = 0; q < 2; q++)
                        mma_bf16(acc[mt][ntp * 2 + q], ah[mt], bh[ntp][q * 2], bh[ntp][q * 2 + 1]);
#pragma unroll
            for (int mt = 0; mt < 2; mt++)
#pragma unroll
                for (int ntp = 0; ntp < 2; ntp++)
#pragma unroll
                    for (int q = 0; q < 2; q++)
                        mma_bf16(acc[mt][ntp * 2 + q], ah[mt], bl[ntp][q * 2], bl[ntp][q * 2 + 1]);
#pragma unroll
            for (int mt = 0; mt < 2; mt++)
#pragma unroll
                for (int ntp = 0; ntp < 2; ntp++)
#pragma unroll
                    for (int q = 0; q < 2; q++)
                        mma_bf16(acc[mt][ntp * 2 + q], al[mt], bh[ntp][q * 2], bh[ntp][q * 2 + 1]);
        }
        __syncthreads();
        buf ^= 1;
    }

#pragma unroll
    for (int mt = 0; mt < 2; mt++) {
        const int r0 = bm + rowbase + mt * 16 + g;
        const int r1 = r0 + 8;
#pragma unroll
        for (int nt = 0; nt < 4; nt++) {
            const int c0 = bn + colbase + nt * 8 + 2 * t;
            float v0 = acc[mt][nt][0], v1 = acc[mt][nt][1];
            float v2 = acc[mt][nt][2], v3 = acc[mt][nt][3];
            if (mode == 0) {
                float b0 = bias[c0], b1 = bias[c0 + 1];
                *reinterpret_cast<float2*>(&outf[(size_t)r0 * N + c0]) = make_float2(v0 + b0, v1 + b1);
                *reinterpret_cast<float2*>(&outf[(size_t)r1 * N + c0]) = make_float2(v2 + b0, v3 + b1);
            } else {
                bf16 h0, l0, h1, l1, h2, l2, h3, l3;
                split1(v0, h0, l0); split1(v1, h1, l1);
                split1(v2, h2, l2); split1(v3, h3, l3);
                *reinterpret_cast<unsigned*>(&outh[(size_t)r0 * N + c0]) = pack2(h0, h1);
                *reinterpret_cast<unsigned*>(&outl[(size_t)r0 * N + c0]) = pack2(l0, l1);
                *reinterpret_cast<unsigned*>(&outh[(size_t)r1 * N + c0]) = pack2(h2, h3);
                *reinterpret_cast<unsigned*>(&outl[(size_t)r1 * N + c0]) = pack2(l2, l3);
            }
        }
    }
}

// ---------------------------------------------------------------------------
// Attention over compacted Q rows and compacted keys.
// 256 thr (8 warps), 128 q-rows/block, 64-key tiles. No mask logic in loop.
// ---------------------------------------------------------------------------
#define ASLD 72
#define A_Q(hl)     (sm + (hl) * (128 * ASLD))
#define A_KV(buf,m) (sm + 2 * 128 * ASLD + ((buf) * 4 + (m)) * (64 * ASLD))
#define ATT_BF16_TOT (2 * 128 * ASLD + 8 * 64 * ASLD)
#define ATT_SMEM_BYTES (ATT_BF16_TOT * 2)

__global__ __launch_bounds__(256, 1) void attn_mma(bf16* __restrict__ outh,
                                                   bf16* __restrict__ outl)
{
    extern __shared__ char smraw[];
    bf16* sm = reinterpret_cast<bf16*>(smraw);

    const int b  = blockIdx.y >> 3;
    const int h  = blockIdx.y & 7;
    const int q0 = blockIdx.x * 128;

    const int qcnt = g_qcnt[b];
    const int qpad = (qcnt + 127) & ~127;
    if (q0 >= qpad) return;

    const int cnt = g_cnt[b];
    const int ntiles = (cnt + 63) >> 6;

    const int tid = threadIdx.x;
    const int warp = tid >> 5;
    const int lane = tid & 31;
    const int g = lane >> 2;
    const int t = lane & 3;
    const int rb = warp * 16;
    const float scale = 0.125f;
    const int tile = lane >> 3;
    const int trow = lane & 7;

    // Q prefetch: 128 rows x 64 dims, hi+lo
#pragma unroll
    for (int j = 0; j < 4; j++) {
        int c = tid * 4 + j;                  // 0..1023
        int row = c >> 3, dch = (c & 7) * 8;
        size_t base = (size_t)(b * NN + q0 + row) * INNER + h * 64 + dch;
        cp16(&A_Q(0)[row * ASLD + dch], &g_qc_h[base]);
        cp16(&A_Q(1)[row * ASLD + dch], &g_qc_l[base]);
    }
    cp_commit();

    auto pref = [&](int buf, int kt0) {
#pragma unroll
        for (int j = 0; j < 2; j++) {
            int c = tid * 2 + j;              // 0..511
            int row = c >> 3, dch = (c & 7) * 8;
            size_t base = ((size_t)(b * NN + kt0 + row)) * INNER + h * 64 + dch;
            cp16(&A_KV(buf, 0)[row * ASLD + dch], &g_kc_h[base]);
            cp16(&A_KV(buf, 1)[row * ASLD + dch], &g_kc_l[base]);
            cp16(&A_KV(buf, 2)[row * ASLD + dch], &g_vc_h[base]);
            cp16(&A_KV(buf, 3)[row * ASLD + dch], &g_vc_l[base]);
        }
    };

    if (ntiles > 0) { pref(0, 0); }
    cp_commit();

    float O[8][4];
#pragma unroll
    for (int nt = 0; nt < 8; nt++)
#pragma unroll
        for (int i = 0; i < 4; i++) O[nt][i] = 0.0f;
    float lsum0 = 0.0f, lsum8 = 0.0f;

    int buf = 0;
    for (int kt = 0; kt < ntiles; kt++) {
        const int kt0 = kt * 64;
        if (kt + 1 < ntiles) { pref(buf ^ 1, (kt + 1) * 64); cp_commit(); cp_wait<1>(); }
        else cp_wait<0>();
        __syncthreads();

        const bf16* QHs = A_Q(0);
        const bf16* QLs = A_Q(1);
        const bf16* KHs = A_KV(buf, 0);
        const bf16* KLs = A_KV(buf, 1);
        const bf16* VHs = A_KV(buf, 2);
        const bf16* VLs = A_KV(buf, 3);

        unsigned pah[4][4], pal[4][4];
        const int qr = rb + (tile & 1) * 8 + trow;

#pragma unroll
        for (int half = 0; half < 2; half++) {
            float sc[4][4];
#pragma unroll
            for (int nt = 0; nt < 4; nt++)
#pragma unroll
                for (int i = 0; i < 4; i++) sc[nt][i] = 0.0f;

#pragma unroll
            for (int kc = 0; kc < 4; kc++) {
                unsigned aqh[4], aql[4];
                ldsm4(aqh, &QHs[qr * ASLD + kc * 16 + (tile >> 1) * 8]);
                ldsm4(aql, &QLs[qr * ASLD + kc * 16 + (tile >> 1) * 8]);
                const int koff = kc * 16 + (tile & 1) * 8;
                unsigned kbh[2][4], kbl[2][4];
#pragma unroll
                for (int ntp = 0; ntp < 2; ntp++) {
                    const int nrow = (half * 2 + ntp) * 16 + (tile >> 1) * 8 + trow;
                    ldsm4(kbh[ntp], &KHs[nrow * ASLD + koff]);
                    ldsm4(kbl[ntp], &KLs[nrow * ASLD + koff]);
                }
#pragma unroll
                for (int ntp = 0; ntp < 2; ntp++)
#pragma unroll
                    for (int q = 0; q < 2; q++)
                        mma_bf16(sc[ntp * 2 + q], aqh, kbh[ntp][q * 2], kbh[ntp][q * 2 + 1]);
#pragma unroll
                for (int ntp = 0; ntp < 2; ntp++)
#pragma unroll
                    for (int q = 0; q < 2; q++)
                        mma_bf16(sc[ntp * 2 + q], aqh, kbl[ntp][q * 2], kbl[ntp][q * 2 + 1]);
#pragma unroll
                for (int ntp = 0; ntp < 2; ntp++)
#pragma unroll
                    for (int q = 0; q < 2; q++)
                        mma_bf16(sc[ntp * 2 + q], aql, kbh[ntp][q * 2], kbh[ntp][q * 2 + 1]);
            }

            // softmax (column validity = compacted index < cnt)
#pragma unroll
            for (int ntl = 0; ntl < 4; ntl++) {
                const int nt = half * 4 + ntl;
                const int kch = nt >> 1, q = nt & 1;
                const int colg = kt0 + nt * 8 + 2 * t;
                const bool v0c = colg < cnt;
                const bool v1c = colg + 1 < cnt;
                float p0 = v0c ? __expf(sc[ntl][0] * scale) : 0.0f;
                float p1 = v1c ? __expf(sc[ntl][1] * scale) : 0.0f;
                float p2 = v0c ? __expf(sc[ntl][2] * scale) : 0.0f;
                float p3 = v1c ? __expf(sc[ntl][3] * scale) : 0.0f;
                lsum0 += p0 + p1;
                lsum8 += p2 + p3;
                bf16 h0, l0, h1, l1, h2, l2, h3, l3;
                split1(p0, h0, l0); split1(p1, h1, l1);
                split1(p2, h2, l2); split1(p3, h3, l3);
                pah[kch][q * 2 + 0] = pack2(h0, h1);
                pah[kch][q * 2 + 1] = pack2(h2, h3);
                pal[kch][q * 2 + 0] = pack2(l0, l1);
                pal[kch][q * 2 + 1] = pack2(l2, l3);
            }
        }

        // ---- PV ----
#pragma unroll
        for (int kch = 0; kch < 4; kch++) {
            const int keyrow = kch * 16 + (tile & 1) * 8 + trow;
            unsigned vh[4][4], vl[4][4];
#pragma unroll
            for (int dp = 0; dp < 4; dp++) {
                const int dcol = dp * 16 + (tile >> 1) * 8;
                ldsm4t(vh[dp], &VHs[keyrow * ASLD + dcol]);
                ldsm4t(vl[dp], &VLs[keyrow * ASLD + dcol]);
            }
#pragma unroll
            for (int dp = 0; dp < 4; dp++)
#pragma unroll
                for (int q = 0; q < 2; q++)
                    mma_bf16(O[dp * 2 + q], pah[kch], vh[dp][q * 2], vh[dp][q * 2 + 1]);
#pragma unroll
            for (int dp = 0; dp < 4; dp++)
#pragma unroll
                for (int q = 0; q < 2; q++)
                    mma_bf16(O[dp * 2 + q], pah[kch], vl[dp][q * 2], vl[dp][q * 2 + 1]);
#pragma unroll
            for (int dp = 0; dp < 4; dp++)
#pragma unroll
                for (int q = 0; q < 2; q++)
                    mma_bf16(O[dp * 2 + q], pal[kch], vh[dp][q * 2], vh[dp][q * 2 + 1]);
        }
        __syncthreads();
        buf ^= 1;
    }

    // epilogue: quad-reduce l, normalize, split-store to compacted rows
    lsum0 += __shfl_xor_sync(0xffffffffu, lsum0, 1);
    lsum0 += __shfl_xor_sync(0xffffffffu, lsum0, 2);
    lsum8 += __shfl_xor_sync(0xffffffffu, lsum8, 1);
    lsum8 += __shfl_xor_sync(0xffffffffu, lsum8, 2);
    const float inv0 = 1.0f / lsum0;
    const float inv8 = 1.0f / lsum8;

    const size_t row0 = (size_t)(b * NN + q0 + rb + g);
    const size_t row8 = row0 + 8;
#pragma unroll
    for (int nt = 0; nt < 8; nt++) {
        const int d = h * 64 + nt * 8 + 2 * t;
        float v0 = O[nt][0] * inv0, v1 = O[nt][1] * inv0;
        float v2 = O[nt][2] * inv8, v3 = O[nt][3] * inv8;
        bf16 h0, l0, h1, l1, h2, l2, h3, l3;
        split1(v0, h0, l0); split1(v1, h1, l1);
        split1(v2, h2, l2); split1(v3, h3, l3);
        *reinterpret_cast<unsigned*>(&outh[row0 * INNER + d]) = pack2(h0, h1);
        *reinterpret_cast<unsigned*>(&outl[row0 * INNER + d]) = pack2(l0, l1);
        *reinterpret_cast<unsigned*>(&outh[row8 * INNER + d]) = pack2(h2, h3);
        *reinterpret_cast<unsigned*>(&outl[row8 * INNER + d]) = pack2(l2, l3);
    }
}

// ---------------------------------------------------------------------------
extern "C" void kernel_launch(void* const* d_in, const int* in_sizes, int n_in,
                              void* d_out, int out_size)
{
    const float* x     = (const float*)d_in[0];
    const int*   mnp   = (const int*)d_in[1];
    const int*   mbert = (const int*)d_in[2];
    const float* Wqkv  = (const float*)d_in[3];
    const float* Wout  = (const float*)d_in[4];
    const float* bout  = (const float*)d_in[5];
    float* out = (float*)d_out;

    bf16 *xh, *xl, *wqh, *wql, *woh, *wol, *qkvh, *qkvl, *ath, *atl, *atch, *atcl;
    cudaGetSymbolAddress((void**)&xh,   g_x_h);
    cudaGetSymbolAddress((void**)&xl,   g_x_l);
    cudaGetSymbolAddress((void**)&wqh,  g_wqkv_h);
    cudaGetSymbolAddress((void**)&wql,  g_wqkv_l);
    cudaGetSymbolAddress((void**)&woh,  g_wout_h);
    cudaGetSymbolAddress((void**)&wol,  g_wout_l);
    cudaGetSymbolAddress((void**)&qkvh, g_qkv_h);
    cudaGetSymbolAddress((void**)&qkvl, g_qkv_l);
    cudaGetSymbolAddress((void**)&ath,  g_att_h);
    cudaGetSymbolAddress((void**)&atl,  g_att_l);
    cudaGetSymbolAddress((void**)&atch, g_atc_h);
    cudaGetSymbolAddress((void**)&atcl, g_atc_l);

    cudaFuncSetAttribute(gemm_mma, cudaFuncAttributeMaxDynamicSharedMemorySize,
                         GEMM_SMEM_BYTES);
    cudaFuncSetAttribute(attn_mma, cudaFuncAttributeMaxDynamicSharedMemorySize,
                         ATT_SMEM_BYTES);

    // prep: split inputs into bf16 hi/lo
    split_kernel<<<512, 256>>>(x,    xh,  xl,  MROWS * DIM);
    split_kernel<<<512, 256>>>(Wqkv, wqh, wql, DIM * QKV3);
    split_kernel<<<256, 256>>>(Wout, woh, wol, INNER * DIM);

    // 1) qkv = x @ W_qkv  -> bf16 hi/lo
    gemm_mma<<<dim3(QKV3 / 128, MROWS / 128), 512, GEMM_SMEM_BYTES>>>(
        xh, xl, wqh, wql, nullptr, nullptr, qkvh, qkvl, MROWS, QKV3, DIM, 1);

    // 2a) compactions + gathers + mean(V)
    build_compact<<<BB, 256>>>(mnp, mbert);
    build_qcompact<<<BB, 256>>>(mnp);
    gather_kv<<<dim3(NN, BB), 128>>>(qkvh, qkvl);
    gather_q<<<dim3(NN, BB), 128>>>(qkvh, qkvl);
    meanv_kernel<<<dim3(INNER / 64, BB), dim3(64, 8)>>>(qkvh, qkvl);

    // 2b) attention over compacted q-rows and keys -> compacted bf16 hi/lo
    attn_mma<<<dim3(NN / 128, BB * HH), 256, ATT_SMEM_BYTES>>>(atch, atcl);

    // 2c) scatter back (dead rows = mean(V))
    scatter_att<<<dim3(NN, BB), 128>>>(ath, atl);

    // 3) out = att @ W_out + b_out  -> fp32
    gemm_mma<<<dim3(DIM / 128, MROWS / 128), 512, GEMM_SMEM_BYTES>>>(
        ath, atl, woh, wol, bout, out, nullptr, nullptr, MROWS, DIM, INNER, 0);
}

// round 9
// speedup vs baseline: 1.2273x; 1.0332x over previous
#include <cuda_runtime.h>
#include <cuda_bf16.h>
#include <math.h>

#define BB    2
#define NN    2048
#define DIM   512
#define HH    8
#define DH    64
#define INNER 512
#define QKV3  1536
#define MROWS (BB*NN)      // 4096

typedef __nv_bfloat16 bf16;

// ---------------- device scratch (no allocation allowed) ----------------
__device__ bf16 g_x_h[MROWS * DIM],    g_x_l[MROWS * DIM];
__device__ bf16 g_wqkv_h[DIM * QKV3],  g_wqkv_l[DIM * QKV3];
__device__ bf16 g_wout_h[INNER * DIM], g_wout_l[INNER * DIM];

// key compaction
__device__ int  g_cnt[BB];
__device__ int  g_idx[BB * NN];
__device__ bf16 g_kc_h[BB * NN * INNER], g_kc_l[BB * NN * INNER];
__device__ bf16 g_v_h[BB * NN * INNER],  g_v_l[BB * NN * INNER];   // full V
__device__ bf16 g_vc_h[BB * NN * INNER], g_vc_l[BB * NN * INNER];  // compacted V
__device__ float g_vmean[BB * INNER];
__device__ float g_dead[BB * DIM];

// query compaction
__device__ int  g_qcnt[BB];
__device__ int  g_qidx[BB * NN];
__device__ int  g_qpos[BB * NN];
__device__ bf16 g_qc_h[BB * NN * INNER], g_qc_l[BB * NN * INNER];
__device__ bf16 g_atc_h[BB * NN * INNER], g_atc_l[BB * NN * INNER];

// ---------------- helpers ----------------
__device__ __forceinline__ unsigned s2u(const void* p) {
    return (unsigned)__cvta_generic_to_shared(p);
}
__device__ __forceinline__ void ldsm4(unsigned* r, const void* p) {
    asm volatile("ldmatrix.sync.aligned.m8n8.x4.shared.b16 {%0,%1,%2,%3}, [%4];"
        : "=r"(r[0]), "=r"(r[1]), "=r"(r[2]), "=r"(r[3]) : "r"(s2u(p)));
}
__device__ __forceinline__ void ldsm4t(unsigned* r, const void* p) {
    asm volatile("ldmatrix.sync.aligned.m8n8.x4.trans.shared.b16 {%0,%1,%2,%3}, [%4];"
        : "=r"(r[0]), "=r"(r[1]), "=r"(r[2]), "=r"(r[3]) : "r"(s2u(p)));
}
__device__ __forceinline__ void cp16(void* s, const void* g) {
    asm volatile("cp.async.cg.shared.global [%0], [%1], 16;" :: "r"(s2u(s)), "l"(g));
}
__device__ __forceinline__ void cp_commit() { asm volatile("cp.async.commit_group;"); }
template<int N> __device__ __forceinline__ void cp_wait() {
    asm volatile("cp.async.wait_group %0;" :: "n"(N));
}
__device__ __forceinline__ void mma_bf16(float* c, const unsigned* a, unsigned b0, unsigned b1) {
    asm volatile(
        "mma.sync.aligned.m16n8k16.row.col.f32.bf16.bf16.f32 "
        "{%0,%1,%2,%3}, {%4,%5,%6,%7}, {%8,%9}, {%0,%1,%2,%3};"
        : "+f"(c[0]), "+f"(c[1]), "+f"(c[2]), "+f"(c[3])
        : "r"(a[0]), "r"(a[1]), "r"(a[2]), "r"(a[3]), "r"(b0), "r"(b1));
}
__device__ __forceinline__ unsigned pack2(bf16 a, bf16 b) {
    __nv_bfloat162 v; v.x = a; v.y = b;
    return *reinterpret_cast<unsigned*>(&v);
}
__device__ __forceinline__ void split1(float v, bf16& h, bf16& l) {
    h = __float2bfloat16(v);
    l = __float2bfloat16(v - __bfloat162float(h));
}

// ---------------- prep: fp32 -> bf16 hi/lo split ----------------
__global__ void split_kernel(const float* __restrict__ src, bf16* __restrict__ hi,
                             bf16* __restrict__ lo, int n)
{
    for (int i = blockIdx.x * blockDim.x + threadIdx.x; i < n; i += gridDim.x * blockDim.x) {
        float v = src[i];
        bf16 h, l; split1(v, h, l);
        hi[i] = h; lo[i] = l;
    }
}

// ---------------- compaction: surviving key columns (stable order) ----------
__global__ void build_compact(const int* __restrict__ mnp, const int* __restrict__ mbert)
{
    const int b = blockIdx.x;
    const int tid = threadIdx.x;            // 256 threads, 8 elems each
    __shared__ int cnts[256];
    __shared__ int offs[256];
    __shared__ int tot;
    int flags[8];
    int local = 0;
#pragma unroll
    for (int k = 0; k < 8; k++) {
        int j = tid * 8 + k;
        int f = (mnp[b * NN + j] == 1) && (mbert[b * NN + j] == 0);
        flags[k] = f; local += f;
    }
    cnts[tid] = local;
    __syncthreads();
    if (tid == 0) {
        int s = 0;
        for (int i = 0; i < 256; i++) { offs[i] = s; s += cnts[i]; }
        g_cnt[b] = s; tot = s;
    }
    __syncthreads();
    int o = offs[tid];
#pragma unroll
    for (int k = 0; k < 8; k++) {
        if (flags[k]) g_idx[b * NN + (o++)] = tid * 8 + k;
    }
    for (int i = tot + tid; i < NN; i += 256) g_idx[b * NN + i] = 0;
}

// ---------------- compaction: alive query rows (stable order) ---------------
__global__ void build_qcompact(const int* __restrict__ mnp)
{
    const int b = blockIdx.x;
    const int tid = threadIdx.x;
    __shared__ int cnts[256];
    __shared__ int offs[256];
    __shared__ int tot;
    int flags[8];
    int local = 0;
#pragma unroll
    for (int k = 0; k < 8; k++) {
        int j = tid * 8 + k;
        int f = (mnp[b * NN + j] == 1);
        flags[k] = f; local += f;
    }
    cnts[tid] = local;
    __syncthreads();
    if (tid == 0) {
        int s = 0;
        for (int i = 0; i < 256; i++) { offs[i] = s; s += cnts[i]; }
        g_qcnt[b] = s; tot = s;
    }
    __syncthreads();
    int o = offs[tid];
#pragma unroll
    for (int k = 0; k < 8; k++) {
        int j = tid * 8 + k;
        if (flags[k]) { g_qidx[b * NN + o] = j; g_qpos[b * NN + j] = o; o++; }
        else g_qpos[b * NN + j] = -1;
    }
    for (int i = tot + tid; i < NN; i += 256) g_qidx[b * NN + i] = 0;
}

// ---------------- gather compacted V (zero-fill pad to 64-multiple) ---------
__global__ void gather_v()
{
    const int b = blockIdx.y;
    const int i = blockIdx.x;
    const int cnt = g_cnt[b];
    const int pad = (cnt + 63) & ~63;
    if (i >= pad) return;
    const int tid = threadIdx.x;            // 128 threads x 4 elems
    const size_t dst = ((size_t)(b * NN + i)) * INNER + tid * 4;
    if (i < cnt) {
        const int j = g_idx[b * NN + i];
        const size_t vs = ((size_t)(b * NN + j)) * INNER + tid * 4;
        *reinterpret_cast<uint2*>(&g_vc_h[dst]) = *reinterpret_cast<const uint2*>(&g_v_h[vs]);
        *reinterpret_cast<uint2*>(&g_vc_l[dst]) = *reinterpret_cast<const uint2*>(&g_v_l[vs]);
    } else {
        uint2 z; z.x = 0u; z.y = 0u;
        *reinterpret_cast<uint2*>(&g_vc_h[dst]) = z;
        *reinterpret_cast<uint2*>(&g_vc_l[dst]) = z;
    }
}

// ---------------- mean of V over all rows (deterministic reduction) ---------
__global__ void meanv_kernel()
{
    const int b = blockIdx.y;
    const int d = blockIdx.x * 64 + threadIdx.x;
    const int yg = threadIdx.y;             // 8 row groups
    float s = 0.0f;
    for (int j = yg; j < NN; j += 8) {
        const size_t idx = ((size_t)(b * NN + j)) * INNER + d;
        s += __bfloat162float(g_v_h[idx]) + __bfloat162float(g_v_l[idx]);
    }
    __shared__ float red[8][64];
    red[yg][threadIdx.x] = s;
    __syncthreads();
    if (yg == 0) {
        float tot = 0.0f;
#pragma unroll
        for (int i = 0; i < 8; i++) tot += red[i][threadIdx.x];
        g_vmean[b * INNER + d] = tot * (1.0f / NN);
    }
}

// ---------------- dead-row output vector: meanV @ W_out + bias --------------
__global__ void deadvec_kernel(const float* __restrict__ Wout,
                               const float* __restrict__ bias)
{
    const int b = blockIdx.y;
    const int col = blockIdx.x * 64 + threadIdx.x;
    const int yg = threadIdx.y;             // 8 groups over d
    float s = 0.0f;
    for (int d = yg; d < INNER; d += 8)
        s += g_vmean[b * INNER + d] * Wout[d * DIM + col];
    __shared__ float red[8][64];
    red[yg][threadIdx.x] = s;
    __syncthreads();
    if (yg == 0) {
        float tot = bias[col];
#pragma unroll
        for (int i = 0; i < 8; i++) tot += red[i][threadIdx.x];
        g_dead[b * DIM + col] = tot;
    }
}

// ---------------- fill dead output rows -------------------------------------
__global__ void dead_fill(float* __restrict__ out)
{
    const int b = blockIdx.y;
    const int i = blockIdx.x;
    if (g_qpos[b * NN + i] >= 0) return;
    const int tid = threadIdx.x;            // 128 threads x 4 floats
    *reinterpret_cast<float4*>(&out[((size_t)(b * NN + i)) * DIM + tid * 4]) =
        *reinterpret_cast<const float4*>(&g_dead[b * DIM + tid * 4]);
}

// ---------------------------------------------------------------------------
// bf16x3 GEMM, 128x128 block, BK=32, 512 thr (16 warps; warp tile 32x32).
// Optional row indirection (ridx) + per-batch row count (cntp) + output
// row indirection (oidx, mode 0 only, write-guarded by count).
// ---------------------------------------------------------------------------
#define GALD 40
#define GBLD 136
#define G_SA(buf,hl) (sm + ((buf)*2 + (hl)) * (128*GALD))
#define G_SB(buf,hl) (sm + 4*128*GALD + ((buf)*2 + (hl)) * (32*GBLD))
#define GEMM_SMEM_BYTES ((4*128*GALD + 4*32*GBLD) * 2)

__global__ __launch_bounds__(512, 1) void gemm_mma(const bf16* __restrict__ Ah,
                                                   const bf16* __restrict__ Al,
                                                   int lda,
                                                   const int* __restrict__ ridx,
                                                   const int* __restrict__ cntp,
                                                   const bf16* __restrict__ Bh,
                                                   const bf16* __restrict__ Bl,
                                                   int ldb,
                                                   const float* __restrict__ bias,
                                                   float* __restrict__ outf,
                                                   bf16* __restrict__ outh,
                                                   bf16* __restrict__ outl,
                                                   int ldo,
                                                   const int* __restrict__ oidx,
                                                   int N, int K, int mode)
{
    extern __shared__ bf16 sm[];

    const int bm = blockIdx.y * 128;
    const int bn = blockIdx.x * 128;
    const int b  = bm >> 11;                 // NN = 2048
    const int lm = bm & (NN - 1);
    const int bbase = b * NN;

    int cntv = NN;
    if (cntp) {
        cntv = cntp[b];
        if (lm >= ((cntv + 127) & ~127)) return;
    }

    const int tid = threadIdx.x;
    const int warp = tid >> 5;
    const int lane = tid & 31;
    const int g = lane >> 2;
    const int t = lane & 3;
    const int rowbase = (warp & 3) * 32;
    const int colbase = (warp >> 2) * 32;

    float acc[2][4][4];
#pragma unroll
    for (int mt = 0; mt < 2; mt++)
#pragma unroll
        for (int nt = 0; nt < 4; nt++)
#pragma unroll
            for (int i = 0; i < 4; i++) acc[mt][nt][i] = 0.0f;

    const int tile = lane >> 3;
    const int trow = lane & 7;

    // A-row global index for this thread's load slot
    const int arow = tid >> 2;
    const int akch = (tid & 3) * 8;
    int agrow;
    if (ridx) agrow = bbase + ridx[bbase + lm + arow];
    else      agrow = bm + arow;

    auto prefetch = [&](int buf, int k0) {
        {
            size_t go = (size_t)agrow * lda + k0 + akch;
            cp16(&G_SA(buf, 0)[arow * GALD + akch], &Ah[go]);
            cp16(&G_SA(buf, 1)[arow * GALD + akch], &Al[go]);
        }
        {
            int kr = tid >> 4, nch = (tid & 15) * 8;
            size_t go = (size_t)(k0 + kr) * ldb + bn + nch;
            cp16(&G_SB(buf, 0)[kr * GBLD + nch], &Bh[go]);
            cp16(&G_SB(buf, 1)[kr * GBLD + nch], &Bl[go]);
        }
    };

    prefetch(0, 0);
    cp_commit();

    const int NIT = K / 32;
    int buf = 0;
    for (int it = 0; it < NIT; it++) {
        if (it + 1 < NIT) { prefetch(buf ^ 1, (it + 1) * 32); cp_commit(); cp_wait<1>(); }
        else cp_wait<0>();
        __syncthreads();

        const bf16* As_h = G_SA(buf, 0);
        const bf16* As_l = G_SA(buf, 1);
        const bf16* Bs_h = G_SB(buf, 0);
        const bf16* Bs_l = G_SB(buf, 1);

#pragma unroll
        for (int kc = 0; kc < 2; kc++) {
            unsigned ah[2][4], al[2][4];
            const int amrow = (tile & 1) * 8 + trow;
            const int akoff = kc * 16 + (tile >> 1) * 8;
#pragma unroll
            for (int mt = 0; mt < 2; mt++) {
                ldsm4(ah[mt], &As_h[(rowbase + mt * 16 + amrow) * GALD + akoff]);
                ldsm4(al[mt], &As_l[(rowbase + mt * 16 + amrow) * GALD + akoff]);
            }
            const int bkrow = kc * 16 + (tile & 1) * 8 + trow;
            unsigned bh[2][4], bl[2][4];
#pragma unroll
            for (int ntp = 0; ntp < 2; ntp++) {
                const int bncol = colbase + ntp * 16 + (tile >> 1) * 8;
                ldsm4t(bh[ntp], &Bs_h[bkrow * GBLD + bncol]);
                ldsm4t(bl[ntp], &Bs_l[bkrow * GBLD + bncol]);
            }
#pragma unroll
            for (int mt = 0; mt < 2; mt++)
#pragma unroll
                for (int ntp = 0; ntp < 2; ntp++)
#pragma unroll
                    for (int q = 0; q < 2; q++)
                        mma_bf16(acc[mt][ntp * 2 + q], ah[mt], bh[ntp][q * 2], bh[ntp][q * 2 + 1]);
#pragma unroll
            for (int mt = 0; mt < 2; mt++)
#pragma unroll
                for (int ntp = 0; ntp < 2; ntp++)
#pragma unroll
                    for (int q = 0; q < 2; q++)
                        mma_bf16(acc[mt][ntp * 2 + q], ah[mt], bl[ntp][q * 2], bl[ntp][q * 2 + 1]);
#pragma unroll
            for (int mt = 0; mt < 2; mt++)
#pragma unroll
                for (int ntp = 0; ntp < 2; ntp++)
#pragma unroll
                    for (int q = 0; q < 2; q++)
                        mma_bf16(acc[mt][ntp * 2 + q], al[mt], bh[ntp][q * 2], bh[ntp][q * 2 + 1]);
        }
        __syncthreads();
        buf ^= 1;
    }

#pragma unroll
    for (int mt = 0; mt < 2; mt++) {
        const int lr0 = lm + rowbase + mt * 16 + g;
        const int lr1 = lr0 + 8;
#pragma unroll
        for (int nt = 0; nt < 4; nt++) {
            const int c0 = bn + colbase + nt * 8 + 2 * t;
            float v0 = acc[mt][nt][0], v1 = acc[mt][nt][1];
            float v2 = acc[mt][nt][2], v3 = acc[mt][nt][3];
            if (mode == 0) {
                float b0 = bias[c0], b1 = bias[c0 + 1];
                if (!oidx || lr0 < cntv) {
                    int orow = oidx ? (bbase + oidx[bbase + lr0]) : (bbase + lr0);
                    *reinterpret_cast<float2*>(&outf[(size_t)orow * ldo + c0]) =
                        make_float2(v0 + b0, v1 + b1);
                }
                if (!oidx || lr1 < cntv) {
                    int orow = oidx ? (bbase + oidx[bbase + lr1]) : (bbase + lr1);
                    *reinterpret_cast<float2*>(&outf[(size_t)orow * ldo + c0]) =
                        make_float2(v2 + b0, v3 + b1);
                }
            } else {
                bf16 h0, l0, h1, l1, h2, l2, h3, l3;
                split1(v0, h0, l0); split1(v1, h1, l1);
                split1(v2, h2, l2); split1(v3, h3, l3);
                const size_t r0o = (size_t)(bbase + lr0) * ldo + c0;
                const size_t r1o = (size_t)(bbase + lr1) * ldo + c0;
                *reinterpret_cast<unsigned*>(&outh[r0o]) = pack2(h0, h1);
                *reinterpret_cast<unsigned*>(&outl[r0o]) = pack2(l0, l1);
                *reinterpret_cast<unsigned*>(&outh[r1o]) = pack2(h2, h3);
                *reinterpret_cast<unsigned*>(&outl[r1o]) = pack2(l2, l3);
            }
        }
    }
}

// ---------------------------------------------------------------------------
// Attention over compacted Q rows and compacted keys.
// 256 thr (8 warps), 128 q-rows/block, 64-key tiles. No mask logic in loop.
// ---------------------------------------------------------------------------
#define ASLD 72
#define A_Q(hl)     (sm + (hl) * (128 * ASLD))
#define A_KV(buf,m) (sm + 2 * 128 * ASLD + ((buf) * 4 + (m)) * (64 * ASLD))
#define ATT_BF16_TOT (2 * 128 * ASLD + 8 * 64 * ASLD)
#define ATT_SMEM_BYTES (ATT_BF16_TOT * 2)

__global__ __launch_bounds__(256, 1) void attn_mma(bf16* __restrict__ outh,
                                                   bf16* __restrict__ outl)
{
    extern __shared__ char smraw[];
    bf16* sm = reinterpret_cast<bf16*>(smraw);

    const int b  = blockIdx.y >> 3;
    const int h  = blockIdx.y & 7;
    const int q0 = blockIdx.x * 128;

    const int qcnt = g_qcnt[b];
    const int qpad = (qcnt + 127) & ~127;
    if (q0 >= qpad) return;

    const int cnt = g_cnt[b];
    const int ntiles = (cnt + 63) >> 6;

    const int tid = threadIdx.x;
    const int warp = tid >> 5;
    const int lane = tid & 31;
    const int g = lane >> 2;
    const int t = lane & 3;
    const int rb = warp * 16;
    const float scale = 0.125f;
    const int tile = lane >> 3;
    const int trow = lane & 7;

    // Q prefetch: 128 rows x 64 dims, hi+lo
#pragma unroll
    for (int j = 0; j < 4; j++) {
        int c = tid * 4 + j;                  // 0..1023
        int row = c >> 3, dch = (c & 7) * 8;
        size_t base = (size_t)(b * NN + q0 + row) * INNER + h * 64 + dch;
        cp16(&A_Q(0)[row * ASLD + dch], &g_qc_h[base]);
        cp16(&A_Q(1)[row * ASLD + dch], &g_qc_l[base]);
    }
    cp_commit();

    auto pref = [&](int buf, int kt0) {
#pragma unroll
        for (int j = 0; j < 2; j++) {
            int c = tid * 2 + j;              // 0..511
            int row = c >> 3, dch = (c & 7) * 8;
            size_t base = ((size_t)(b * NN + kt0 + row)) * INNER + h * 64 + dch;
            cp16(&A_KV(buf, 0)[row * ASLD + dch], &g_kc_h[base]);
            cp16(&A_KV(buf, 1)[row * ASLD + dch], &g_kc_l[base]);
            cp16(&A_KV(buf, 2)[row * ASLD + dch], &g_vc_h[base]);
            cp16(&A_KV(buf, 3)[row * ASLD + dch], &g_vc_l[base]);
        }
    };

    if (ntiles > 0) { pref(0, 0); }
    cp_commit();

    float O[8][4];
#pragma unroll
    for (int nt = 0; nt < 8; nt++)
#pragma unroll
        for (int i = 0; i < 4; i++) O[nt][i] = 0.0f;
    float lsum0 = 0.0f, lsum8 = 0.0f;

    int buf = 0;
    for (int kt = 0; kt < ntiles; kt++) {
        const int kt0 = kt * 64;
        if (kt + 1 < ntiles) { pref(buf ^ 1, (kt + 1) * 64); cp_commit(); cp_wait<1>(); }
        else cp_wait<0>();
        __syncthreads();

        const bf16* QHs = A_Q(0);
        const bf16* QLs = A_Q(1);
        const bf16* KHs = A_KV(buf, 0);
        const bf16* KLs = A_KV(buf, 1);
        const bf16* VHs = A_KV(buf, 2);
        const bf16* VLs = A_KV(buf, 3);

        unsigned pah[4][4], pal[4][4];
        const int qr = rb + (tile & 1) * 8 + trow;

#pragma unroll
        for (int half = 0; half < 2; half++) {
            float sc[4][4];
#pragma unroll
            for (int nt = 0; nt < 4; nt++)
#pragma unroll
                for (int i = 0; i < 4; i++) sc[nt][i] = 0.0f;

#pragma unroll
            for (int kc = 0; kc < 4; kc++) {
                unsigned aqh[4], aql[4];
                ldsm4(aqh, &QHs[qr * ASLD + kc * 16 + (tile >> 1) * 8]);
                ldsm4(aql, &QLs[qr * ASLD + kc * 16 + (tile >> 1) * 8]);
                const int koff = kc * 16 + (tile & 1) * 8;
                unsigned kbh[2][4], kbl[2][4];
#pragma unroll
                for (int ntp = 0; ntp < 2; ntp++) {
                    const int nrow = (half * 2 + ntp) * 16 + (tile >> 1) * 8 + trow;
                    ldsm4(kbh[ntp], &KHs[nrow * ASLD + koff]);
                    ldsm4(kbl[ntp], &KLs[nrow * ASLD + koff]);
                }
#pragma unroll
                for (int ntp = 0; ntp < 2; ntp++)
#pragma unroll
                    for (int q = 0; q < 2; q++)
                        mma_bf16(sc[ntp * 2 + q], aqh, kbh[ntp][q * 2], kbh[ntp][q * 2 + 1]);
#pragma unroll
                for (int ntp = 0; ntp < 2; ntp++)
#pragma unroll
                    for (int q = 0; q < 2; q++)
                        mma_bf16(sc[ntp * 2 + q], aqh, kbl[ntp][q * 2], kbl[ntp][q * 2 + 1]);
#pragma unroll
                for (int ntp = 0; ntp < 2; ntp++)
#pragma unroll
                    for (int q = 0; q < 2; q++)
                        mma_bf16(sc[ntp * 2 + q], aql, kbh[ntp][q * 2], kbh[ntp][q * 2 + 1]);
            }

            // softmax (column validity = compacted index < cnt)
#pragma unroll
            for (int ntl = 0; ntl < 4; ntl++) {
                const int nt = half * 4 + ntl;
                const int kch = nt >> 1, q = nt & 1;
                const int colg = kt0 + nt * 8 + 2 * t;
                const bool v0c = colg < cnt;
                const bool v1c = colg + 1 < cnt;
                float p0 = v0c ? __expf(sc[ntl][0] * scale) : 0.0f;
                float p1 = v1c ? __expf(sc[ntl][1] * scale) : 0.0f;
                float p2 = v0c ? __expf(sc[ntl][2] * scale) : 0.0f;
                float p3 = v1c ? __expf(sc[ntl][3] * scale) : 0.0f;
                lsum0 += p0 + p1;
                lsum8 += p2 + p3;
                bf16 h0, l0, h1, l1, h2, l2, h3, l3;
                split1(p0, h0, l0); split1(p1, h1, l1);
                split1(p2, h2, l2); split1(p3, h3, l3);
                pah[kch][q * 2 + 0] = pack2(h0, h1);
                pah[kch][q * 2 + 1] = pack2(h2, h3);
                pal[kch][q * 2 + 0] = pack2(l0, l1);
                pal[kch][q * 2 + 1] = pack2(l2, l3);
            }
        }

        // ---- PV ----
#pragma unroll
        for (int kch = 0; kch < 4; kch++) {
            const int keyrow = kch * 16 + (tile & 1) * 8 + trow;
            unsigned vh[4][4], vl[4][4];
#pragma unroll
            for (int dp = 0; dp < 4; dp++) {
                const int dcol = dp * 16 + (tile >> 1) * 8;
                ldsm4t(vh[dp], &VHs[keyrow * ASLD + dcol]);
                ldsm4t(vl[dp], &VLs[keyrow * ASLD + dcol]);
            }
#pragma unroll
            for (int dp = 0; dp < 4; dp++)
#pragma unroll
                for (int q = 0; q < 2; q++)
                    mma_bf16(O[dp * 2 + q], pah[kch], vh[dp][q * 2], vh[dp][q * 2 + 1]);
#pragma unroll
            for (int dp = 0; dp < 4; dp++)
#pragma unroll
                for (int q = 0; q < 2; q++)
                    mma_bf16(O[dp * 2 + q], pah[kch], vl[dp][q * 2], vl[dp][q * 2 + 1]);
#pragma unroll
            for (int dp = 0; dp < 4; dp++)
#pragma unroll
                for (int q = 0; q < 2; q++)
                    mma_bf16(O[dp * 2 + q], pal[kch], vh[dp][q * 2], vh[dp][q * 2 + 1]);
        }
        __syncthreads();
        buf ^= 1;
    }

    // epilogue
    const size_t row0 = (size_t)(b * NN + q0 + rb + g);
    const size_t row8 = row0 + 8;
    if (cnt == 0) {
        // no surviving keys: uniform softmax over all keys = mean(V)
#pragma unroll
        for (int nt = 0; nt < 8; nt++) {
            const int d = h * 64 + nt * 8 + 2 * t;
            float m0 = g_vmean[b * INNER + d];
            float m1 = g_vmean[b * INNER + d + 1];
            bf16 h0, l0, h1, l1;
            split1(m0, h0, l0); split1(m1, h1, l1);
            unsigned ph = pack2(h0, h1), pl = pack2(l0, l1);
            *reinterpret_cast<unsigned*>(&outh[row0 * INNER + d]) = ph;
            *reinterpret_cast<unsigned*>(&outl[row0 * INNER + d]) = pl;
            *reinterpret_cast<unsigned*>(&outh[row8 * INNER + d]) = ph;
            *reinterpret_cast<unsigned*>(&outl[row8 * INNER + d]) = pl;
        }
        return;
    }
    lsum0 += __shfl_xor_sync(0xffffffffu, lsum0, 1);
    lsum0 += __shfl_xor_sync(0xffffffffu, lsum0, 2);
    lsum8 += __shfl_xor_sync(0xffffffffu, lsum8, 1);
    lsum8 += __shfl_xor_sync(0xffffffffu, lsum8, 2);
    const float inv0 = 1.0f / lsum0;
    const float inv8 = 1.0f / lsum8;

#pragma unroll
    for (int nt = 0; nt < 8; nt++) {
        const int d = h * 64 + nt * 8 + 2 * t;
        float v0 = O[nt][0] * inv0, v1 = O[nt][1] * inv0;
        float v2 = O[nt][2] * inv8, v3 = O[nt][3] * inv8;
        bf16 h0, l0, h1, l1, h2, l2, h3, l3;
        split1(v0, h0, l0); split1(v1, h1, l1);
        split1(v2, h2, l2); split1(v3, h3, l3);
        *reinterpret_cast<unsigned*>(&outh[row0 * INNER + d]) = pack2(h0, h1);
        *reinterpret_cast<unsigned*>(&outl[row0 * INNER + d]) = pack2(l0, l1);
        *reinterpret_cast<unsigned*>(&outh[row8 * INNER + d]) = pack2(h2, h3);
        *reinterpret_cast<unsigned*>(&outl[row8 * INNER + d]) = pack2(l2, l3);
    }
}

// ---------------------------------------------------------------------------
extern "C" void kernel_launch(void* const* d_in, const int* in_sizes, int n_in,
                              void* d_out, int out_size)
{
    const float* x     = (const float*)d_in[0];
    const int*   mnp   = (const int*)d_in[1];
    const int*   mbert = (const int*)d_in[2];
    const float* Wqkv  = (const float*)d_in[3];
    const float* Wout  = (const float*)d_in[4];
    const float* bout  = (const float*)d_in[5];
    float* out = (float*)d_out;

    bf16 *xh, *xl, *wqh, *wql, *woh, *wol;
    bf16 *qch, *qcl, *kch, *kcl, *vh, *vl, *atch, *atcl;
    int *idx, *qidx, *cntp, *qcntp;
    cudaGetSymbolAddress((void**)&xh,   g_x_h);
    cudaGetSymbolAddress((void**)&xl,   g_x_l);
    cudaGetSymbolAddress((void**)&wqh,  g_wqkv_h);
    cudaGetSymbolAddress((void**)&wql,  g_wqkv_l);
    cudaGetSymbolAddress((void**)&woh,  g_wout_h);
    cudaGetSymbolAddress((void**)&wol,  g_wout_l);
    cudaGetSymbolAddress((void**)&qch,  g_qc_h);
    cudaGetSymbolAddress((void**)&qcl,  g_qc_l);
    cudaGetSymbolAddress((void**)&kch,  g_kc_h);
    cudaGetSymbolAddress((void**)&kcl,  g_kc_l);
    cudaGetSymbolAddress((void**)&vh,   g_v_h);
    cudaGetSymbolAddress((void**)&vl,   g_v_l);
    cudaGetSymbolAddress((void**)&atch, g_atc_h);
    cudaGetSymbolAddress((void**)&atcl, g_atc_l);
    cudaGetSymbolAddress((void**)&idx,  g_idx);
    cudaGetSymbolAddress((void**)&qidx, g_qidx);
    cudaGetSymbolAddress((void**)&cntp, g_cnt);
    cudaGetSymbolAddress((void**)&qcntp, g_qcnt);

    cudaFuncSetAttribute(gemm_mma, cudaFuncAttributeMaxDynamicSharedMemorySize,
                         GEMM_SMEM_BYTES);
    cudaFuncSetAttribute(attn_mma, cudaFuncAttributeMaxDynamicSharedMemorySize,
                         ATT_SMEM_BYTES);

    // prep: split inputs into bf16 hi/lo
    split_kernel<<<512, 256>>>(x,    xh,  xl,  MROWS * DIM);
    split_kernel<<<512, 256>>>(Wqkv, wqh, wql, DIM * QKV3);
    split_kernel<<<256, 256>>>(Wout, woh, wol, INNER * DIM);

    // compactions
    build_compact<<<BB, 256>>>(mnp, mbert);
    build_qcompact<<<BB, 256>>>(mnp);

    // 1) three projection GEMMs (Q/K row-compacted, V full)
    gemm_mma<<<dim3(INNER / 128, MROWS / 128), 512, GEMM_SMEM_BYTES>>>(
        xh, xl, DIM, qidx, qcntp, wqh, wql, QKV3, nullptr,
        nullptr, qch, qcl, INNER, nullptr, INNER, DIM, 1);
    gemm_mma<<<dim3(INNER / 128, MROWS / 128), 512, GEMM_SMEM_BYTES>>>(
        xh, xl, DIM, idx, cntp, wqh + INNER, wql + INNER, QKV3, nullptr,
        nullptr, kch, kcl, INNER, nullptr, INNER, DIM, 1);
    gemm_mma<<<dim3(INNER / 128, MROWS / 128), 512, GEMM_SMEM_BYTES>>>(
        xh, xl, DIM, nullptr, nullptr, wqh + 2 * INNER, wql + 2 * INNER, QKV3, nullptr,
        nullptr, vh, vl, INNER, nullptr, INNER, DIM, 1);

    // V compaction + mean(V) + dead-row output vector
    gather_v<<<dim3(NN, BB), 128>>>();
    meanv_kernel<<<dim3(INNER / 64, BB), dim3(64, 8)>>>();
    deadvec_kernel<<<dim3(DIM / 64, BB), dim3(64, 8)>>>(Wout, bout);

    // 2) attention over compacted q-rows and keys -> compacted bf16 hi/lo
    attn_mma<<<dim3(NN / 128, BB * HH), 256, ATT_SMEM_BYTES>>>(atch, atcl);

    // 3) out = attc @ W_out + b_out with output scatter; dead rows filled
    gemm_mma<<<dim3(DIM / 128, MROWS / 128), 512, GEMM_SMEM_BYTES>>>(
        atch, atcl, INNER, nullptr, qcntp, woh, wol, DIM, bout,
        out, nullptr, nullptr, DIM, qidx, DIM, INNER, 0);
    dead_fill<<<dim3(NN, BB), 128>>>(out);
}

// round 10
// speedup vs baseline: 1.6898x; 1.3769x over previous
#include <cuda_runtime.h>
#include <cuda_bf16.h>
#include <math.h>

#define BB    2
#define NN    2048
#define DIM   512
#define HH    8
#define DH    64
#define INNER 512
#define QKV3  1536
#define MROWS (BB*NN)      // 4096

typedef __nv_bfloat16 bf16;

// ---------------- device scratch (no allocation allowed) ----------------
__device__ bf16 g_x_h[MROWS * DIM],    g_x_l[MROWS * DIM];
__device__ bf16 g_wqkv_h[DIM * QKV3],  g_wqkv_l[DIM * QKV3];
__device__ bf16 g_wout_h[INNER * DIM], g_wout_l[INNER * DIM];

// key compaction
__device__ int  g_cnt[BB];
__device__ int  g_idx[BB * NN];
__device__ bf16 g_kc_h[BB * NN * INNER], g_kc_l[BB * NN * INNER];
__device__ bf16 g_vc_h[BB * NN * INNER], g_vc_l[BB * NN * INNER];
__device__ float g_xmean[BB * DIM];
__device__ float g_vmean[BB * INNER];
__device__ float g_dead[BB * DIM];

// query compaction
__device__ int  g_qcnt[BB];
__device__ int  g_qidx[BB * NN];
__device__ int  g_qpos[BB * NN];
__device__ bf16 g_qc_h[BB * NN * INNER], g_qc_l[BB * NN * INNER];
__device__ bf16 g_atc_h[BB * NN * INNER], g_atc_l[BB * NN * INNER];

// ---------------- helpers ----------------
__device__ __forceinline__ unsigned s2u(const void* p) {
    return (unsigned)__cvta_generic_to_shared(p);
}
__device__ __forceinline__ void ldsm4(unsigned* r, const void* p) {
    asm volatile("ldmatrix.sync.aligned.m8n8.x4.shared.b16 {%0,%1,%2,%3}, [%4];"
        : "=r"(r[0]), "=r"(r[1]), "=r"(r[2]), "=r"(r[3]) : "r"(s2u(p)));
}
__device__ __forceinline__ void ldsm4t(unsigned* r, const void* p) {
    asm volatile("ldmatrix.sync.aligned.m8n8.x4.trans.shared.b16 {%0,%1,%2,%3}, [%4];"
        : "=r"(r[0]), "=r"(r[1]), "=r"(r[2]), "=r"(r[3]) : "r"(s2u(p)));
}
__device__ __forceinline__ void cp16(void* s, const void* g) {
    asm volatile("cp.async.cg.shared.global [%0], [%1], 16;" :: "r"(s2u(s)), "l"(g));
}
__device__ __forceinline__ void cp_commit() { asm volatile("cp.async.commit_group;"); }
template<int N> __device__ __forceinline__ void cp_wait() {
    asm volatile("cp.async.wait_group %0;" :: "n"(N));
}
__device__ __forceinline__ void mma_bf16(float* c, const unsigned* a, unsigned b0, unsigned b1) {
    asm volatile(
        "mma.sync.aligned.m16n8k16.row.col.f32.bf16.bf16.f32 "
        "{%0,%1,%2,%3}, {%4,%5,%6,%7}, {%8,%9}, {%0,%1,%2,%3};"
        : "+f"(c[0]), "+f"(c[1]), "+f"(c[2]), "+f"(c[3])
        : "r"(a[0]), "r"(a[1]), "r"(a[2]), "r"(a[3]), "r"(b0), "r"(b1));
}
__device__ __forceinline__ unsigned pack2(bf16 a, bf16 b) {
    __nv_bfloat162 v; v.x = a; v.y = b;
    return *reinterpret_cast<unsigned*>(&v);
}
__device__ __forceinline__ void split1(float v, bf16& h, bf16& l) {
    h = __float2bfloat16(v);
    l = __float2bfloat16(v - __bfloat162float(h));
}

// ---------------- prep: fused fp32 -> bf16 hi/lo split of all 3 inputs ------
__global__ void split3_kernel(const float* __restrict__ x,
                              const float* __restrict__ wqkv,
                              const float* __restrict__ wout)
{
    const int n1 = MROWS * DIM, n2 = DIM * QKV3, n3 = INNER * DIM;
    const int total = n1 + n2 + n3;
    for (int i = blockIdx.x * blockDim.x + threadIdx.x; i < total;
         i += gridDim.x * blockDim.x) {
        float v; bf16 *hi, *lo; int off;
        if (i < n1)            { v = x[i];            hi = g_x_h;    lo = g_x_l;    off = i; }
        else if (i < n1 + n2)  { off = i - n1; v = wqkv[off]; hi = g_wqkv_h; lo = g_wqkv_l; }
        else                   { off = i - n1 - n2; v = wout[off]; hi = g_wout_h; lo = g_wout_l; }
        bf16 h, l; split1(v, h, l);
        hi[off] = h; lo[off] = l;
    }
}

// ---------------- fused compactions (parallel scan); grid (2, BB) -----------
__global__ void build_both(const int* __restrict__ mnp, const int* __restrict__ mbert)
{
    const int b = blockIdx.y;
    const bool isQ = (blockIdx.x == 1);
    const int tid = threadIdx.x;
    __shared__ int scan[256];

    int flags[8];
    int local = 0;
#pragma unroll
    for (int k = 0; k < 8; k++) {
        int j = tid * 8 + k;
        int f;
        if (isQ) f = (mnp[b * NN + j] == 1);
        else     f = (mnp[b * NN + j] == 1) && (mbert[b * NN + j] == 0);
        flags[k] = f; local += f;
    }
    scan[tid] = local;
    __syncthreads();
    // Hillis-Steele inclusive scan over 256 counts
#pragma unroll
    for (int off = 1; off < 256; off <<= 1) {
        int add = (tid >= off) ? scan[tid - off] : 0;
        __syncthreads();
        scan[tid] += add;
        __syncthreads();
    }
    const int tot = scan[255];
    int o = scan[tid] - local;          // exclusive prefix
    if (isQ) {
        if (tid == 0) g_qcnt[b] = tot;
#pragma unroll
        for (int k = 0; k < 8; k++) {
            int j = tid * 8 + k;
            if (flags[k]) { g_qidx[b * NN + o] = j; g_qpos[b * NN + j] = o; o++; }
            else g_qpos[b * NN + j] = -1;
        }
        for (int i = tot + tid; i < NN; i += 256) g_qidx[b * NN + i] = 0;
    } else {
        if (tid == 0) g_cnt[b] = tot;
#pragma unroll
        for (int k = 0; k < 8; k++) {
            if (flags[k]) g_idx[b * NN + (o++)] = tid * 8 + k;
        }
        for (int i = tot + tid; i < NN; i += 256) g_idx[b * NN + i] = 0;
    }
}

// ---------------- mean of x rows (fp32, deterministic) ----------------------
__global__ void meanx_kernel(const float* __restrict__ x)
{
    const int b = blockIdx.y;
    const int d = blockIdx.x * 64 + threadIdx.x;
    const int yg = threadIdx.y;
    float s = 0.0f;
    for (int j = yg; j < NN; j += 8)
        s += x[((size_t)(b * NN + j)) * DIM + d];
    __shared__ float red[8][64];
    red[yg][threadIdx.x] = s;
    __syncthreads();
    if (yg == 0) {
        float tot = 0.0f;
#pragma unroll
        for (int i = 0; i < 8; i++) tot += red[i][threadIdx.x];
        g_xmean[b * DIM + d] = tot * (1.0f / NN);
    }
}

// ---------------- vmean = xmean @ Wv (fp32) ---------------------------------
__global__ void vmean_kernel(const float* __restrict__ Wqkv)
{
    const int b = blockIdx.y;
    const int col = blockIdx.x * 64 + threadIdx.x;   // over INNER
    const int yg = threadIdx.y;
    float s = 0.0f;
    for (int d = yg; d < DIM; d += 8)
        s += g_xmean[b * DIM + d] * Wqkv[(size_t)d * QKV3 + 2 * INNER + col];
    __shared__ float red[8][64];
    red[yg][threadIdx.x] = s;
    __syncthreads();
    if (yg == 0) {
        float tot = 0.0f;
#pragma unroll
        for (int i = 0; i < 8; i++) tot += red[i][threadIdx.x];
        g_vmean[b * INNER + col] = tot;
    }
}

// ---------------- dead-row output vector: vmean @ W_out + bias --------------
__global__ void deadvec_kernel(const float* __restrict__ Wout,
                               const float* __restrict__ bias)
{
    const int b = blockIdx.y;
    const int col = blockIdx.x * 64 + threadIdx.x;
    const int yg = threadIdx.y;
    float s = 0.0f;
    for (int d = yg; d < INNER; d += 8)
        s += g_vmean[b * INNER + d] * Wout[(size_t)d * DIM + col];
    __shared__ float red[8][64];
    red[yg][threadIdx.x] = s;
    __syncthreads();
    if (yg == 0) {
        float tot = bias[col];
#pragma unroll
        for (int i = 0; i < 8; i++) tot += red[i][threadIdx.x];
        g_dead[b * DIM + col] = tot;
    }
}

// ---------------- fill dead output rows -------------------------------------
__global__ void dead_fill(float* __restrict__ out)
{
    const int b = blockIdx.y;
    const int i = blockIdx.x;
    if (g_qpos[b * NN + i] >= 0) return;
    const int tid = threadIdx.x;            // 128 threads x 4 floats
    *reinterpret_cast<float4*>(&out[((size_t)(b * NN + i)) * DIM + tid * 4]) =
        *reinterpret_cast<const float4*>(&g_dead[b * DIM + tid * 4]);
}

// ---------------------------------------------------------------------------
// bf16x3 GEMM, 128x128 block, BK=32, 512 thr (16 warps; warp tile 32x32).
// Optional input-row indirection (ridx) + per-batch row count (cntp) +
// output-row indirection (oidx, mode 0 only, write-guarded by count).
// ---------------------------------------------------------------------------
#define GALD 40
#define GBLD 136
#define G_SA(buf,hl) (sm + ((buf)*2 + (hl)) * (128*GALD))
#define G_SB(buf,hl) (sm + 4*128*GALD + ((buf)*2 + (hl)) * (32*GBLD))
#define GEMM_SMEM_BYTES ((4*128*GALD + 4*32*GBLD) * 2)

__global__ __launch_bounds__(512, 1) void gemm_mma(const bf16* __restrict__ Ah,
                                                   const bf16* __restrict__ Al,
                                                   int lda,
                                                   const int* __restrict__ ridx,
                                                   const int* __restrict__ cntp,
                                                   const bf16* __restrict__ Bh,
                                                   const bf16* __restrict__ Bl,
                                                   int ldb,
                                                   const float* __restrict__ bias,
                                                   float* __restrict__ outf,
                                                   bf16* __restrict__ outh,
                                                   bf16* __restrict__ outl,
                                                   int ldo,
                                                   const int* __restrict__ oidx,
                                                   int N, int K, int mode)
{
    extern __shared__ bf16 sm[];

    const int bm = blockIdx.y * 128;
    const int bn = blockIdx.x * 128;
    const int b  = bm >> 11;                 // NN = 2048
    const int lm = bm & (NN - 1);
    const int bbase = b * NN;

    int cntv = NN;
    if (cntp) {
        cntv = cntp[b];
        if (lm >= ((cntv + 127) & ~127)) return;
    }

    const int tid = threadIdx.x;
    const int warp = tid >> 5;
    const int lane = tid & 31;
    const int g = lane >> 2;
    const int t = lane & 3;
    const int rowbase = (warp & 3) * 32;
    const int colbase = (warp >> 2) * 32;

    float acc[2][4][4];
#pragma unroll
    for (int mt = 0; mt < 2; mt++)
#pragma unroll
        for (int nt = 0; nt < 4; nt++)
#pragma unroll
            for (int i = 0; i < 4; i++) acc[mt][nt][i] = 0.0f;

    const int tile = lane >> 3;
    const int trow = lane & 7;

    const int arow = tid >> 2;
    const int akch = (tid & 3) * 8;
    int agrow;
    if (ridx) agrow = bbase + ridx[bbase + lm + arow];
    else      agrow = bm + arow;

    auto prefetch = [&](int buf, int k0) {
        {
            size_t go = (size_t)agrow * lda + k0 + akch;
            cp16(&G_SA(buf, 0)[arow * GALD + akch], &Ah[go]);
            cp16(&G_SA(buf, 1)[arow * GALD + akch], &Al[go]);
        }
        {
            int kr = tid >> 4, nch = (tid & 15) * 8;
            size_t go = (size_t)(k0 + kr) * ldb + bn + nch;
            cp16(&G_SB(buf, 0)[kr * GBLD + nch], &Bh[go]);
            cp16(&G_SB(buf, 1)[kr * GBLD + nch], &Bl[go]);
        }
    };

    prefetch(0, 0);
    cp_commit();

    const int NIT = K / 32;
    int buf = 0;
    for (int it = 0; it < NIT; it++) {
        if (it + 1 < NIT) { prefetch(buf ^ 1, (it + 1) * 32); cp_commit(); cp_wait<1>(); }
        else cp_wait<0>();
        __syncthreads();

        const bf16* As_h = G_SA(buf, 0);
        const bf16* As_l = G_SA(buf, 1);
        const bf16* Bs_h = G_SB(buf, 0);
        const bf16* Bs_l = G_SB(buf, 1);

#pragma unroll
        for (int kc = 0; kc < 2; kc++) {
            unsigned ah[2][4], al[2][4];
            const int amrow = (tile & 1) * 8 + trow;
            const int akoff = kc * 16 + (tile >> 1) * 8;
#pragma unroll
            for (int mt = 0; mt < 2; mt++) {
                ldsm4(ah[mt], &As_h[(rowbase + mt * 16 + amrow) * GALD + akoff]);
                ldsm4(al[mt], &As_l[(rowbase + mt * 16 + amrow) * GALD + akoff]);
            }
            const int bkrow = kc * 16 + (tile & 1) * 8 + trow;
            unsigned bh[2][4], bl[2][4];
#pragma unroll
            for (int ntp = 0; ntp < 2; ntp++) {
                const int bncol = colbase + ntp * 16 + (tile >> 1) * 8;
                ldsm4t(bh[ntp], &Bs_h[bkrow * GBLD + bncol]);
                ldsm4t(bl[ntp], &Bs_l[bkrow * GBLD + bncol]);
            }
#pragma unroll
            for (int mt = 0; mt < 2; mt++)
#pragma unroll
                for (int ntp = 0; ntp < 2; ntp++)
#pragma unroll
                    for (int q = 0; q < 2; q++)
                        mma_bf16(acc[mt][ntp * 2 + q], ah[mt], bh[ntp][q * 2], bh[ntp][q * 2 + 1]);
#pragma unroll
            for (int mt = 0; mt < 2; mt++)
#pragma unroll
                for (int ntp = 0; ntp < 2; ntp++)
#pragma unroll
                    for (int q = 0; q < 2; q++)
                        mma_bf16(acc[mt][ntp * 2 + q], ah[mt], bl[ntp][q * 2], bl[ntp][q * 2 + 1]);
#pragma unroll
            for (int mt = 0; mt < 2; mt++)
#pragma unroll
                for (int ntp = 0; ntp < 2; ntp++)
#pragma unroll
                    for (int q = 0; q < 2; q++)
                        mma_bf16(acc[mt][ntp * 2 + q], al[mt], bh[ntp][q * 2], bh[ntp][q * 2 + 1]);
        }
        __syncthreads();
        buf ^= 1;
    }

#pragma unroll
    for (int mt = 0; mt < 2; mt++) {
        const int lr0 = lm + rowbase + mt * 16 + g;
        const int lr1 = lr0 + 8;
#pragma unroll
        for (int nt = 0; nt < 4; nt++) {
            const int c0 = bn + colbase + nt * 8 + 2 * t;
            float v0 = acc[mt][nt][0], v1 = acc[mt][nt][1];
            float v2 = acc[mt][nt][2], v3 = acc[mt][nt][3];
            if (mode == 0) {
                float b0 = bias[c0], b1 = bias[c0 + 1];
                if (!oidx || lr0 < cntv) {
                    int orow = oidx ? (bbase + oidx[bbase + lr0]) : (bbase + lr0);
                    *reinterpret_cast<float2*>(&outf[(size_t)orow * ldo + c0]) =
                        make_float2(v0 + b0, v1 + b1);
                }
                if (!oidx || lr1 < cntv) {
                    int orow = oidx ? (bbase + oidx[bbase + lr1]) : (bbase + lr1);
                    *reinterpret_cast<float2*>(&outf[(size_t)orow * ldo + c0]) =
                        make_float2(v2 + b0, v3 + b1);
                }
            } else {
                bf16 h0, l0, h1, l1, h2, l2, h3, l3;
                split1(v0, h0, l0); split1(v1, h1, l1);
                split1(v2, h2, l2); split1(v3, h3, l3);
                const size_t r0o = (size_t)(bbase + lr0) * ldo + c0;
                const size_t r1o = (size_t)(bbase + lr1) * ldo + c0;
                *reinterpret_cast<unsigned*>(&outh[r0o]) = pack2(h0, h1);
                *reinterpret_cast<unsigned*>(&outl[r0o]) = pack2(l0, l1);
                *reinterpret_cast<unsigned*>(&outh[r1o]) = pack2(h2, h3);
                *reinterpret_cast<unsigned*>(&outl[r1o]) = pack2(l2, l3);
            }
        }
    }
}

// ---------------------------------------------------------------------------
// Attention over compacted Q rows and compacted keys.
// 256 thr (8 warps), 128 q-rows/block, 64-key tiles. No mask logic in loop.
// ---------------------------------------------------------------------------
#define ASLD 72
#define A_Q(hl)     (sm + (hl) * (128 * ASLD))
#define A_KV(buf,m) (sm + 2 * 128 * ASLD + ((buf) * 4 + (m)) * (64 * ASLD))
#define ATT_BF16_TOT (2 * 128 * ASLD + 8 * 64 * ASLD)
#define ATT_SMEM_BYTES (ATT_BF16_TOT * 2)

__global__ __launch_bounds__(256, 1) void attn_mma(bf16* __restrict__ outh,
                                                   bf16* __restrict__ outl)
{
    extern __shared__ char smraw[];
    bf16* sm = reinterpret_cast<bf16*>(smraw);

    const int b  = blockIdx.y >> 3;
    const int h  = blockIdx.y & 7;
    const int q0 = blockIdx.x * 128;

    const int qcnt = g_qcnt[b];
    const int qpad = (qcnt + 127) & ~127;
    if (q0 >= qpad) return;

    const int cnt = g_cnt[b];
    const int ntiles = (cnt + 63) >> 6;

    const int tid = threadIdx.x;
    const int warp = tid >> 5;
    const int lane = tid & 31;
    const int g = lane >> 2;
    const int t = lane & 3;
    const int rb = warp * 16;
    const float scale = 0.125f;
    const int tile = lane >> 3;
    const int trow = lane & 7;

#pragma unroll
    for (int j = 0; j < 4; j++) {
        int c = tid * 4 + j;
        int row = c >> 3, dch = (c & 7) * 8;
        size_t base = (size_t)(b * NN + q0 + row) * INNER + h * 64 + dch;
        cp16(&A_Q(0)[row * ASLD + dch], &g_qc_h[base]);
        cp16(&A_Q(1)[row * ASLD + dch], &g_qc_l[base]);
    }
    cp_commit();

    auto pref = [&](int buf, int kt0) {
#pragma unroll
        for (int j = 0; j < 2; j++) {
            int c = tid * 2 + j;
            int row = c >> 3, dch = (c & 7) * 8;
            size_t base = ((size_t)(b * NN + kt0 + row)) * INNER + h * 64 + dch;
            cp16(&A_KV(buf, 0)[row * ASLD + dch], &g_kc_h[base]);
            cp16(&A_KV(buf, 1)[row * ASLD + dch], &g_kc_l[base]);
            cp16(&A_KV(buf, 2)[row * ASLD + dch], &g_vc_h[base]);
            cp16(&A_KV(buf, 3)[row * ASLD + dch], &g_vc_l[base]);
        }
    };

    if (ntiles > 0) { pref(0, 0); }
    cp_commit();

    float O[8][4];
#pragma unroll
    for (int nt = 0; nt < 8; nt++)
#pragma unroll
        for (int i = 0; i < 4; i++) O[nt][i] = 0.0f;
    float lsum0 = 0.0f, lsum8 = 0.0f;

    int buf = 0;
    for (int kt = 0; kt < ntiles; kt++) {
        const int kt0 = kt * 64;
        if (kt + 1 < ntiles) { pref(buf ^ 1, (kt + 1) * 64); cp_commit(); cp_wait<1>(); }
        else cp_wait<0>();
        __syncthreads();

        const bf16* QHs = A_Q(0);
        const bf16* QLs = A_Q(1);
        const bf16* KHs = A_KV(buf, 0);
        const bf16* KLs = A_KV(buf, 1);
        const bf16* VHs = A_KV(buf, 2);
        const bf16* VLs = A_KV(buf, 3);

        unsigned pah[4][4], pal[4][4];
        const int qr = rb + (tile & 1) * 8 + trow;

#pragma unroll
        for (int half = 0; half < 2; half++) {
            float sc[4][4];
#pragma unroll
            for (int nt = 0; nt < 4; nt++)
#pragma unroll
                for (int i = 0; i < 4; i++) sc[nt][i] = 0.0f;

#pragma unroll
            for (int kc = 0; kc < 4; kc++) {
                unsigned aqh[4], aql[4];
                ldsm4(aqh, &QHs[qr * ASLD + kc * 16 + (tile >> 1) * 8]);
                ldsm4(aql, &QLs[qr * ASLD + kc * 16 + (tile >> 1) * 8]);
                const int koff = kc * 16 + (tile & 1) * 8;
                unsigned kbh[2][4], kbl[2][4];
#pragma unroll
                for (int ntp = 0; ntp < 2; ntp++) {
                    const int nrow = (half * 2 + ntp) * 16 + (tile >> 1) * 8 + trow;
                    ldsm4(kbh[ntp], &KHs[nrow * ASLD + koff]);
                    ldsm4(kbl[ntp], &KLs[nrow * ASLD + koff]);
                }
#pragma unroll
                for (int ntp = 0; ntp < 2; ntp++)
#pragma unroll
                    for (int q = 0; q < 2; q++)
                        mma_bf16(sc[ntp * 2 + q], aqh, kbh[ntp][q * 2], kbh[ntp][q * 2 + 1]);
#pragma unroll
                for (int ntp = 0; ntp < 2; ntp++)
#pragma unroll
                    for (int q = 0; q < 2; q++)
                        mma_bf16(sc[ntp * 2 + q], aqh, kbl[ntp][q * 2], kbl[ntp][q * 2 + 1]);
#pragma unroll
                for (int ntp = 0; ntp < 2; ntp++)
#pragma unroll
                    for (int q = 0; q < 2; q++)
                        mma_bf16(sc[ntp * 2 + q], aql, kbh[ntp][q * 2], kbh[ntp][q * 2 + 1]);
            }

#pragma unroll
            for (int ntl = 0; ntl < 4; ntl++) {
                const int nt = half * 4 + ntl;
                const int kch = nt >> 1, q = nt & 1;
                const int colg = kt0 + nt * 8 + 2 * t;
                const bool v0c = colg < cnt;
                const bool v1c = colg + 1 < cnt;
                float p0 = v0c ? __expf(sc[ntl][0] * scale) : 0.0f;
                float p1 = v1c ? __expf(sc[ntl][1] * scale) : 0.0f;
                float p2 = v0c ? __expf(sc[ntl][2] * scale) : 0.0f;
                float p3 = v1c ? __expf(sc[ntl][3] * scale) : 0.0f;
                lsum0 += p0 + p1;
                lsum8 += p2 + p3;
                bf16 h0, l0, h1, l1, h2, l2, h3, l3;
                split1(p0, h0, l0); split1(p1, h1, l1);
                split1(p2, h2, l2); split1(p3, h3, l3);
                pah[kch][q * 2 + 0] = pack2(h0, h1);
                pah[kch][q * 2 + 1] = pack2(h2, h3);
                pal[kch][q * 2 + 0] = pack2(l0, l1);
                pal[kch][q * 2 + 1] = pack2(l2, l3);
            }
        }

#pragma unroll
        for (int kch = 0; kch < 4; kch++) {
            const int keyrow = kch * 16 + (tile & 1) * 8 + trow;
            unsigned vh[4][4], vl[4][4];
#pragma unroll
            for (int dp = 0; dp < 4; dp++) {
                const int dcol = dp * 16 + (tile >> 1) * 8;
                ldsm4t(vh[dp], &VHs[keyrow * ASLD + dcol]);
                ldsm4t(vl[dp], &VLs[keyrow * ASLD + dcol]);
            }
#pragma unroll
            for (int dp = 0; dp < 4; dp++)
#pragma unroll
                for (int q = 0; q < 2; q++)
                    mma_bf16(O[dp * 2 + q], pah[kch], vh[dp][q * 2], vh[dp][q * 2 + 1]);
#pragma unroll
            for (int dp = 0; dp < 4; dp++)
#pragma unroll
                for (int q = 0; q < 2; q++)
                    mma_bf16(O[dp * 2 + q], pah[kch], vl[dp][q * 2], vl[dp][q * 2 + 1]);
#pragma unroll
            for (int dp = 0; dp < 4; dp++)
#pragma unroll
                for (int q = 0; q < 2; q++)
                    mma_bf16(O[dp * 2 + q], pal[kch], vh[dp][q * 2], vh[dp][q * 2 + 1]);
        }
        __syncthreads();
        buf ^= 1;
    }

    const size_t row0 = (size_t)(b * NN + q0 + rb + g);
    const size_t row8 = row0 + 8;
    if (cnt == 0) {
#pragma unroll
        for (int nt = 0; nt < 8; nt++) {
            const int d = h * 64 + nt * 8 + 2 * t;
            float m0 = g_vmean[b * INNER + d];
            float m1 = g_vmean[b * INNER + d + 1];
            bf16 h0, l0, h1, l1;
            split1(m0, h0, l0); split1(m1, h1, l1);
            unsigned ph = pack2(h0, h1), pl = pack2(l0, l1);
            *reinterpret_cast<unsigned*>(&outh[row0 * INNER + d]) = ph;
            *reinterpret_cast<unsigned*>(&outl[row0 * INNER + d]) = pl;
            *reinterpret_cast<unsigned*>(&outh[row8 * INNER + d]) = ph;
            *reinterpret_cast<unsigned*>(&outl[row8 * INNER + d]) = pl;
        }
        return;
    }
    lsum0 += __shfl_xor_sync(0xffffffffu, lsum0, 1);
    lsum0 += __shfl_xor_sync(0xffffffffu, lsum0, 2);
    lsum8 += __shfl_xor_sync(0xffffffffu, lsum8, 1);
    lsum8 += __shfl_xor_sync(0xffffffffu, lsum8, 2);
    const float inv0 = 1.0f / lsum0;
    const float inv8 = 1.0f / lsum8;

#pragma unroll
    for (int nt = 0; nt < 8; nt++) {
        const int d = h * 64 + nt * 8 + 2 * t;
        float v0 = O[nt][0] * inv0, v1 = O[nt][1] * inv0;
        float v2 = O[nt][2] * inv8, v3 = O[nt][3] * inv8;
        bf16 h0, l0, h1, l1, h2, l2, h3, l3;
        split1(v0, h0, l0); split1(v1, h1, l1);
        split1(v2, h2, l2); split1(v3, h3, l3);
        *reinterpret_cast<unsigned*>(&outh[row0 * INNER + d]) = pack2(h0, h1);
        *reinterpret_cast<unsigned*>(&outl[row0 * INNER + d]) = pack2(l0, l1);
        *reinterpret_cast<unsigned*>(&outh[row8 * INNER + d]) = pack2(h2, h3);
        *reinterpret_cast<unsigned*>(&outl[row8 * INNER + d]) = pack2(l2, l3);
    }
}

// ---------------------------------------------------------------------------
extern "C" void kernel_launch(void* const* d_in, const int* in_sizes, int n_in,
                              void* d_out, int out_size)
{
    const float* x     = (const float*)d_in[0];
    const int*   mnp   = (const int*)d_in[1];
    const int*   mbert = (const int*)d_in[2];
    const float* Wqkv  = (const float*)d_in[3];
    const float* Wout  = (const float*)d_in[4];
    const float* bout  = (const float*)d_in[5];
    float* out = (float*)d_out;

    bf16 *xh, *xl, *wqh, *wql, *woh, *wol;
    bf16 *qch, *qcl, *kch, *kcl, *vch, *vcl, *atch, *atcl;
    int *idx, *qidx, *cntp, *qcntp;
    cudaGetSymbolAddress((void**)&xh,   g_x_h);
    cudaGetSymbolAddress((void**)&xl,   g_x_l);
    cudaGetSymbolAddress((void**)&wqh,  g_wqkv_h);
    cudaGetSymbolAddress((void**)&wql,  g_wqkv_l);
    cudaGetSymbolAddress((void**)&woh,  g_wout_h);
    cudaGetSymbolAddress((void**)&wol,  g_wout_l);
    cudaGetSymbolAddress((void**)&qch,  g_qc_h);
    cudaGetSymbolAddress((void**)&qcl,  g_qc_l);
    cudaGetSymbolAddress((void**)&kch,  g_kc_h);
    cudaGetSymbolAddress((void**)&kcl,  g_kc_l);
    cudaGetSymbolAddress((void**)&vch,  g_vc_h);
    cudaGetSymbolAddress((void**)&vcl,  g_vc_l);
    cudaGetSymbolAddress((void**)&atch, g_atc_h);
    cudaGetSymbolAddress((void**)&atcl, g_atc_l);
    cudaGetSymbolAddress((void**)&idx,  g_idx);
    cudaGetSymbolAddress((void**)&qidx, g_qidx);
    cudaGetSymbolAddress((void**)&cntp, g_cnt);
    cudaGetSymbolAddress((void**)&qcntp, g_qcnt);

    cudaFuncSetAttribute(gemm_mma, cudaFuncAttributeMaxDynamicSharedMemorySize,
                         GEMM_SMEM_BYTES);
    cudaFuncSetAttribute(attn_mma, cudaFuncAttributeMaxDynamicSharedMemorySize,
                         ATT_SMEM_BYTES);

    // prep: fused split + fused compactions + mean chain
    split3_kernel<<<512, 256>>>(x, Wqkv, Wout);
    build_both<<<dim3(2, BB), 256>>>(mnp, mbert);
    meanx_kernel<<<dim3(DIM / 64, BB), dim3(64, 8)>>>(x);
    vmean_kernel<<<dim3(INNER / 64, BB), dim3(64, 8)>>>(Wqkv);
    deadvec_kernel<<<dim3(DIM / 64, BB), dim3(64, 8)>>>(Wout, bout);

    // 1) three row-compacted projection GEMMs (Q alive-rows, K/V surviving keys)
    gemm_mma<<<dim3(INNER / 128, MROWS / 128), 512, GEMM_SMEM_BYTES>>>(
        xh, xl, DIM, qidx, qcntp, wqh, wql, QKV3, nullptr,
        nullptr, qch, qcl, INNER, nullptr, INNER, DIM, 1);
    gemm_mma<<<dim3(INNER / 128, MROWS / 128), 512, GEMM_SMEM_BYTES>>>(
        xh, xl, DIM, idx, cntp, wqh + INNER, wql + INNER, QKV3, nullptr,
        nullptr, kch, kcl, INNER, nullptr, INNER, DIM, 1);
    gemm_mma<<<dim3(INNER / 128, MROWS / 128), 512, GEMM_SMEM_BYTES>>>(
        xh, xl, DIM, idx, cntp, wqh + 2 * INNER, wql + 2 * INNER, QKV3, nullptr,
        nullptr, vch, vcl, INNER, nullptr, INNER, DIM, 1);

    // 2) attention over compacted q-rows and keys -> compacted bf16 hi/lo
    attn_mma<<<dim3(NN / 128, BB * HH), 256, ATT_SMEM_BYTES>>>(atch, atcl);

    // 3) out = attc @ W_out + b_out with output scatter; dead rows filled
    gemm_mma<<<dim3(DIM / 128, MROWS / 128), 512, GEMM_SMEM_BYTES>>>(
        atch, atcl, INNER, nullptr, qcntp, woh, wol, DIM, bout,
        out, nullptr, nullptr, DIM, qidx, DIM, INNER, 0);
    dead_fill<<<dim3(NN, BB), 128>>>(out);
}

// round 11
// speedup vs baseline: 2.1422x; 1.2677x over previous
#include <cuda_runtime.h>
#include <cuda_bf16.h>
#include <math.h>

#define BB    2
#define NN    2048
#define DIM   512
#define HH    8
#define DH    64
#define INNER 512
#define QKV3  1536
#define MROWS (BB*NN)      // 4096

typedef __nv_bfloat16 bf16;

// ---------------- device scratch (no allocation allowed) ----------------
__device__ bf16 g_x_h[MROWS * DIM],    g_x_l[MROWS * DIM];
__device__ bf16 g_wqkv_h[DIM * QKV3],  g_wqkv_l[DIM * QKV3];
__device__ bf16 g_wout_h[INNER * DIM], g_wout_l[INNER * DIM];

// key compaction + fused K|V buffer (K at col 0..511, V at col 512..1023)
__device__ int  g_cnt[BB];
__device__ int  g_idx[BB * NN];
__device__ bf16 g_kvc_h[BB * NN * 1024], g_kvc_l[BB * NN * 1024];
__device__ float g_xpart[BB * 8 * DIM];
__device__ float g_vmean[BB * INNER];
__device__ float g_dead[BB * DIM];

// query compaction
__device__ int  g_qcnt[BB];
__device__ int  g_qidx[BB * NN];
__device__ int  g_qpos[BB * NN];
__device__ bf16 g_qc_h[BB * NN * INNER], g_qc_l[BB * NN * INNER];
__device__ bf16 g_atc_h[BB * NN * INNER], g_atc_l[BB * NN * INNER];

// ---------------- helpers ----------------
__device__ __forceinline__ unsigned s2u(const void* p) {
    return (unsigned)__cvta_generic_to_shared(p);
}
__device__ __forceinline__ void ldsm4(unsigned* r, const void* p) {
    asm volatile("ldmatrix.sync.aligned.m8n8.x4.shared.b16 {%0,%1,%2,%3}, [%4];"
        : "=r"(r[0]), "=r"(r[1]), "=r"(r[2]), "=r"(r[3]) : "r"(s2u(p)));
}
__device__ __forceinline__ void ldsm4t(unsigned* r, const void* p) {
    asm volatile("ldmatrix.sync.aligned.m8n8.x4.trans.shared.b16 {%0,%1,%2,%3}, [%4];"
        : "=r"(r[0]), "=r"(r[1]), "=r"(r[2]), "=r"(r[3]) : "r"(s2u(p)));
}
__device__ __forceinline__ void cp16(void* s, const void* g) {
    asm volatile("cp.async.cg.shared.global [%0], [%1], 16;" :: "r"(s2u(s)), "l"(g));
}
__device__ __forceinline__ void cp_commit() { asm volatile("cp.async.commit_group;"); }
template<int N> __device__ __forceinline__ void cp_wait() {
    asm volatile("cp.async.wait_group %0;" :: "n"(N));
}
__device__ __forceinline__ void mma_bf16(float* c, const unsigned* a, unsigned b0, unsigned b1) {
    asm volatile(
        "mma.sync.aligned.m16n8k16.row.col.f32.bf16.bf16.f32 "
        "{%0,%1,%2,%3}, {%4,%5,%6,%7}, {%8,%9}, {%0,%1,%2,%3};"
        : "+f"(c[0]), "+f"(c[1]), "+f"(c[2]), "+f"(c[3])
        : "r"(a[0]), "r"(a[1]), "r"(a[2]), "r"(a[3]), "r"(b0), "r"(b1));
}
__device__ __forceinline__ unsigned pack2(bf16 a, bf16 b) {
    __nv_bfloat162 v; v.x = a; v.y = b;
    return *reinterpret_cast<unsigned*>(&v);
}
__device__ __forceinline__ void split1(float v, bf16& h, bf16& l) {
    h = __float2bfloat16(v);
    l = __float2bfloat16(v - __bfloat162float(h));
}

// ---------------- prep: fused fp32 -> bf16 hi/lo split of all 3 inputs ------
__global__ void split3_kernel(const float* __restrict__ x,
                              const float* __restrict__ wqkv,
                              const float* __restrict__ wout)
{
    const int n1 = MROWS * DIM, n2 = DIM * QKV3, n3 = INNER * DIM;
    const int total = n1 + n2 + n3;
    for (int i = blockIdx.x * blockDim.x + threadIdx.x; i < total;
         i += gridDim.x * blockDim.x) {
        float v; bf16 *hi, *lo; int off;
        if (i < n1)            { v = x[i];            hi = g_x_h;    lo = g_x_l;    off = i; }
        else if (i < n1 + n2)  { off = i - n1; v = wqkv[off]; hi = g_wqkv_h; lo = g_wqkv_l; }
        else                   { off = i - n1 - n2; v = wout[off]; hi = g_wout_h; lo = g_wout_l; }
        bf16 h, l; split1(v, h, l);
        hi[off] = h; lo[off] = l;
    }
}

// ---------------- fused compactions (parallel scan); grid (2, BB) -----------
__global__ void build_both(const int* __restrict__ mnp, const int* __restrict__ mbert)
{
    const int b = blockIdx.y;
    const bool isQ = (blockIdx.x == 1);
    const int tid = threadIdx.x;
    __shared__ int scan[256];

    int flags[8];
    int local = 0;
#pragma unroll
    for (int k = 0; k < 8; k++) {
        int j = tid * 8 + k;
        int f;
        if (isQ) f = (mnp[b * NN + j] == 1);
        else     f = (mnp[b * NN + j] == 1) && (mbert[b * NN + j] == 0);
        flags[k] = f; local += f;
    }
    scan[tid] = local;
    __syncthreads();
#pragma unroll
    for (int off = 1; off < 256; off <<= 1) {
        int add = (tid >= off) ? scan[tid - off] : 0;
        __syncthreads();
        scan[tid] += add;
        __syncthreads();
    }
    const int tot = scan[255];
    int o = scan[tid] - local;
    if (isQ) {
        if (tid == 0) g_qcnt[b] = tot;
#pragma unroll
        for (int k = 0; k < 8; k++) {
            int j = tid * 8 + k;
            if (flags[k]) { g_qidx[b * NN + o] = j; g_qpos[b * NN + j] = o; o++; }
            else g_qpos[b * NN + j] = -1;
        }
        for (int i = tot + tid; i < NN; i += 256) g_qidx[b * NN + i] = 0;
    } else {
        if (tid == 0) g_cnt[b] = tot;
#pragma unroll
        for (int k = 0; k < 8; k++) {
            if (flags[k]) g_idx[b * NN + (o++)] = tid * 8 + k;
        }
        for (int i = tot + tid; i < NN; i += 256) g_idx[b * NN + i] = 0;
    }
}

// ---------------- partial sums of x rows: grid (DIM/64, BB, 8) --------------
__global__ void meanx_part(const float* __restrict__ x)
{
    const int b = blockIdx.y;
    const int z = blockIdx.z;                    // row chunk of 256
    const int d = blockIdx.x * 64 + threadIdx.x;
    const int yg = threadIdx.y;                  // 8 groups
    float s = 0.0f;
    const int r0 = z * 256;
    for (int j = yg; j < 256; j += 8)
        s += x[((size_t)(b * NN + r0 + j)) * DIM + d];
    __shared__ float red[8][64];
    red[yg][threadIdx.x] = s;
    __syncthreads();
    if (yg == 0) {
        float tot = 0.0f;
#pragma unroll
        for (int i = 0; i < 8; i++) tot += red[i][threadIdx.x];
        g_xpart[(b * 8 + z) * DIM + d] = tot;
    }
}

// ---------------- vmean = (reduce xpart)/N @ Wv;  block (64, 16) ------------
__global__ void vmean_kernel(const float* __restrict__ Wqkv)
{
    const int b = blockIdx.y;
    const int col = blockIdx.x * 64 + threadIdx.x;   // over INNER
    const int yg = threadIdx.y;                      // 16 groups
    const int tid = threadIdx.y * 64 + threadIdx.x;
    __shared__ float xm[DIM];
    if (tid < DIM) {
        float s = 0.0f;
#pragma unroll
        for (int z = 0; z < 8; z++) s += g_xpart[(b * 8 + z) * DIM + tid];
        xm[tid] = s * (1.0f / NN);
    }
    __syncthreads();
    float s = 0.0f;
#pragma unroll 4
    for (int d = yg; d < DIM; d += 16)
        s += xm[d] * Wqkv[(size_t)d * QKV3 + 2 * INNER + col];
    __shared__ float red[16][64];
    red[yg][threadIdx.x] = s;
    __syncthreads();
    if (yg == 0) {
        float tot = 0.0f;
#pragma unroll
        for (int i = 0; i < 16; i++) tot += red[i][threadIdx.x];
        g_vmean[b * INNER + col] = tot;
    }
}

// ---------------- dead-row output vector: vmean @ W_out + bias; (64,16) -----
__global__ void deadvec_kernel(const float* __restrict__ Wout,
                               const float* __restrict__ bias)
{
    const int b = blockIdx.y;
    const int col = blockIdx.x * 64 + threadIdx.x;
    const int yg = threadIdx.y;                      // 16 groups
    float s = 0.0f;
#pragma unroll 4
    for (int d = yg; d < INNER; d += 16)
        s += g_vmean[b * INNER + d] * Wout[(size_t)d * DIM + col];
    __shared__ float red[16][64];
    red[yg][threadIdx.x] = s;
    __syncthreads();
    if (yg == 0) {
        float tot = bias[col];
#pragma unroll
        for (int i = 0; i < 16; i++) tot += red[i][threadIdx.x];
        g_dead[b * DIM + col] = tot;
    }
}

// ---------------- fill dead output rows -------------------------------------
__global__ void dead_fill(float* __restrict__ out)
{
    const int b = blockIdx.y;
    const int i = blockIdx.x;
    if (g_qpos[b * NN + i] >= 0) return;
    const int tid = threadIdx.x;            // 128 threads x 4 floats
    *reinterpret_cast<float4*>(&out[((size_t)(b * NN + i)) * DIM + tid * 4]) =
        *reinterpret_cast<const float4*>(&g_dead[b * DIM + tid * 4]);
}

// ---------------------------------------------------------------------------
// bf16x3 GEMM, 128x128 block, BK=32, 512 thr (16 warps; warp tile 32x32).
// Optional input-row indirection (ridx) + per-batch row count (cntp) +
// output-row indirection (oidx, mode 0 only, write-guarded by count).
// ---------------------------------------------------------------------------
#define GALD 40
#define GBLD 136
#define G_SA(buf,hl) (sm + ((buf)*2 + (hl)) * (128*GALD))
#define G_SB(buf,hl) (sm + 4*128*GALD + ((buf)*2 + (hl)) * (32*GBLD))
#define GEMM_SMEM_BYTES ((4*128*GALD + 4*32*GBLD) * 2)

__global__ __launch_bounds__(512, 1) void gemm_mma(const bf16* __restrict__ Ah,
                                                   const bf16* __restrict__ Al,
                                                   int lda,
                                                   const int* __restrict__ ridx,
                                                   const int* __restrict__ cntp,
                                                   const bf16* __restrict__ Bh,
                                                   const bf16* __restrict__ Bl,
                                                   int ldb,
                                                   const float* __restrict__ bias,
                                                   float* __restrict__ outf,
                                                   bf16* __restrict__ outh,
                                                   bf16* __restrict__ outl,
                                                   int ldo,
                                                   const int* __restrict__ oidx,
                                                   int N, int K, int mode)
{
    extern __shared__ bf16 sm[];

    const int bm = blockIdx.y * 128;
    const int bn = blockIdx.x * 128;
    const int b  = bm >> 11;                 // NN = 2048
    const int lm = bm & (NN - 1);
    const int bbase = b * NN;

    int cntv = NN;
    if (cntp) {
        cntv = cntp[b];
        if (lm >= ((cntv + 127) & ~127)) return;
    }

    const int tid = threadIdx.x;
    const int warp = tid >> 5;
    const int lane = tid & 31;
    const int g = lane >> 2;
    const int t = lane & 3;
    const int rowbase = (warp & 3) * 32;
    const int colbase = (warp >> 2) * 32;

    float acc[2][4][4];
#pragma unroll
    for (int mt = 0; mt < 2; mt++)
#pragma unroll
        for (int nt = 0; nt < 4; nt++)
#pragma unroll
            for (int i = 0; i < 4; i++) acc[mt][nt][i] = 0.0f;

    const int tile = lane >> 3;
    const int trow = lane & 7;

    const int arow = tid >> 2;
    const int akch = (tid & 3) * 8;
    int agrow;
    if (ridx) agrow = bbase + ridx[bbase + lm + arow];
    else      agrow = bm + arow;

    auto prefetch = [&](int buf, int k0) {
        {
            size_t go = (size_t)agrow * lda + k0 + akch;
            cp16(&G_SA(buf, 0)[arow * GALD + akch], &Ah[go]);
            cp16(&G_SA(buf, 1)[arow * GALD + akch], &Al[go]);
        }
        {
            int kr = tid >> 4, nch = (tid & 15) * 8;
            size_t go = (size_t)(k0 + kr) * ldb + bn + nch;
            cp16(&G_SB(buf, 0)[kr * GBLD + nch], &Bh[go]);
            cp16(&G_SB(buf, 1)[kr * GBLD + nch], &Bl[go]);
        }
    };

    prefetch(0, 0);
    cp_commit();

    const int NIT = K / 32;
    int buf = 0;
    for (int it = 0; it < NIT; it++) {
        if (it + 1 < NIT) { prefetch(buf ^ 1, (it + 1) * 32); cp_commit(); cp_wait<1>(); }
        else cp_wait<0>();
        __syncthreads();

        const bf16* As_h = G_SA(buf, 0);
        const bf16* As_l = G_SA(buf, 1);
        const bf16* Bs_h = G_SB(buf, 0);
        const bf16* Bs_l = G_SB(buf, 1);

#pragma unroll
        for (int kc = 0; kc < 2; kc++) {
            unsigned ah[2][4], al[2][4];
            const int amrow = (tile & 1) * 8 + trow;
            const int akoff = kc * 16 + (tile >> 1) * 8;
#pragma unroll
            for (int mt = 0; mt < 2; mt++) {
                ldsm4(ah[mt], &As_h[(rowbase + mt * 16 + amrow) * GALD + akoff]);
                ldsm4(al[mt], &As_l[(rowbase + mt * 16 + amrow) * GALD + akoff]);
            }
            const int bkrow = kc * 16 + (tile & 1) * 8 + trow;
            unsigned bh[2][4], bl[2][4];
#pragma unroll
            for (int ntp = 0; ntp < 2; ntp++) {
                const int bncol = colbase + ntp * 16 + (tile >> 1) * 8;
                ldsm4t(bh[ntp], &Bs_h[bkrow * GBLD + bncol]);
                ldsm4t(bl[ntp], &Bs_l[bkrow * GBLD + bncol]);
            }
#pragma unroll
            for (int mt = 0; mt < 2; mt++)
#pragma unroll
                for (int ntp = 0; ntp < 2; ntp++)
#pragma unroll
                    for (int q = 0; q < 2; q++)
                        mma_bf16(acc[mt][ntp * 2 + q], ah[mt], bh[ntp][q * 2], bh[ntp][q * 2 + 1]);
#pragma unroll
            for (int mt = 0; mt < 2; mt++)
#pragma unroll
                for (int ntp = 0; ntp < 2; ntp++)
#pragma unroll
                    for (int q = 0; q < 2; q++)
                        mma_bf16(acc[mt][ntp * 2 + q], ah[mt], bl[ntp][q * 2], bl[ntp][q * 2 + 1]);
#pragma unroll
            for (int mt = 0; mt < 2; mt++)
#pragma unroll
                for (int ntp = 0; ntp < 2; ntp++)
#pragma unroll
                    for (int q = 0; q < 2; q++)
                        mma_bf16(acc[mt][ntp * 2 + q], al[mt], bh[ntp][q * 2], bh[ntp][q * 2 + 1]);
        }
        __syncthreads();
        buf ^= 1;
    }

#pragma unroll
    for (int mt = 0; mt < 2; mt++) {
        const int lr0 = lm + rowbase + mt * 16 + g;
        const int lr1 = lr0 + 8;
#pragma unroll
        for (int nt = 0; nt < 4; nt++) {
            const int c0 = bn + colbase + nt * 8 + 2 * t;
            float v0 = acc[mt][nt][0], v1 = acc[mt][nt][1];
            float v2 = acc[mt][nt][2], v3 = acc[mt][nt][3];
            if (mode == 0) {
                float b0 = bias[c0], b1 = bias[c0 + 1];
                if (!oidx || lr0 < cntv) {
                    int orow = oidx ? (bbase + oidx[bbase + lr0]) : (bbase + lr0);
                    *reinterpret_cast<float2*>(&outf[(size_t)orow * ldo + c0]) =
                        make_float2(v0 + b0, v1 + b1);
                }
                if (!oidx || lr1 < cntv) {
                    int orow = oidx ? (bbase + oidx[bbase + lr1]) : (bbase + lr1);
                    *reinterpret_cast<float2*>(&outf[(size_t)orow * ldo + c0]) =
                        make_float2(v2 + b0, v3 + b1);
                }
            } else {
                bf16 h0, l0, h1, l1, h2, l2, h3, l3;
                split1(v0, h0, l0); split1(v1, h1, l1);
                split1(v2, h2, l2); split1(v3, h3, l3);
                const size_t r0o = (size_t)(bbase + lr0) * ldo + c0;
                const size_t r1o = (size_t)(bbase + lr1) * ldo + c0;
                *reinterpret_cast<unsigned*>(&outh[r0o]) = pack2(h0, h1);
                *reinterpret_cast<unsigned*>(&outl[r0o]) = pack2(l0, l1);
                *reinterpret_cast<unsigned*>(&outh[r1o]) = pack2(h2, h3);
                *reinterpret_cast<unsigned*>(&outl[r1o]) = pack2(l2, l3);
            }
        }
    }
}

// ---------------------------------------------------------------------------
// Attention over compacted Q rows and fused K|V buffer.
// 256 thr (8 warps), 128 q-rows/block, 64-key tiles.
// ---------------------------------------------------------------------------
#define ASLD 72
#define A_Q(hl)     (sm + (hl) * (128 * ASLD))
#define A_KV(buf,m) (sm + 2 * 128 * ASLD + ((buf) * 4 + (m)) * (64 * ASLD))
#define ATT_BF16_TOT (2 * 128 * ASLD + 8 * 64 * ASLD)
#define ATT_SMEM_BYTES (ATT_BF16_TOT * 2)

__global__ __launch_bounds__(256, 1) void attn_mma(bf16* __restrict__ outh,
                                                   bf16* __restrict__ outl)
{
    extern __shared__ char smraw[];
    bf16* sm = reinterpret_cast<bf16*>(smraw);

    const int b  = blockIdx.y >> 3;
    const int h  = blockIdx.y & 7;
    const int q0 = blockIdx.x * 128;

    const int qcnt = g_qcnt[b];
    const int qpad = (qcnt + 127) & ~127;
    if (q0 >= qpad) return;

    const int cnt = g_cnt[b];
    const int ntiles = (cnt + 63) >> 6;

    const int tid = threadIdx.x;
    const int warp = tid >> 5;
    const int lane = tid & 31;
    const int g = lane >> 2;
    const int t = lane & 3;
    const int rb = warp * 16;
    const float scale = 0.125f;
    const int tile = lane >> 3;
    const int trow = lane & 7;

#pragma unroll
    for (int j = 0; j < 4; j++) {
        int c = tid * 4 + j;
        int row = c >> 3, dch = (c & 7) * 8;
        size_t base = (size_t)(b * NN + q0 + row) * INNER + h * 64 + dch;
        cp16(&A_Q(0)[row * ASLD + dch], &g_qc_h[base]);
        cp16(&A_Q(1)[row * ASLD + dch], &g_qc_l[base]);
    }
    cp_commit();

    auto pref = [&](int buf, int kt0) {
#pragma unroll
        for (int j = 0; j < 2; j++) {
            int c = tid * 2 + j;
            int row = c >> 3, dch = (c & 7) * 8;
            size_t base = ((size_t)(b * NN + kt0 + row)) * 1024 + h * 64 + dch;
            cp16(&A_KV(buf, 0)[row * ASLD + dch], &g_kvc_h[base]);
            cp16(&A_KV(buf, 1)[row * ASLD + dch], &g_kvc_l[base]);
            cp16(&A_KV(buf, 2)[row * ASLD + dch], &g_kvc_h[base + 512]);
            cp16(&A_KV(buf, 3)[row * ASLD + dch], &g_kvc_l[base + 512]);
        }
    };

    if (ntiles > 0) { pref(0, 0); }
    cp_commit();

    float O[8][4];
#pragma unroll
    for (int nt = 0; nt < 8; nt++)
#pragma unroll
        for (int i = 0; i < 4; i++) O[nt][i] = 0.0f;
    float lsum0 = 0.0f, lsum8 = 0.0f;

    int buf = 0;
    for (int kt = 0; kt < ntiles; kt++) {
        const int kt0 = kt * 64;
        if (kt + 1 < ntiles) { pref(buf ^ 1, (kt + 1) * 64); cp_commit(); cp_wait<1>(); }
        else cp_wait<0>();
        __syncthreads();

        const bf16* QHs = A_Q(0);
        const bf16* QLs = A_Q(1);
        const bf16* KHs = A_KV(buf, 0);
        const bf16* KLs = A_KV(buf, 1);
        const bf16* VHs = A_KV(buf, 2);
        const bf16* VLs = A_KV(buf, 3);

        unsigned pah[4][4], pal[4][4];
        const int qr = rb + (tile & 1) * 8 + trow;

#pragma unroll
        for (int half = 0; half < 2; half++) {
            float sc[4][4];
#pragma unroll
            for (int nt = 0; nt < 4; nt++)
#pragma unroll
                for (int i = 0; i < 4; i++) sc[nt][i] = 0.0f;

#pragma unroll
            for (int kc = 0; kc < 4; kc++) {
                unsigned aqh[4], aql[4];
                ldsm4(aqh, &QHs[qr * ASLD + kc * 16 + (tile >> 1) * 8]);
                ldsm4(aql, &QLs[qr * ASLD + kc * 16 + (tile >> 1) * 8]);
                const int koff = kc * 16 + (tile & 1) * 8;
                unsigned kbh[2][4], kbl[2][4];
#pragma unroll
                for (int ntp = 0; ntp < 2; ntp++) {
                    const int nrow = (half * 2 + ntp) * 16 + (tile >> 1) * 8 + trow;
                    ldsm4(kbh[ntp], &KHs[nrow * ASLD + koff]);
                    ldsm4(kbl[ntp], &KLs[nrow * ASLD + koff]);
                }
#pragma unroll
                for (int ntp = 0; ntp < 2; ntp++)
#pragma unroll
                    for (int q = 0; q < 2; q++)
                        mma_bf16(sc[ntp * 2 + q], aqh, kbh[ntp][q * 2], kbh[ntp][q * 2 + 1]);
#pragma unroll
                for (int ntp = 0; ntp < 2; ntp++)
#pragma unroll
                    for (int q = 0; q < 2; q++)
                        mma_bf16(sc[ntp * 2 + q], aqh, kbl[ntp][q * 2], kbl[ntp][q * 2 + 1]);
#pragma unroll
                for (int ntp = 0; ntp < 2; ntp++)
#pragma unroll
                    for (int q = 0; q < 2; q++)
                        mma_bf16(sc[ntp * 2 + q], aql, kbh[ntp][q * 2], kbh[ntp][q * 2 + 1]);
            }

#pragma unroll
            for (int ntl = 0; ntl < 4; ntl++) {
                const int nt = half * 4 + ntl;
                const int kch = nt >> 1, q = nt & 1;
                const int colg = kt0 + nt * 8 + 2 * t;
                const bool v0c = colg < cnt;
                const bool v1c = colg + 1 < cnt;
                float p0 = v0c ? __expf(sc[ntl][0] * scale) : 0.0f;
                float p1 = v1c ? __expf(sc[ntl][1] * scale) : 0.0f;
                float p2 = v0c ? __expf(sc[ntl][2] * scale) : 0.0f;
                float p3 = v1c ? __expf(sc[ntl][3] * scale) : 0.0f;
                lsum0 += p0 + p1;
                lsum8 += p2 + p3;
                bf16 h0, l0, h1, l1, h2, l2, h3, l3;
                split1(p0, h0, l0); split1(p1, h1, l1);
                split1(p2, h2, l2); split1(p3, h3, l3);
                pah[kch][q * 2 + 0] = pack2(h0, h1);
                pah[kch][q * 2 + 1] = pack2(h2, h3);
                pal[kch][q * 2 + 0] = pack2(l0, l1);
                pal[kch][q * 2 + 1] = pack2(l2, l3);
            }
        }

#pragma unroll
        for (int kch = 0; kch < 4; kch++) {
            const int keyrow = kch * 16 + (tile & 1) * 8 + trow;
            unsigned vh[4][4], vl[4][4];
#pragma unroll
            for (int dp = 0; dp < 4; dp++) {
                const int dcol = dp * 16 + (tile >> 1) * 8;
                ldsm4t(vh[dp], &VHs[keyrow * ASLD + dcol]);
                ldsm4t(vl[dp], &VLs[keyrow * ASLD + dcol]);
            }
#pragma unroll
            for (int dp = 0; dp < 4; dp++)
#pragma unroll
                for (int q = 0; q < 2; q++)
                    mma_bf16(O[dp * 2 + q], pah[kch], vh[dp][q * 2], vh[dp][q * 2 + 1]);
#pragma unroll
            for (int dp = 0; dp < 4; dp++)
#pragma unroll
                for (int q = 0; q < 2; q++)
                    mma_bf16(O[dp * 2 + q], pah[kch], vl[dp][q * 2], vl[dp][q * 2 + 1]);
#pragma unroll
            for (int dp = 0; dp < 4; dp++)
#pragma unroll
                for (int q = 0; q < 2; q++)
                    mma_bf16(O[dp * 2 + q], pal[kch], vh[dp][q * 2], vh[dp][q * 2 + 1]);
        }
        __syncthreads();
        buf ^= 1;
    }

    const size_t row0 = (size_t)(b * NN + q0 + rb + g);
    const size_t row8 = row0 + 8;
    if (cnt == 0) {
#pragma unroll
        for (int nt = 0; nt < 8; nt++) {
            const int d = h * 64 + nt * 8 + 2 * t;
            float m0 = g_vmean[b * INNER + d];
            float m1 = g_vmean[b * INNER + d + 1];
            bf16 h0, l0, h1, l1;
            split1(m0, h0, l0); split1(m1, h1, l1);
            unsigned ph = pack2(h0, h1), pl = pack2(l0, l1);
            *reinterpret_cast<unsigned*>(&outh[row0 * INNER + d]) = ph;
            *reinterpret_cast<unsigned*>(&outl[row0 * INNER + d]) = pl;
            *reinterpret_cast<unsigned*>(&outh[row8 * INNER + d]) = ph;
            *reinterpret_cast<unsigned*>(&outl[row8 * INNER + d]) = pl;
        }
        return;
    }
    lsum0 += __shfl_xor_sync(0xffffffffu, lsum0, 1);
    lsum0 += __shfl_xor_sync(0xffffffffu, lsum0, 2);
    lsum8 += __shfl_xor_sync(0xffffffffu, lsum8, 1);
    lsum8 += __shfl_xor_sync(0xffffffffu, lsum8, 2);
    const float inv0 = 1.0f / lsum0;
    const float inv8 = 1.0f / lsum8;

#pragma unroll
    for (int nt = 0; nt < 8; nt++) {
        const int d = h * 64 + nt * 8 + 2 * t;
        float v0 = O[nt][0] * inv0, v1 = O[nt][1] * inv0;
        float v2 = O[nt][2] * inv8, v3 = O[nt][3] * inv8;
        bf16 h0, l0, h1, l1, h2, l2, h3, l3;
        split1(v0, h0, l0); split1(v1, h1, l1);
        split1(v2, h2, l2); split1(v3, h3, l3);
        *reinterpret_cast<unsigned*>(&outh[row0 * INNER + d]) = pack2(h0, h1);
        *reinterpret_cast<unsigned*>(&outl[row0 * INNER + d]) = pack2(l0, l1);
        *reinterpret_cast<unsigned*>(&outh[row8 * INNER + d]) = pack2(h2, h3);
        *reinterpret_cast<unsigned*>(&outl[row8 * INNER + d]) = pack2(l2, l3);
    }
}

// ---------------------------------------------------------------------------
extern "C" void kernel_launch(void* const* d_in, const int* in_sizes, int n_in,
                              void* d_out, int out_size)
{
    const float* x     = (const float*)d_in[0];
    const int*   mnp   = (const int*)d_in[1];
    const int*   mbert = (const int*)d_in[2];
    const float* Wqkv  = (const float*)d_in[3];
    const float* Wout  = (const float*)d_in[4];
    const float* bout  = (const float*)d_in[5];
    float* out = (float*)d_out;

    bf16 *xh, *xl, *wqh, *wql, *woh, *wol;
    bf16 *qch, *qcl, *kvch, *kvcl, *atch, *atcl;
    int *idx, *qidx, *cntp, *qcntp;
    cudaGetSymbolAddress((void**)&xh,   g_x_h);
    cudaGetSymbolAddress((void**)&xl,   g_x_l);
    cudaGetSymbolAddress((void**)&wqh,  g_wqkv_h);
    cudaGetSymbolAddress((void**)&wql,  g_wqkv_l);
    cudaGetSymbolAddress((void**)&woh,  g_wout_h);
    cudaGetSymbolAddress((void**)&wol,  g_wout_l);
    cudaGetSymbolAddress((void**)&qch,  g_qc_h);
    cudaGetSymbolAddress((void**)&qcl,  g_qc_l);
    cudaGetSymbolAddress((void**)&kvch, g_kvc_h);
    cudaGetSymbolAddress((void**)&kvcl, g_kvc_l);
    cudaGetSymbolAddress((void**)&atch, g_atc_h);
    cudaGetSymbolAddress((void**)&atcl, g_atc_l);
    cudaGetSymbolAddress((void**)&idx,  g_idx);
    cudaGetSymbolAddress((void**)&qidx, g_qidx);
    cudaGetSymbolAddress((void**)&cntp, g_cnt);
    cudaGetSymbolAddress((void**)&qcntp, g_qcnt);

    cudaFuncSetAttribute(gemm_mma, cudaFuncAttributeMaxDynamicSharedMemorySize,
                         GEMM_SMEM_BYTES);
    cudaFuncSetAttribute(attn_mma, cudaFuncAttributeMaxDynamicSharedMemorySize,
                         ATT_SMEM_BYTES);

    // prep: fused split + fused compactions + parallel mean chain
    split3_kernel<<<512, 256>>>(x, Wqkv, Wout);
    build_both<<<dim3(2, BB), 256>>>(mnp, mbert);
    meanx_part<<<dim3(DIM / 64, BB, 8), dim3(64, 8)>>>(x);
    vmean_kernel<<<dim3(INNER / 64, BB), dim3(64, 16)>>>(Wqkv);
    deadvec_kernel<<<dim3(DIM / 64, BB), dim3(64, 16)>>>(Wout, bout);

    // 1) projections: Q (alive rows, N=512) and fused K|V (key rows, N=1024)
    gemm_mma<<<dim3(INNER / 128, MROWS / 128), 512, GEMM_SMEM_BYTES>>>(
        xh, xl, DIM, qidx, qcntp, wqh, wql, QKV3, nullptr,
        nullptr, qch, qcl, INNER, nullptr, INNER, DIM, 1);
    gemm_mma<<<dim3(1024 / 128, MROWS / 128), 512, GEMM_SMEM_BYTES>>>(
        xh, xl, DIM, idx, cntp, wqh + INNER, wql + INNER, QKV3, nullptr,
        nullptr, kvch, kvcl, 1024, nullptr, 1024, DIM, 1);

    // 2) attention over compacted q-rows and fused K|V -> compacted bf16
    attn_mma<<<dim3(NN / 128, BB * HH), 256, ATT_SMEM_BYTES>>>(atch, atcl);

    // 3) out = attc @ W_out + b_out with output scatter; dead rows filled
    gemm_mma<<<dim3(DIM / 128, MROWS / 128), 512, GEMM_SMEM_BYTES>>>(
        atch, atcl, INNER, nullptr, qcntp, woh, wol, DIM, bout,
        out, nullptr, nullptr, DIM, qidx, DIM, INNER, 0);
    dead_fill<<<dim3(NN, BB), 128>>>(out);
}

// round 12
// speedup vs baseline: 2.6076x; 1.2173x over previous
#include <cuda_runtime.h>
#include <cuda_bf16.h>
#include <math.h>

#define BB    2
#define NN    2048
#define DIM   512
#define HH    8
#define DH    64
#define INNER 512
#define QKV3  1536
#define MROWS (BB*NN)      // 4096

typedef __nv_bfloat16 bf16;

// ---------------- device scratch (no allocation allowed) ----------------
__device__ bf16 g_x_h[MROWS * DIM],    g_x_l[MROWS * DIM];
__device__ bf16 g_wqkv_h[DIM * QKV3],  g_wqkv_l[DIM * QKV3];
__device__ bf16 g_wout_h[INNER * DIM], g_wout_l[INNER * DIM];

// key compaction + fused K|V buffer (K at col 0..511, V at col 512..1023)
__device__ int  g_cnt[BB];
__device__ int  g_idx[BB * NN];
__device__ bf16 g_kvc_h[BB * NN * 1024], g_kvc_l[BB * NN * 1024];
__device__ float g_xpart[BB * 8 * DIM];
__device__ float g_vmpart[BB * 8 * INNER];
__device__ float g_vmean[BB * INNER];
__device__ float g_dead[BB * DIM];

// query compaction
__device__ int  g_qcnt[BB];
__device__ int  g_qidx[BB * NN];
__device__ int  g_qpos[BB * NN];
__device__ bf16 g_qc_h[BB * NN * INNER], g_qc_l[BB * NN * INNER];
__device__ bf16 g_atc_h[BB * NN * INNER], g_atc_l[BB * NN * INNER];

// ---------------- helpers ----------------
__device__ __forceinline__ unsigned s2u(const void* p) {
    return (unsigned)__cvta_generic_to_shared(p);
}
__device__ __forceinline__ void ldsm4(unsigned* r, const void* p) {
    asm volatile("ldmatrix.sync.aligned.m8n8.x4.shared.b16 {%0,%1,%2,%3}, [%4];"
        : "=r"(r[0]), "=r"(r[1]), "=r"(r[2]), "=r"(r[3]) : "r"(s2u(p)));
}
__device__ __forceinline__ void ldsm4t(unsigned* r, const void* p) {
    asm volatile("ldmatrix.sync.aligned.m8n8.x4.trans.shared.b16 {%0,%1,%2,%3}, [%4];"
        : "=r"(r[0]), "=r"(r[1]), "=r"(r[2]), "=r"(r[3]) : "r"(s2u(p)));
}
__device__ __forceinline__ void cp16(void* s, const void* g) {
    asm volatile("cp.async.cg.shared.global [%0], [%1], 16;" :: "r"(s2u(s)), "l"(g));
}
__device__ __forceinline__ void cp_commit() { asm volatile("cp.async.commit_group;"); }
template<int N> __device__ __forceinline__ void cp_wait() {
    asm volatile("cp.async.wait_group %0;" :: "n"(N));
}
__device__ __forceinline__ void mma_bf16(float* c, const unsigned* a, unsigned b0, unsigned b1) {
    asm volatile(
        "mma.sync.aligned.m16n8k16.row.col.f32.bf16.bf16.f32 "
        "{%0,%1,%2,%3}, {%4,%5,%6,%7}, {%8,%9}, {%0,%1,%2,%3};"
        : "+f"(c[0]), "+f"(c[1]), "+f"(c[2]), "+f"(c[3])
        : "r"(a[0]), "r"(a[1]), "r"(a[2]), "r"(a[3]), "r"(b0), "r"(b1));
}
__device__ __forceinline__ unsigned pack2(bf16 a, bf16 b) {
    __nv_bfloat162 v; v.x = a; v.y = b;
    return *reinterpret_cast<unsigned*>(&v);
}
__device__ __forceinline__ void split1(float v, bf16& h, bf16& l) {
    h = __float2bfloat16(v);
    l = __float2bfloat16(v - __bfloat162float(h));
}

// ---------------- prep: fused fp32 -> bf16 hi/lo split of all 3 inputs ------
__global__ void split3_kernel(const float* __restrict__ x,
                              const float* __restrict__ wqkv,
                              const float* __restrict__ wout)
{
    const int n1 = MROWS * DIM, n2 = DIM * QKV3, n3 = INNER * DIM;
    const int total = n1 + n2 + n3;
    for (int i = blockIdx.x * blockDim.x + threadIdx.x; i < total;
         i += gridDim.x * blockDim.x) {
        float v; bf16 *hi, *lo; int off;
        if (i < n1)            { v = x[i];            hi = g_x_h;    lo = g_x_l;    off = i; }
        else if (i < n1 + n2)  { off = i - n1; v = wqkv[off]; hi = g_wqkv_h; lo = g_wqkv_l; }
        else                   { off = i - n1 - n2; v = wout[off]; hi = g_wout_h; lo = g_wout_l; }
        bf16 h, l; split1(v, h, l);
        hi[off] = h; lo[off] = l;
    }
}

// ---------------- fused compactions (parallel scan); grid (2, BB) -----------
__global__ void build_both(const int* __restrict__ mnp, const int* __restrict__ mbert)
{
    const int b = blockIdx.y;
    const bool isQ = (blockIdx.x == 1);
    const int tid = threadIdx.x;
    __shared__ int scan[256];

    int flags[8];
    int local = 0;
#pragma unroll
    for (int k = 0; k < 8; k++) {
        int j = tid * 8 + k;
        int f;
        if (isQ) f = (mnp[b * NN + j] == 1);
        else     f = (mnp[b * NN + j] == 1) && (mbert[b * NN + j] == 0);
        flags[k] = f; local += f;
    }
    scan[tid] = local;
    __syncthreads();
#pragma unroll
    for (int off = 1; off < 256; off <<= 1) {
        int add = (tid >= off) ? scan[tid - off] : 0;
        __syncthreads();
        scan[tid] += add;
        __syncthreads();
    }
    const int tot = scan[255];
    int o = scan[tid] - local;
    if (isQ) {
        if (tid == 0) g_qcnt[b] = tot;
#pragma unroll
        for (int k = 0; k < 8; k++) {
            int j = tid * 8 + k;
            if (flags[k]) { g_qidx[b * NN + o] = j; g_qpos[b * NN + j] = o; o++; }
            else g_qpos[b * NN + j] = -1;
        }
        for (int i = tot + tid; i < NN; i += 256) g_qidx[b * NN + i] = 0;
    } else {
        if (tid == 0) g_cnt[b] = tot;
#pragma unroll
        for (int k = 0; k < 8; k++) {
            if (flags[k]) g_idx[b * NN + (o++)] = tid * 8 + k;
        }
        for (int i = tot + tid; i < NN; i += 256) g_idx[b * NN + i] = 0;
    }
}

// ---------------- partial sums of x rows: grid (DIM/64, BB, 8) --------------
__global__ void meanx_part(const float* __restrict__ x)
{
    const int b = blockIdx.y;
    const int z = blockIdx.z;
    const int d = blockIdx.x * 64 + threadIdx.x;
    const int yg = threadIdx.y;
    float s = 0.0f;
    const int r0 = z * 256;
    for (int j = yg; j < 256; j += 8)
        s += x[((size_t)(b * NN + r0 + j)) * DIM + d];
    __shared__ float red[8][64];
    red[yg][threadIdx.x] = s;
    __syncthreads();
    if (yg == 0) {
        float tot = 0.0f;
#pragma unroll
        for (int i = 0; i < 8; i++) tot += red[i][threadIdx.x];
        g_xpart[(b * 8 + z) * DIM + d] = tot;
    }
}

// ---------------- vmean partials: grid (INNER/64, BB, 8 d-chunks) -----------
__global__ void vmean_part(const float* __restrict__ Wqkv)
{
    const int b = blockIdx.y;
    const int z = blockIdx.z;
    const int col = blockIdx.x * 64 + threadIdx.x;
    const int yg = threadIdx.y;
    const int tid = yg * 64 + threadIdx.x;
    __shared__ float xm[64];
    if (tid < 64) {
        float s = 0.0f;
#pragma unroll
        for (int zz = 0; zz < 8; zz++) s += g_xpart[(b * 8 + zz) * DIM + z * 64 + tid];
        xm[tid] = s * (1.0f / NN);
    }
    __syncthreads();
    float s = 0.0f;
#pragma unroll
    for (int j = yg; j < 64; j += 8)
        s += xm[j] * Wqkv[(size_t)(z * 64 + j) * QKV3 + 2 * INNER + col];
    __shared__ float red[8][64];
    red[yg][threadIdx.x] = s;
    __syncthreads();
    if (yg == 0) {
        float tot = 0.0f;
#pragma unroll
        for (int i = 0; i < 8; i++) tot += red[i][threadIdx.x];
        g_vmpart[(b * 8 + z) * INNER + col] = tot;
    }
}

// ---------------- fused vmean combine + dead vector; grid (DIM/64, BB) ------
__global__ void deadvec_fused(const float* __restrict__ Wout,
                              const float* __restrict__ bias)
{
    const int b = blockIdx.y;
    const int col = blockIdx.x * 64 + threadIdx.x;
    const int yg = threadIdx.y;
    const int tid = yg * 64 + threadIdx.x;
    __shared__ float vm[INNER];
    if (tid < INNER) {
        float s = 0.0f;
#pragma unroll
        for (int z = 0; z < 8; z++) s += g_vmpart[(b * 8 + z) * INNER + tid];
        vm[tid] = s;
        if (blockIdx.x == 0) g_vmean[b * INNER + tid] = s;
    }
    __syncthreads();
    float s = 0.0f;
#pragma unroll 4
    for (int d = yg; d < INNER; d += 16)
        s += vm[d] * Wout[(size_t)d * DIM + col];
    __shared__ float red[16][64];
    red[yg][threadIdx.x] = s;
    __syncthreads();
    if (yg == 0) {
        float tot = bias[col];
#pragma unroll
        for (int i = 0; i < 16; i++) tot += red[i][threadIdx.x];
        g_dead[b * DIM + col] = tot;
    }
}

// ---------------- fill dead output rows -------------------------------------
__global__ void dead_fill(float* __restrict__ out)
{
    const int b = blockIdx.y;
    const int i = blockIdx.x;
    if (g_qpos[b * NN + i] >= 0) return;
    const int tid = threadIdx.x;
    *reinterpret_cast<float4*>(&out[((size_t)(b * NN + i)) * DIM + tid * 4]) =
        *reinterpret_cast<const float4*>(&g_dead[b * DIM + tid * 4]);
}

// ---------------------------------------------------------------------------
// bf16x3 GEMM body, 128x128 block, BK=32, 512 thr (16 warps; warp tile 32x32).
// ---------------------------------------------------------------------------
#define GALD 40
#define GBLD 136
#define G_SA(buf,hl) (sm + ((buf)*2 + (hl)) * (128*GALD))
#define G_SB(buf,hl) (sm + 4*128*GALD + ((buf)*2 + (hl)) * (32*GBLD))
#define GEMM_SMEM_BYTES ((4*128*GALD + 4*32*GBLD) * 2)

__device__ __forceinline__ void gemm_body(bf16* sm, int bm, int bn,
                                          const bf16* __restrict__ Ah,
                                          const bf16* __restrict__ Al,
                                          int lda,
                                          const int* __restrict__ ridx,
                                          const int* __restrict__ cntp,
                                          const bf16* __restrict__ Bh,
                                          const bf16* __restrict__ Bl,
                                          int ldb,
                                          const float* __restrict__ bias,
                                          float* __restrict__ outf,
                                          bf16* __restrict__ outh,
                                          bf16* __restrict__ outl,
                                          int ldo,
                                          const int* __restrict__ oidx,
                                          int K, int mode)
{
    const int b  = bm >> 11;                 // NN = 2048
    const int lm = bm & (NN - 1);
    const int bbase = b * NN;

    int cntv = NN;
    if (cntp) {
        cntv = cntp[b];
        if (lm >= ((cntv + 127) & ~127)) return;
    }

    const int tid = threadIdx.x;
    const int warp = tid >> 5;
    const int lane = tid & 31;
    const int g = lane >> 2;
    const int t = lane & 3;
    const int rowbase = (warp & 3) * 32;
    const int colbase = (warp >> 2) * 32;

    float acc[2][4][4];
#pragma unroll
    for (int mt = 0; mt < 2; mt++)
#pragma unroll
        for (int nt = 0; nt < 4; nt++)
#pragma unroll
            for (int i = 0; i < 4; i++) acc[mt][nt][i] = 0.0f;

    const int tile = lane >> 3;
    const int trow = lane & 7;

    const int arow = tid >> 2;
    const int akch = (tid & 3) * 8;
    int agrow;
    if (ridx) agrow = bbase + ridx[bbase + lm + arow];
    else      agrow = bm + arow;

    auto prefetch = [&](int buf, int k0) {
        {
            size_t go = (size_t)agrow * lda + k0 + akch;
            cp16(&G_SA(buf, 0)[arow * GALD + akch], &Ah[go]);
            cp16(&G_SA(buf, 1)[arow * GALD + akch], &Al[go]);
        }
        {
            int kr = tid >> 4, nch = (tid & 15) * 8;
            size_t go = (size_t)(k0 + kr) * ldb + bn + nch;
            cp16(&G_SB(buf, 0)[kr * GBLD + nch], &Bh[go]);
            cp16(&G_SB(buf, 1)[kr * GBLD + nch], &Bl[go]);
        }
    };

    prefetch(0, 0);
    cp_commit();

    const int NIT = K / 32;
    int buf = 0;
    for (int it = 0; it < NIT; it++) {
        if (it + 1 < NIT) { prefetch(buf ^ 1, (it + 1) * 32); cp_commit(); cp_wait<1>(); }
        else cp_wait<0>();
        __syncthreads();

        const bf16* As_h = G_SA(buf, 0);
        const bf16* As_l = G_SA(buf, 1);
        const bf16* Bs_h = G_SB(buf, 0);
        const bf16* Bs_l = G_SB(buf, 1);

#pragma unroll
        for (int kc = 0; kc < 2; kc++) {
            unsigned ah[2][4], al[2][4];
            const int amrow = (tile & 1) * 8 + trow;
            const int akoff = kc * 16 + (tile >> 1) * 8;
#pragma unroll
            for (int mt = 0; mt < 2; mt++) {
                ldsm4(ah[mt], &As_h[(rowbase + mt * 16 + amrow) * GALD + akoff]);
                ldsm4(al[mt], &As_l[(rowbase + mt * 16 + amrow) * GALD + akoff]);
            }
            const int bkrow = kc * 16 + (tile & 1) * 8 + trow;
            unsigned bh[2][4], bl[2][4];
#pragma unroll
            for (int ntp = 0; ntp < 2; ntp++) {
                const int bncol = colbase + ntp * 16 + (tile >> 1) * 8;
                ldsm4t(bh[ntp], &Bs_h[bkrow * GBLD + bncol]);
                ldsm4t(bl[ntp], &Bs_l[bkrow * GBLD + bncol]);
            }
#pragma unroll
            for (int mt = 0; mt < 2; mt++)
#pragma unroll
                for (int ntp = 0; ntp < 2; ntp++)
#pragma unroll
                    for (int q = 0; q < 2; q++)
                        mma_bf16(acc[mt][ntp * 2 + q], ah[mt], bh[ntp][q * 2], bh[ntp][q * 2 + 1]);
#pragma unroll
            for (int mt = 0; mt < 2; mt++)
#pragma unroll
                for (int ntp = 0; ntp < 2; ntp++)
#pragma unroll
                    for (int q = 0; q < 2; q++)
                        mma_bf16(acc[mt][ntp * 2 + q], ah[mt], bl[ntp][q * 2], bl[ntp][q * 2 + 1]);
#pragma unroll
            for (int mt = 0; mt < 2; mt++)
#pragma unroll
                for (int ntp = 0; ntp < 2; ntp++)
#pragma unroll
                    for (int q = 0; q < 2; q++)
                        mma_bf16(acc[mt][ntp * 2 + q], al[mt], bh[ntp][q * 2], bh[ntp][q * 2 + 1]);
        }
        __syncthreads();
        buf ^= 1;
    }

#pragma unroll
    for (int mt = 0; mt < 2; mt++) {
        const int lr0 = lm + rowbase + mt * 16 + g;
        const int lr1 = lr0 + 8;
#pragma unroll
        for (int nt = 0; nt < 4; nt++) {
            const int c0 = bn + colbase + nt * 8 + 2 * t;
            float v0 = acc[mt][nt][0], v1 = acc[mt][nt][1];
            float v2 = acc[mt][nt][2], v3 = acc[mt][nt][3];
            if (mode == 0) {
                float b0 = bias[c0], b1 = bias[c0 + 1];
                if (lr0 < cntv) {
                    int orow = bbase + oidx[bbase + lr0];
                    *reinterpret_cast<float2*>(&outf[(size_t)orow * ldo + c0]) =
                        make_float2(v0 + b0, v1 + b1);
                }
                if (lr1 < cntv) {
                    int orow = bbase + oidx[bbase + lr1];
                    *reinterpret_cast<float2*>(&outf[(size_t)orow * ldo + c0]) =
                        make_float2(v2 + b0, v3 + b1);
                }
            } else {
                bf16 h0, l0, h1, l1, h2, l2, h3, l3;
                split1(v0, h0, l0); split1(v1, h1, l1);
                split1(v2, h2, l2); split1(v3, h3, l3);
                const size_t r0o = (size_t)(bbase + lr0) * ldo + c0;
                const size_t r1o = (size_t)(bbase + lr1) * ldo + c0;
                *reinterpret_cast<unsigned*>(&outh[r0o]) = pack2(h0, h1);
                *reinterpret_cast<unsigned*>(&outl[r0o]) = pack2(l0, l1);
                *reinterpret_cast<unsigned*>(&outh[r1o]) = pack2(h2, h3);
                *reinterpret_cast<unsigned*>(&outl[r1o]) = pack2(l2, l3);
            }
        }
    }
}

// ---- fused projection GEMM: x<4 -> Q (alive rows), x>=4 -> K|V (key rows) --
__global__ __launch_bounds__(512, 1) void gemm_proj()
{
    extern __shared__ bf16 sm[];
    const int bm = blockIdx.y * 128;
    if (blockIdx.x < 4) {
        gemm_body(sm, bm, blockIdx.x * 128,
                  g_x_h, g_x_l, DIM, g_qidx, g_qcnt,
                  g_wqkv_h, g_wqkv_l, QKV3, nullptr,
                  nullptr, g_qc_h, g_qc_l, INNER, nullptr, DIM, 1);
    } else {
        gemm_body(sm, bm, (blockIdx.x - 4) * 128,
                  g_x_h, g_x_l, DIM, g_idx, g_cnt,
                  g_wqkv_h + INNER, g_wqkv_l + INNER, QKV3, nullptr,
                  nullptr, g_kvc_h, g_kvc_l, 1024, nullptr, DIM, 1);
    }
}

// ---- output GEMM: compacted att rows @ W_out + bias, scatter rows ----------
__global__ __launch_bounds__(512, 1) void gemm_out(const float* __restrict__ bias,
                                                   float* __restrict__ out)
{
    extern __shared__ bf16 sm[];
    gemm_body(sm, blockIdx.y * 128, blockIdx.x * 128,
              g_atc_h, g_atc_l, INNER, nullptr, g_qcnt,
              g_wout_h, g_wout_l, DIM, bias,
              out, nullptr, nullptr, DIM, g_qidx, INNER, 0);
}

// ---------------------------------------------------------------------------
// Attention over compacted Q rows and fused K|V buffer.
// 256 thr (8 warps), 128 q-rows/block, 64-key tiles.
// ---------------------------------------------------------------------------
#define ASLD 72
#define A_Q(hl)     (sm + (hl) * (128 * ASLD))
#define A_KV(buf,m) (sm + 2 * 128 * ASLD + ((buf) * 4 + (m)) * (64 * ASLD))
#define ATT_BF16_TOT (2 * 128 * ASLD + 8 * 64 * ASLD)
#define ATT_SMEM_BYTES (ATT_BF16_TOT * 2)

__global__ __launch_bounds__(256, 1) void attn_mma()
{
    extern __shared__ char smraw[];
    bf16* sm = reinterpret_cast<bf16*>(smraw);

    const int b  = blockIdx.y >> 3;
    const int h  = blockIdx.y & 7;
    const int q0 = blockIdx.x * 128;

    const int qcnt = g_qcnt[b];
    const int qpad = (qcnt + 127) & ~127;
    if (q0 >= qpad) return;

    const int cnt = g_cnt[b];
    const int ntiles = (cnt + 63) >> 6;

    const int tid = threadIdx.x;
    const int warp = tid >> 5;
    const int lane = tid & 31;
    const int g = lane >> 2;
    const int t = lane & 3;
    const int rb = warp * 16;
    const float scale = 0.125f;
    const int tile = lane >> 3;
    const int trow = lane & 7;

#pragma unroll
    for (int j = 0; j < 4; j++) {
        int c = tid * 4 + j;
        int row = c >> 3, dch = (c & 7) * 8;
        size_t base = (size_t)(b * NN + q0 + row) * INNER + h * 64 + dch;
        cp16(&A_Q(0)[row * ASLD + dch], &g_qc_h[base]);
        cp16(&A_Q(1)[row * ASLD + dch], &g_qc_l[base]);
    }
    cp_commit();

    auto pref = [&](int buf, int kt0) {
#pragma unroll
        for (int j = 0; j < 2; j++) {
            int c = tid * 2 + j;
            int row = c >> 3, dch = (c & 7) * 8;
            size_t base = ((size_t)(b * NN + kt0 + row)) * 1024 + h * 64 + dch;
            cp16(&A_KV(buf, 0)[row * ASLD + dch], &g_kvc_h[base]);
            cp16(&A_KV(buf, 1)[row * ASLD + dch], &g_kvc_l[base]);
            cp16(&A_KV(buf, 2)[row * ASLD + dch], &g_kvc_h[base + 512]);
            cp16(&A_KV(buf, 3)[row * ASLD + dch], &g_kvc_l[base + 512]);
        }
    };

    if (ntiles > 0) { pref(0, 0); }
    cp_commit();

    float O[8][4];
#pragma unroll
    for (int nt = 0; nt < 8; nt++)
#pragma unroll
        for (int i = 0; i < 4; i++) O[nt][i] = 0.0f;
    float lsum0 = 0.0f, lsum8 = 0.0f;

    int buf = 0;
    for (int kt = 0; kt < ntiles; kt++) {
        const int kt0 = kt * 64;
        if (kt + 1 < ntiles) { pref(buf ^ 1, (kt + 1) * 64); cp_commit(); cp_wait<1>(); }
        else cp_wait<0>();
        __syncthreads();

        const bf16* QHs = A_Q(0);
        const bf16* QLs = A_Q(1);
        const bf16* KHs = A_KV(buf, 0);
        const bf16* KLs = A_KV(buf, 1);
        const bf16* VHs = A_KV(buf, 2);
        const bf16* VLs = A_KV(buf, 3);

        unsigned pah[4][4], pal[4][4];
        const int qr = rb + (tile & 1) * 8 + trow;

#pragma unroll
        for (int half = 0; half < 2; half++) {
            float sc[4][4];
#pragma unroll
            for (int nt = 0; nt < 4; nt++)
#pragma unroll
                for (int i = 0; i < 4; i++) sc[nt][i] = 0.0f;

#pragma unroll
            for (int kc = 0; kc < 4; kc++) {
                unsigned aqh[4], aql[4];
                ldsm4(aqh, &QHs[qr * ASLD + kc * 16 + (tile >> 1) * 8]);
                ldsm4(aql, &QLs[qr * ASLD + kc * 16 + (tile >> 1) * 8]);
                const int koff = kc * 16 + (tile & 1) * 8;
                unsigned kbh[2][4], kbl[2][4];
#pragma unroll
                for (int ntp = 0; ntp < 2; ntp++) {
                    const int nrow = (half * 2 + ntp) * 16 + (tile >> 1) * 8 + trow;
                    ldsm4(kbh[ntp], &KHs[nrow * ASLD + koff]);
                    ldsm4(kbl[ntp], &KLs[nrow * ASLD + koff]);
                }
#pragma unroll
                for (int ntp = 0; ntp < 2; ntp++)
#pragma unroll
                    for (int q = 0; q < 2; q++)
                        mma_bf16(sc[ntp * 2 + q], aqh, kbh[ntp][q * 2], kbh[ntp][q * 2 + 1]);
#pragma unroll
                for (int ntp = 0; ntp < 2; ntp++)
#pragma unroll
                    for (int q = 0; q < 2; q++)
                        mma_bf16(sc[ntp * 2 + q], aqh, kbl[ntp][q * 2], kbl[ntp][q * 2 + 1]);
#pragma unroll
                for (int ntp = 0; ntp < 2; ntp++)
#pragma unroll
                    for (int q = 0; q < 2; q++)
                        mma_bf16(sc[ntp * 2 + q], aql, kbh[ntp][q * 2], kbh[ntp][q * 2 + 1]);
            }

#pragma unroll
            for (int ntl = 0; ntl < 4; ntl++) {
                const int nt = half * 4 + ntl;
                const int kch = nt >> 1, q = nt & 1;
                const int colg = kt0 + nt * 8 + 2 * t;
                const bool v0c = colg < cnt;
                const bool v1c = colg + 1 < cnt;
                float p0 = v0c ? __expf(sc[ntl][0] * scale) : 0.0f;
                float p1 = v1c ? __expf(sc[ntl][1] * scale) : 0.0f;
                float p2 = v0c ? __expf(sc[ntl][2] * scale) : 0.0f;
                float p3 = v1c ? __expf(sc[ntl][3] * scale) : 0.0f;
                lsum0 += p0 + p1;
                lsum8 += p2 + p3;
                bf16 h0, l0, h1, l1, h2, l2, h3, l3;
                split1(p0, h0, l0); split1(p1, h1, l1);
                split1(p2, h2, l2); split1(p3, h3, l3);
                pah[kch][q * 2 + 0] = pack2(h0, h1);
                pah[kch][q * 2 + 1] = pack2(h2, h3);
                pal[kch][q * 2 + 0] = pack2(l0, l1);
                pal[kch][q * 2 + 1] = pack2(l2, l3);
            }
        }

#pragma unroll
        for (int kch = 0; kch < 4; kch++) {
            const int keyrow = kch * 16 + (tile & 1) * 8 + trow;
            unsigned vh[4][4], vl[4][4];
#pragma unroll
            for (int dp = 0; dp < 4; dp++) {
                const int dcol = dp * 16 + (tile >> 1) * 8;
                ldsm4t(vh[dp], &VHs[keyrow * ASLD + dcol]);
                ldsm4t(vl[dp], &VLs[keyrow * ASLD + dcol]);
            }
#pragma unroll
            for (int dp = 0; dp < 4; dp++)
#pragma unroll
                for (int q = 0; q < 2; q++)
                    mma_bf16(O[dp * 2 + q], pah[kch], vh[dp][q * 2], vh[dp][q * 2 + 1]);
#pragma unroll
            for (int dp = 0; dp < 4; dp++)
#pragma unroll
                for (int q = 0; q < 2; q++)
                    mma_bf16(O[dp * 2 + q], pah[kch], vl[dp][q * 2], vl[dp][q * 2 + 1]);
#pragma unroll
            for (int dp = 0; dp < 4; dp++)
#pragma unroll
                for (int q = 0; q < 2; q++)
                    mma_bf16(O[dp * 2 + q], pal[kch], vh[dp][q * 2], vh[dp][q * 2 + 1]);
        }
        __syncthreads();
        buf ^= 1;
    }

    const size_t row0 = (size_t)(b * NN + q0 + rb + g);
    const size_t row8 = row0 + 8;
    if (cnt == 0) {
#pragma unroll
        for (int nt = 0; nt < 8; nt++) {
            const int d = h * 64 + nt * 8 + 2 * t;
            float m0 = g_vmean[b * INNER + d];
            float m1 = g_vmean[b * INNER + d + 1];
            bf16 h0, l0, h1, l1;
            split1(m0, h0, l0); split1(m1, h1, l1);
            unsigned ph = pack2(h0, h1), pl = pack2(l0, l1);
            *reinterpret_cast<unsigned*>(&g_atc_h[row0 * INNER + d]) = ph;
            *reinterpret_cast<unsigned*>(&g_atc_l[row0 * INNER + d]) = pl;
            *reinterpret_cast<unsigned*>(&g_atc_h[row8 * INNER + d]) = ph;
            *reinterpret_cast<unsigned*>(&g_atc_l[row8 * INNER + d]) = pl;
        }
        return;
    }
    lsum0 += __shfl_xor_sync(0xffffffffu, lsum0, 1);
    lsum0 += __shfl_xor_sync(0xffffffffu, lsum0, 2);
    lsum8 += __shfl_xor_sync(0xffffffffu, lsum8, 1);
    lsum8 += __shfl_xor_sync(0xffffffffu, lsum8, 2);
    const float inv0 = 1.0f / lsum0;
    const float inv8 = 1.0f / lsum8;

#pragma unroll
    for (int nt = 0; nt < 8; nt++) {
        const int d = h * 64 + nt * 8 + 2 * t;
        float v0 = O[nt][0] * inv0, v1 = O[nt][1] * inv0;
        float v2 = O[nt][2] * inv8, v3 = O[nt][3] * inv8;
        bf16 h0, l0, h1, l1, h2, l2, h3, l3;
        split1(v0, h0, l0); split1(v1, h1, l1);
        split1(v2, h2, l2); split1(v3, h3, l3);
        *reinterpret_cast<unsigned*>(&g_atc_h[row0 * INNER + d]) = pack2(h0, h1);
        *reinterpret_cast<unsigned*>(&g_atc_l[row0 * INNER + d]) = pack2(l0, l1);
        *reinterpret_cast<unsigned*>(&g_atc_h[row8 * INNER + d]) = pack2(h2, h3);
        *reinterpret_cast<unsigned*>(&g_atc_l[row8 * INNER + d]) = pack2(l2, l3);
    }
}

// ---------------------------------------------------------------------------
extern "C" void kernel_launch(void* const* d_in, const int* in_sizes, int n_in,
                              void* d_out, int out_size)
{
    const float* x     = (const float*)d_in[0];
    const int*   mnp   = (const int*)d_in[1];
    const int*   mbert = (const int*)d_in[2];
    const float* Wqkv  = (const float*)d_in[3];
    const float* Wout  = (const float*)d_in[4];
    const float* bout  = (const float*)d_in[5];
    float* out = (float*)d_out;

    cudaFuncSetAttribute(gemm_proj, cudaFuncAttributeMaxDynamicSharedMemorySize,
                         GEMM_SMEM_BYTES);
    cudaFuncSetAttribute(gemm_out, cudaFuncAttributeMaxDynamicSharedMemorySize,
                         GEMM_SMEM_BYTES);
    cudaFuncSetAttribute(attn_mma, cudaFuncAttributeMaxDynamicSharedMemorySize,
                         ATT_SMEM_BYTES);

    // prep: fused split + compactions + parallel mean chain
    split3_kernel<<<512, 256>>>(x, Wqkv, Wout);
    build_both<<<dim3(2, BB), 256>>>(mnp, mbert);
    meanx_part<<<dim3(DIM / 64, BB, 8), dim3(64, 8)>>>(x);
    vmean_part<<<dim3(INNER / 64, BB, 8), dim3(64, 8)>>>(Wqkv);
    deadvec_fused<<<dim3(DIM / 64, BB), dim3(64, 16)>>>(Wout, bout);

    // 1) fused projections: Q (x 0-3) and K|V (x 4-11) in one wave
    gemm_proj<<<dim3(12, MROWS / 128), 512, GEMM_SMEM_BYTES>>>();

    // 2) attention over compacted q-rows and fused K|V -> compacted bf16
    attn_mma<<<dim3(NN / 128, BB * HH), 256, ATT_SMEM_BYTES>>>();

    // 3) out = attc @ W_out + b_out with output scatter; dead rows filled
    gemm_out<<<dim3(DIM / 128, MROWS / 128), 512, GEMM_SMEM_BYTES>>>(bout, out);
    dead_fill<<<dim3(NN, BB), 128>>>(out);
}

// round 13
// speedup vs baseline: 2.8969x; 1.1109x over previous
#include <cuda_runtime.h>
#include <cuda_bf16.h>
#include <math.h>

#define BB    2
#define NN    2048
#define DIM   512
#define HH    8
#define DH    64
#define INNER 512
#define QKV3  1536
#define MROWS (BB*NN)      // 4096

typedef __nv_bfloat16 bf16;

// ---------------- device scratch (no allocation allowed) ----------------
__device__ bf16 g_x_h[MROWS * DIM],    g_x_l[MROWS * DIM];
__device__ bf16 g_wqkv_h[DIM * QKV3],  g_wqkv_l[DIM * QKV3];
__device__ bf16 g_wout_h[INNER * DIM], g_wout_l[INNER * DIM];

// key compaction + fused K|V buffer (K at col 0..511, V at col 512..1023)
__device__ int  g_cnt[BB];
__device__ int  g_idx[BB * NN];
__device__ bf16 g_kvc_h[BB * NN * 1024], g_kvc_l[BB * NN * 1024];
__device__ float g_xpart[BB * 8 * DIM];
__device__ float g_vmpart[BB * 8 * INNER];
__device__ float g_vmean[BB * INNER];
__device__ float g_dead[BB * DIM];

// query compaction
__device__ int  g_qcnt[BB];
__device__ int  g_qidx[BB * NN];
__device__ int  g_qpos[BB * NN];
__device__ bf16 g_qc_h[BB * NN * INNER], g_qc_l[BB * NN * INNER];
__device__ bf16 g_atc_h[BB * NN * INNER], g_atc_l[BB * NN * INNER];

// ---------------- helpers ----------------
__device__ __forceinline__ unsigned s2u(const void* p) {
    return (unsigned)__cvta_generic_to_shared(p);
}
__device__ __forceinline__ void ldsm4(unsigned* r, const void* p) {
    asm volatile("ldmatrix.sync.aligned.m8n8.x4.shared.b16 {%0,%1,%2,%3}, [%4];"
        : "=r"(r[0]), "=r"(r[1]), "=r"(r[2]), "=r"(r[3]) : "r"(s2u(p)));
}
__device__ __forceinline__ void ldsm4t(unsigned* r, const void* p) {
    asm volatile("ldmatrix.sync.aligned.m8n8.x4.trans.shared.b16 {%0,%1,%2,%3}, [%4];"
        : "=r"(r[0]), "=r"(r[1]), "=r"(r[2]), "=r"(r[3]) : "r"(s2u(p)));
}
__device__ __forceinline__ void cp16(void* s, const void* g) {
    asm volatile("cp.async.cg.shared.global [%0], [%1], 16;" :: "r"(s2u(s)), "l"(g));
}
__device__ __forceinline__ void cp_commit() { asm volatile("cp.async.commit_group;"); }
template<int N> __device__ __forceinline__ void cp_wait() {
    asm volatile("cp.async.wait_group %0;" :: "n"(N));
}
__device__ __forceinline__ void mma_bf16(float* c, const unsigned* a, unsigned b0, unsigned b1) {
    asm volatile(
        "mma.sync.aligned.m16n8k16.row.col.f32.bf16.bf16.f32 "
        "{%0,%1,%2,%3}, {%4,%5,%6,%7}, {%8,%9}, {%0,%1,%2,%3};"
        : "+f"(c[0]), "+f"(c[1]), "+f"(c[2]), "+f"(c[3])
        : "r"(a[0]), "r"(a[1]), "r"(a[2]), "r"(a[3]), "r"(b0), "r"(b1));
}
__device__ __forceinline__ unsigned pack2(bf16 a, bf16 b) {
    __nv_bfloat162 v; v.x = a; v.y = b;
    return *reinterpret_cast<unsigned*>(&v);
}
__device__ __forceinline__ void split1(float v, bf16& h, bf16& l) {
    h = __float2bfloat16(v);
    l = __float2bfloat16(v - __bfloat162float(h));
}

// ---------------- prep: fused fp32 -> bf16 hi/lo split of all 3 inputs ------
__global__ void split3_kernel(const float* __restrict__ x,
                              const float* __restrict__ wqkv,
                              const float* __restrict__ wout)
{
    const int n1 = MROWS * DIM, n2 = DIM * QKV3, n3 = INNER * DIM;
    const int total = n1 + n2 + n3;
    for (int i = blockIdx.x * blockDim.x + threadIdx.x; i < total;
         i += gridDim.x * blockDim.x) {
        float v; bf16 *hi, *lo; int off;
        if (i < n1)            { v = x[i];            hi = g_x_h;    lo = g_x_l;    off = i; }
        else if (i < n1 + n2)  { off = i - n1; v = wqkv[off]; hi = g_wqkv_h; lo = g_wqkv_l; }
        else                   { off = i - n1 - n2; v = wout[off]; hi = g_wout_h; lo = g_wout_l; }
        bf16 h, l; split1(v, h, l);
        hi[off] = h; lo[off] = l;
    }
}

// ---------------- fused compactions (parallel scan); grid (2, BB) -----------
__global__ void build_both(const int* __restrict__ mnp, const int* __restrict__ mbert)
{
    const int b = blockIdx.y;
    const bool isQ = (blockIdx.x == 1);
    const int tid = threadIdx.x;
    __shared__ int scan[256];

    int flags[8];
    int local = 0;
#pragma unroll
    for (int k = 0; k < 8; k++) {
        int j = tid * 8 + k;
        int f;
        if (isQ) f = (mnp[b * NN + j] == 1);
        else     f = (mnp[b * NN + j] == 1) && (mbert[b * NN + j] == 0);
        flags[k] = f; local += f;
    }
    scan[tid] = local;
    __syncthreads();
#pragma unroll
    for (int off = 1; off < 256; off <<= 1) {
        int add = (tid >= off) ? scan[tid - off] : 0;
        __syncthreads();
        scan[tid] += add;
        __syncthreads();
    }
    const int tot = scan[255];
    int o = scan[tid] - local;
    if (isQ) {
        if (tid == 0) g_qcnt[b] = tot;
#pragma unroll
        for (int k = 0; k < 8; k++) {
            int j = tid * 8 + k;
            if (flags[k]) { g_qidx[b * NN + o] = j; g_qpos[b * NN + j] = o; o++; }
            else g_qpos[b * NN + j] = -1;
        }
        for (int i = tot + tid; i < NN; i += 256) g_qidx[b * NN + i] = 0;
    } else {
        if (tid == 0) g_cnt[b] = tot;
#pragma unroll
        for (int k = 0; k < 8; k++) {
            if (flags[k]) g_idx[b * NN + (o++)] = tid * 8 + k;
        }
        for (int i = tot + tid; i < NN; i += 256) g_idx[b * NN + i] = 0;
    }
}

// ---------------- partial sums of x rows: grid (DIM/64, BB, 8) --------------
__global__ void meanx_part(const float* __restrict__ x)
{
    const int b = blockIdx.y;
    const int z = blockIdx.z;
    const int d = blockIdx.x * 64 + threadIdx.x;
    const int yg = threadIdx.y;
    float s = 0.0f;
    const int r0 = z * 256;
    for (int j = yg; j < 256; j += 8)
        s += x[((size_t)(b * NN + r0 + j)) * DIM + d];
    __shared__ float red[8][64];
    red[yg][threadIdx.x] = s;
    __syncthreads();
    if (yg == 0) {
        float tot = 0.0f;
#pragma unroll
        for (int i = 0; i < 8; i++) tot += red[i][threadIdx.x];
        g_xpart[(b * 8 + z) * DIM + d] = tot;
    }
}

// ---------------- vmean partials: grid (INNER/64, BB, 8 d-chunks) -----------
__global__ void vmean_part(const float* __restrict__ Wqkv)
{
    const int b = blockIdx.y;
    const int z = blockIdx.z;
    const int col = blockIdx.x * 64 + threadIdx.x;
    const int yg = threadIdx.y;
    const int tid = yg * 64 + threadIdx.x;
    __shared__ float xm[64];
    if (tid < 64) {
        float s = 0.0f;
#pragma unroll
        for (int zz = 0; zz < 8; zz++) s += g_xpart[(b * 8 + zz) * DIM + z * 64 + tid];
        xm[tid] = s * (1.0f / NN);
    }
    __syncthreads();
    float s = 0.0f;
#pragma unroll
    for (int j = yg; j < 64; j += 8)
        s += xm[j] * Wqkv[(size_t)(z * 64 + j) * QKV3 + 2 * INNER + col];
    __shared__ float red[8][64];
    red[yg][threadIdx.x] = s;
    __syncthreads();
    if (yg == 0) {
        float tot = 0.0f;
#pragma unroll
        for (int i = 0; i < 8; i++) tot += red[i][threadIdx.x];
        g_vmpart[(b * 8 + z) * INNER + col] = tot;
    }
}

// ---------------- fused vmean combine + dead vector; grid (DIM/64, BB) ------
__global__ void deadvec_fused(const float* __restrict__ Wout,
                              const float* __restrict__ bias)
{
    const int b = blockIdx.y;
    const int col = blockIdx.x * 64 + threadIdx.x;
    const int yg = threadIdx.y;
    const int tid = yg * 64 + threadIdx.x;
    __shared__ float vm[INNER];
    if (tid < INNER) {
        float s = 0.0f;
#pragma unroll
        for (int z = 0; z < 8; z++) s += g_vmpart[(b * 8 + z) * INNER + tid];
        vm[tid] = s;
        if (blockIdx.x == 0) g_vmean[b * INNER + tid] = s;
    }
    __syncthreads();
    float s = 0.0f;
#pragma unroll 4
    for (int d = yg; d < INNER; d += 16)
        s += vm[d] * Wout[(size_t)d * DIM + col];
    __shared__ float red[16][64];
    red[yg][threadIdx.x] = s;
    __syncthreads();
    if (yg == 0) {
        float tot = bias[col];
#pragma unroll
        for (int i = 0; i < 16; i++) tot += red[i][threadIdx.x];
        g_dead[b * DIM + col] = tot;
    }
}

// ---------------- fill dead output rows -------------------------------------
__global__ void dead_fill(float* __restrict__ out)
{
    const int b = blockIdx.y;
    const int i = blockIdx.x;
    if (g_qpos[b * NN + i] >= 0) return;
    const int tid = threadIdx.x;
    *reinterpret_cast<float4*>(&out[((size_t)(b * NN + i)) * DIM + tid * 4]) =
        *reinterpret_cast<const float4*>(&g_dead[b * DIM + tid * 4]);
}

// ---------------------------------------------------------------------------
// bf16x3 GEMM body, 128x128 block, BK=32, 512 thr (16 warps; warp tile 32x32).
// ---------------------------------------------------------------------------
#define GALD 40
#define GBLD 136
#define G_SA(buf,hl) (sm + ((buf)*2 + (hl)) * (128*GALD))
#define G_SB(buf,hl) (sm + 4*128*GALD + ((buf)*2 + (hl)) * (32*GBLD))
#define GEMM_SMEM_BYTES ((4*128*GALD + 4*32*GBLD) * 2)

__device__ __forceinline__ void gemm_body(bf16* sm, int bm, int bn,
                                          const bf16* __restrict__ Ah,
                                          const bf16* __restrict__ Al,
                                          int lda,
                                          const int* __restrict__ ridx,
                                          const int* __restrict__ cntp,
                                          const bf16* __restrict__ Bh,
                                          const bf16* __restrict__ Bl,
                                          int ldb,
                                          const float* __restrict__ bias,
                                          float* __restrict__ outf,
                                          bf16* __restrict__ outh,
                                          bf16* __restrict__ outl,
                                          int ldo,
                                          const int* __restrict__ oidx,
                                          int K, int mode)
{
    const int b  = bm >> 11;                 // NN = 2048
    const int lm = bm & (NN - 1);
    const int bbase = b * NN;

    int cntv = NN;
    if (cntp) {
        cntv = cntp[b];
        if (lm >= ((cntv + 127) & ~127)) return;
    }

    const int tid = threadIdx.x;
    const int warp = tid >> 5;
    const int lane = tid & 31;
    const int g = lane >> 2;
    const int t = lane & 3;
    const int rowbase = (warp & 3) * 32;
    const int colbase = (warp >> 2) * 32;

    float acc[2][4][4];
#pragma unroll
    for (int mt = 0; mt < 2; mt++)
#pragma unroll
        for (int nt = 0; nt < 4; nt++)
#pragma unroll
            for (int i = 0; i < 4; i++) acc[mt][nt][i] = 0.0f;

    const int tile = lane >> 3;
    const int trow = lane & 7;

    const int arow = tid >> 2;
    const int akch = (tid & 3) * 8;
    int agrow;
    if (ridx) agrow = bbase + ridx[bbase + lm + arow];
    else      agrow = bm + arow;

    auto prefetch = [&](int buf, int k0) {
        {
            size_t go = (size_t)agrow * lda + k0 + akch;
            cp16(&G_SA(buf, 0)[arow * GALD + akch], &Ah[go]);
            cp16(&G_SA(buf, 1)[arow * GALD + akch], &Al[go]);
        }
        {
            int kr = tid >> 4, nch = (tid & 15) * 8;
            size_t go = (size_t)(k0 + kr) * ldb + bn + nch;
            cp16(&G_SB(buf, 0)[kr * GBLD + nch], &Bh[go]);
            cp16(&G_SB(buf, 1)[kr * GBLD + nch], &Bl[go]);
        }
    };

    prefetch(0, 0);
    cp_commit();

    const int NIT = K / 32;
    int buf = 0;
    for (int it = 0; it < NIT; it++) {
        if (it + 1 < NIT) { prefetch(buf ^ 1, (it + 1) * 32); cp_commit(); cp_wait<1>(); }
        else cp_wait<0>();
        __syncthreads();

        const bf16* As_h = G_SA(buf, 0);
        const bf16* As_l = G_SA(buf, 1);
        const bf16* Bs_h = G_SB(buf, 0);
        const bf16* Bs_l = G_SB(buf, 1);

#pragma unroll
        for (int kc = 0; kc < 2; kc++) {
            unsigned ah[2][4], al[2][4];
            const int amrow = (tile & 1) * 8 + trow;
            const int akoff = kc * 16 + (tile >> 1) * 8;
#pragma unroll
            for (int mt = 0; mt < 2; mt++) {
                ldsm4(ah[mt], &As_h[(rowbase + mt * 16 + amrow) * GALD + akoff]);
                ldsm4(al[mt], &As_l[(rowbase + mt * 16 + amrow) * GALD + akoff]);
            }
            const int bkrow = kc * 16 + (tile & 1) * 8 + trow;
            unsigned bh[2][4], bl[2][4];
#pragma unroll
            for (int ntp = 0; ntp < 2; ntp++) {
                const int bncol = colbase + ntp * 16 + (tile >> 1) * 8;
                ldsm4t(bh[ntp], &Bs_h[bkrow * GBLD + bncol]);
                ldsm4t(bl[ntp], &Bs_l[bkrow * GBLD + bncol]);
            }
#pragma unroll
            for (int mt = 0; mt < 2; mt++)
#pragma unroll
                for (int ntp = 0; ntp < 2; ntp++)
#pragma unroll
                    for (int q = 0; q < 2; q++)
                        mma_bf16(acc[mt][ntp * 2 + q], ah[mt], bh[ntp][q * 2], bh[ntp][q * 2 + 1]);
#pragma unroll
            for (int mt = 0; mt < 2; mt++)
#pragma unroll
                for (int ntp = 0; ntp < 2; ntp++)
#pragma unroll
                    for (int q = 0; q < 2; q++)
                        mma_bf16(acc[mt][ntp * 2 + q], ah[mt], bl[ntp][q * 2], bl[ntp][q * 2 + 1]);
#pragma unroll
            for (int mt = 0; mt < 2; mt++)
#pragma unroll
                for (int ntp = 0; ntp < 2; ntp++)
#pragma unroll
                    for (int q = 0; q < 2; q++)
                        mma_bf16(acc[mt][ntp * 2 + q], al[mt], bh[ntp][q * 2], bh[ntp][q * 2 + 1]);
        }
        __syncthreads();
        buf ^= 1;
    }

#pragma unroll
    for (int mt = 0; mt < 2; mt++) {
        const int lr0 = lm + rowbase + mt * 16 + g;
        const int lr1 = lr0 + 8;
#pragma unroll
        for (int nt = 0; nt < 4; nt++) {
            const int c0 = bn + colbase + nt * 8 + 2 * t;
            float v0 = acc[mt][nt][0], v1 = acc[mt][nt][1];
            float v2 = acc[mt][nt][2], v3 = acc[mt][nt][3];
            if (mode == 0) {
                float b0 = bias[c0], b1 = bias[c0 + 1];
                if (lr0 < cntv) {
                    int orow = bbase + oidx[bbase + lr0];
                    *reinterpret_cast<float2*>(&outf[(size_t)orow * ldo + c0]) =
                        make_float2(v0 + b0, v1 + b1);
                }
                if (lr1 < cntv) {
                    int orow = bbase + oidx[bbase + lr1];
                    *reinterpret_cast<float2*>(&outf[(size_t)orow * ldo + c0]) =
                        make_float2(v2 + b0, v3 + b1);
                }
            } else {
                bf16 h0, l0, h1, l1, h2, l2, h3, l3;
                split1(v0, h0, l0); split1(v1, h1, l1);
                split1(v2, h2, l2); split1(v3, h3, l3);
                const size_t r0o = (size_t)(bbase + lr0) * ldo + c0;
                const size_t r1o = (size_t)(bbase + lr1) * ldo + c0;
                *reinterpret_cast<unsigned*>(&outh[r0o]) = pack2(h0, h1);
                *reinterpret_cast<unsigned*>(&outl[r0o]) = pack2(l0, l1);
                *reinterpret_cast<unsigned*>(&outh[r1o]) = pack2(h2, h3);
                *reinterpret_cast<unsigned*>(&outl[r1o]) = pack2(l2, l3);
            }
        }
    }
}

// ---- fused projection GEMM: x<4 -> Q (alive rows), x>=4 -> K|V (key rows) --
__global__ __launch_bounds__(512, 1) void gemm_proj()
{
    extern __shared__ bf16 sm[];
    const int bm = blockIdx.y * 128;
    if (blockIdx.x < 4) {
        gemm_body(sm, bm, blockIdx.x * 128,
                  g_x_h, g_x_l, DIM, g_qidx, g_qcnt,
                  g_wqkv_h, g_wqkv_l, QKV3, nullptr,
                  nullptr, g_qc_h, g_qc_l, INNER, nullptr, DIM, 1);
    } else {
        gemm_body(sm, bm, (blockIdx.x - 4) * 128,
                  g_x_h, g_x_l, DIM, g_idx, g_cnt,
                  g_wqkv_h + INNER, g_wqkv_l + INNER, QKV3, nullptr,
                  nullptr, g_kvc_h, g_kvc_l, 1024, nullptr, DIM, 1);
    }
}

// ---- output GEMM: compacted att rows @ W_out + bias, scatter rows ----------
__global__ __launch_bounds__(512, 1) void gemm_out(const float* __restrict__ bias,
                                                   float* __restrict__ out)
{
    extern __shared__ bf16 sm[];
    gemm_body(sm, blockIdx.y * 128, blockIdx.x * 128,
              g_atc_h, g_atc_l, INNER, nullptr, g_qcnt,
              g_wout_h, g_wout_l, DIM, bias,
              out, nullptr, nullptr, DIM, g_qidx, INNER, 0);
}

// ---------------------------------------------------------------------------
// Attention over compacted Q rows and fused K|V buffer.
// 256 thr (8 warps), 128 q-rows/block, 64-key tiles.
// ---------------------------------------------------------------------------
#define ASLD 72
#define A_Q(hl)     (sm + (hl) * (128 * ASLD))
#define A_KV(buf,m) (sm + 2 * 128 * ASLD + ((buf) * 4 + (m)) * (64 * ASLD))
#define ATT_BF16_TOT (2 * 128 * ASLD + 8 * 64 * ASLD)
#define ATT_SMEM_BYTES (ATT_BF16_TOT * 2)

__global__ __launch_bounds__(256, 1) void attn_mma()
{
    extern __shared__ char smraw[];
    bf16* sm = reinterpret_cast<bf16*>(smraw);

    const int b  = blockIdx.y >> 3;
    const int h  = blockIdx.y & 7;
    const int q0 = blockIdx.x * 128;

    const int qcnt = g_qcnt[b];
    const int qpad = (qcnt + 127) & ~127;
    if (q0 >= qpad) return;

    const int cnt = g_cnt[b];
    const int ntiles = (cnt + 63) >> 6;

    const int tid = threadIdx.x;
    const int warp = tid >> 5;
    const int lane = tid & 31;
    const int g = lane >> 2;
    const int t = lane & 3;
    const int rb = warp * 16;
    const float scale = 0.125f;
    const int tile = lane >> 3;
    const int trow = lane & 7;

#pragma unroll
    for (int j = 0; j < 4; j++) {
        int c = tid * 4 + j;
        int row = c >> 3, dch = (c & 7) * 8;
        size_t base = (size_t)(b * NN + q0 + row) * INNER + h * 64 + dch;
        cp16(&A_Q(0)[row * ASLD + dch], &g_qc_h[base]);
        cp16(&A_Q(1)[row * ASLD + dch], &g_qc_l[base]);
    }
    cp_commit();

    auto pref = [&](int buf, int kt0) {
#pragma unroll
        for (int j = 0; j < 2; j++) {
            int c = tid * 2 + j;
            int row = c >> 3, dch = (c & 7) * 8;
            size_t base = ((size_t)(b * NN + kt0 + row)) * 1024 + h * 64 + dch;
            cp16(&A_KV(buf, 0)[row * ASLD + dch], &g_kvc_h[base]);
            cp16(&A_KV(buf, 1)[row * ASLD + dch], &g_kvc_l[base]);
            cp16(&A_KV(buf, 2)[row * ASLD + dch], &g_kvc_h[base + 512]);
            cp16(&A_KV(buf, 3)[row * ASLD + dch], &g_kvc_l[base + 512]);
        }
    };

    if (ntiles > 0) { pref(0, 0); }
    cp_commit();

    float O[8][4];
#pragma unroll
    for (int nt = 0; nt < 8; nt++)
#pragma unroll
        for (int i = 0; i < 4; i++) O[nt][i] = 0.0f;
    float lsum0 = 0.0f, lsum8 = 0.0f;

    int buf = 0;
    for (int kt = 0; kt < ntiles; kt++) {
        const int kt0 = kt * 64;
        if (kt + 1 < ntiles) { pref(buf ^ 1, (kt + 1) * 64); cp_commit(); cp_wait<1>(); }
        else cp_wait<0>();
        __syncthreads();

        const bf16* QHs = A_Q(0);
        const bf16* QLs = A_Q(1);
        const bf16* KHs = A_KV(buf, 0);
        const bf16* KLs = A_KV(buf, 1);
        const bf16* VHs = A_KV(buf, 2);
        const bf16* VLs = A_KV(buf, 3);

        unsigned pah[4][4], pal[4][4];
        const int qr = rb + (tile & 1) * 8 + trow;

#pragma unroll
        for (int half = 0; half < 2; half++) {
            float sc[4][4];
#pragma unroll
            for (int nt = 0; nt < 4; nt++)
#pragma unroll
                for (int i = 0; i < 4; i++) sc[nt][i] = 0.0f;

#pragma unroll
            for (int kc = 0; kc < 4; kc++) {
                unsigned aqh[4], aql[4];
                ldsm4(aqh, &QHs[qr * ASLD + kc * 16 + (tile >> 1) * 8]);
                ldsm4(aql, &QLs[qr * ASLD + kc * 16 + (tile >> 1) * 8]);
                const int koff = kc * 16 + (tile & 1) * 8;
                unsigned kbh[2][4], kbl[2][4];
#pragma unroll
                for (int ntp = 0; ntp < 2; ntp++) {
                    const int nrow = (half * 2 + ntp) * 16 + (tile >> 1) * 8 + trow;
                    ldsm4(kbh[ntp], &KHs[nrow * ASLD + koff]);
                    ldsm4(kbl[ntp], &KLs[nrow * ASLD + koff]);
                }
#pragma unroll
                for (int ntp = 0; ntp < 2; ntp++)
#pragma unroll
                    for (int q = 0; q < 2; q++)
                        mma_bf16(sc[ntp * 2 + q], aqh, kbh[ntp][q * 2], kbh[ntp][q * 2 + 1]);
#pragma unroll
                for (int ntp = 0; ntp < 2; ntp++)
#pragma unroll
                    for (int q = 0; q < 2; q++)
                        mma_bf16(sc[ntp * 2 + q], aqh, kbl[ntp][q * 2], kbl[ntp][q * 2 + 1]);
#pragma unroll
                for (int ntp = 0; ntp < 2; ntp++)
#pragma unroll
                    for (int q = 0; q < 2; q++)
                        mma_bf16(sc[ntp * 2 + q], aql, kbh[ntp][q * 2], kbh[ntp][q * 2 + 1]);
            }

#pragma unroll
            for (int ntl = 0; ntl < 4; ntl++) {
                const int nt = half * 4 + ntl;
                const int kch = nt >> 1, q = nt & 1;
                const int colg = kt0 + nt * 8 + 2 * t;
                const bool v0c = colg < cnt;
                const bool v1c = colg + 1 < cnt;
                float p0 = v0c ? __expf(sc[ntl][0] * scale) : 0.0f;
                float p1 = v1c ? __expf(sc[ntl][1] * scale) : 0.0f;
                float p2 = v0c ? __expf(sc[ntl][2] * scale) : 0.0f;
                float p3 = v1c ? __expf(sc[ntl][3] * scale) : 0.0f;
                lsum0 += p0 + p1;
                lsum8 += p2 + p3;
                bf16 h0, l0, h1, l1, h2, l2, h3, l3;
                split1(p0, h0, l0); split1(p1, h1, l1);
                split1(p2, h2, l2); split1(p3, h3, l3);
                pah[kch][q * 2 + 0] = pack2(h0, h1);
                pah[kch][q * 2 + 1] = pack2(h2, h3);
                pal[kch][q * 2 + 0] = pack2(l0, l1);
                pal[kch][q * 2 + 1] = pack2(l2, l3);
            }
        }

#pragma unroll
        for (int kch = 0; kch < 4; kch++) {
            const int keyrow = kch * 16 + (tile & 1) * 8 + trow;
            unsigned vh[4][4], vl[4][4];
#pragma unroll
            for (int dp = 0; dp < 4; dp++) {
                const int dcol = dp * 16 + (tile >> 1) * 8;
                ldsm4t(vh[dp], &VHs[keyrow * ASLD + dcol]);
                ldsm4t(vl[dp], &VLs[keyrow * ASLD + dcol]);
            }
#pragma unroll
            for (int dp = 0; dp < 4; dp++)
#pragma unroll
                for (int q = 0; q < 2; q++)
                    mma_bf16(O[dp * 2 + q], pah[kch], vh[dp][q * 2], vh[dp][q * 2 + 1]);
#pragma unroll
            for (int dp = 0; dp < 4; dp++)
#pragma unroll
                for (int q = 0; q < 2; q++)
                    mma_bf16(O[dp * 2 + q], pah[kch], vl[dp][q * 2], vl[dp][q * 2 + 1]);
#pragma unroll
            for (int dp = 0; dp < 4; dp++)
#pragma unroll
                for (int q = 0; q < 2; q++)
                    mma_bf16(O[dp * 2 + q], pal[kch], vh[dp][q * 2], vh[dp][q * 2 + 1]);
        }
        __syncthreads();
        buf ^= 1;
    }

    const size_t row0 = (size_t)(b * NN + q0 + rb + g);
    const size_t row8 = row0 + 8;
    if (cnt == 0) {
#pragma unroll
        for (int nt = 0; nt < 8; nt++) {
            const int d = h * 64 + nt * 8 + 2 * t;
            float m0 = g_vmean[b * INNER + d];
            float m1 = g_vmean[b * INNER + d + 1];
            bf16 h0, l0, h1, l1;
            split1(m0, h0, l0); split1(m1, h1, l1);
            unsigned ph = pack2(h0, h1), pl = pack2(l0, l1);
            *reinterpret_cast<unsigned*>(&g_atc_h[row0 * INNER + d]) = ph;
            *reinterpret_cast<unsigned*>(&g_atc_l[row0 * INNER + d]) = pl;
            *reinterpret_cast<unsigned*>(&g_atc_h[row8 * INNER + d]) = ph;
            *reinterpret_cast<unsigned*>(&g_atc_l[row8 * INNER + d]) = pl;
        }
        return;
    }
    lsum0 += __shfl_xor_sync(0xffffffffu, lsum0, 1);
    lsum0 += __shfl_xor_sync(0xffffffffu, lsum0, 2);
    lsum8 += __shfl_xor_sync(0xffffffffu, lsum8, 1);
    lsum8 += __shfl_xor_sync(0xffffffffu, lsum8, 2);
    const float inv0 = 1.0f / lsum0;
    const float inv8 = 1.0f / lsum8;

#pragma unroll
    for (int nt = 0; nt < 8; nt++) {
        const int d = h * 64 + nt * 8 + 2 * t;
        float v0 = O[nt][0] * inv0, v1 = O[nt][1] * inv0;
        float v2 = O[nt][2] * inv8, v3 = O[nt][3] * inv8;
        bf16 h0, l0, h1, l1, h2, l2, h3, l3;
        split1(v0, h0, l0); split1(v1, h1, l1);
        split1(v2, h2, l2); split1(v3, h3, l3);
        *reinterpret_cast<unsigned*>(&g_atc_h[row0 * INNER + d]) = pack2(h0, h1);
        *reinterpret_cast<unsigned*>(&g_atc_l[row0 * INNER + d]) = pack2(l0, l1);
        *reinterpret_cast<unsigned*>(&g_atc_h[row8 * INNER + d]) = pack2(h2, h3);
        *reinterpret_cast<unsigned*>(&g_atc_l[row8 * INNER + d]) = pack2(l2, l3);
    }
}

// ---------------------------------------------------------------------------
extern "C" void kernel_launch(void* const* d_in, const int* in_sizes, int n_in,
                              void* d_out, int out_size)
{
    const float* x     = (const float*)d_in[0];
    const int*   mnp   = (const int*)d_in[1];
    const int*   mbert = (const int*)d_in[2];
    const float* Wqkv  = (const float*)d_in[3];
    const float* Wout  = (const float*)d_in[4];
    const float* bout  = (const float*)d_in[5];
    float* out = (float*)d_out;

    cudaFuncSetAttribute(gemm_proj, cudaFuncAttributeMaxDynamicSharedMemorySize,
                         GEMM_SMEM_BYTES);
    cudaFuncSetAttribute(gemm_out, cudaFuncAttributeMaxDynamicSharedMemorySize,
                         GEMM_SMEM_BYTES);
    cudaFuncSetAttribute(attn_mma, cudaFuncAttributeMaxDynamicSharedMemorySize,
                         ATT_SMEM_BYTES);

    // Fork/join: side stream runs the (input-independent) mean chain and
    // dead-row fill concurrently with the main tensor pipeline.
    cudaStream_t s2;
    cudaStreamCreateWithFlags(&s2, cudaStreamNonBlocking);
    cudaEvent_t e0, e_bb, e_chain, e_df;
    cudaEventCreateWithFlags(&e0,      cudaEventDisableTiming);
    cudaEventCreateWithFlags(&e_bb,    cudaEventDisableTiming);
    cudaEventCreateWithFlags(&e_chain, cudaEventDisableTiming);
    cudaEventCreateWithFlags(&e_df,    cudaEventDisableTiming);

    // fork point
    cudaEventRecord(e0, 0);
    cudaStreamWaitEvent(s2, e0, 0);

    // main stream: split + compaction + projections
    split3_kernel<<<512, 256>>>(x, Wqkv, Wout);
    build_both<<<dim3(2, BB), 256>>>(mnp, mbert);
    cudaEventRecord(e_bb, 0);
    gemm_proj<<<dim3(12, MROWS / 128), 512, GEMM_SMEM_BYTES>>>();

    // side stream: mean chain (reads raw fp32 inputs only)
    meanx_part<<<dim3(DIM / 64, BB, 8), dim3(64, 8), 0, s2>>>(x);
    vmean_part<<<dim3(INNER / 64, BB, 8), dim3(64, 8), 0, s2>>>(Wqkv);
    deadvec_fused<<<dim3(DIM / 64, BB), dim3(64, 16), 0, s2>>>(Wout, bout);
    cudaEventRecord(e_chain, s2);
    // dead rows of the output (needs g_dead + g_qpos; disjoint from gemm_out)
    cudaStreamWaitEvent(s2, e_bb, 0);
    dead_fill<<<dim3(NN, BB), 128, 0, s2>>>(out);
    cudaEventRecord(e_df, s2);

    // main stream: attention (uses g_vmean in the cnt==0 path -> join chain)
    cudaStreamWaitEvent(0, e_chain, 0);
    attn_mma<<<dim3(NN / 128, BB * HH), 256, ATT_SMEM_BYTES>>>();

    // output projection for alive rows
    gemm_out<<<dim3(DIM / 128, MROWS / 128), 512, GEMM_SMEM_BYTES>>>(bout, out);

    // join side stream before returning
    cudaStreamWaitEvent(0, e_df, 0);
}

// round 14
// speedup vs baseline: 2.9899x; 1.0321x over previous
#include <cuda_runtime.h>
#include <cuda_bf16.h>
#include <math.h>

#define BB    2
#define NN    2048
#define DIM   512
#define HH    8
#define DH    64
#define INNER 512
#define QKV3  1536
#define MROWS (BB*NN)      // 4096

typedef __nv_bfloat16 bf16;

// ---------------- device scratch (no allocation allowed) ----------------
__device__ bf16 g_x_h[MROWS * DIM],    g_x_l[MROWS * DIM];
__device__ bf16 g_wqkv_h[DIM * QKV3],  g_wqkv_l[DIM * QKV3];
__device__ bf16 g_wout_h[INNER * DIM], g_wout_l[INNER * DIM];

// key compaction + fused K|V buffer (K at col 0..511, V at col 512..1023)
__device__ int  g_cnt[BB];
__device__ int  g_idx[BB * NN];
__device__ bf16 g_kvc_h[BB * NN * 1024], g_kvc_l[BB * NN * 1024];
__device__ float g_xpart[BB * 8 * DIM];
__device__ float g_vmpart[BB * 8 * INNER];
__device__ float g_vmean[BB * INNER];
__device__ float g_dead[BB * DIM];

// query compaction
__device__ int  g_qcnt[BB];
__device__ int  g_qidx[BB * NN];
__device__ int  g_qpos[BB * NN];
__device__ bf16 g_qc_h[BB * NN * INNER], g_qc_l[BB * NN * INNER];
__device__ bf16 g_atc_h[BB * NN * INNER], g_atc_l[BB * NN * INNER];

// ---------------- helpers ----------------
__device__ __forceinline__ unsigned s2u(const void* p) {
    return (unsigned)__cvta_generic_to_shared(p);
}
__device__ __forceinline__ void ldsm4(unsigned* r, const void* p) {
    asm volatile("ldmatrix.sync.aligned.m8n8.x4.shared.b16 {%0,%1,%2,%3}, [%4];"
        : "=r"(r[0]), "=r"(r[1]), "=r"(r[2]), "=r"(r[3]) : "r"(s2u(p)));
}
__device__ __forceinline__ void ldsm4t(unsigned* r, const void* p) {
    asm volatile("ldmatrix.sync.aligned.m8n8.x4.trans.shared.b16 {%0,%1,%2,%3}, [%4];"
        : "=r"(r[0]), "=r"(r[1]), "=r"(r[2]), "=r"(r[3]) : "r"(s2u(p)));
}
__device__ __forceinline__ void cp16(void* s, const void* g) {
    asm volatile("cp.async.cg.shared.global [%0], [%1], 16;" :: "r"(s2u(s)), "l"(g));
}
__device__ __forceinline__ void cp_commit() { asm volatile("cp.async.commit_group;"); }
template<int N> __device__ __forceinline__ void cp_wait() {
    asm volatile("cp.async.wait_group %0;" :: "n"(N));
}
__device__ __forceinline__ void mma_bf16(float* c, const unsigned* a, unsigned b0, unsigned b1) {
    asm volatile(
        "mma.sync.aligned.m16n8k16.row.col.f32.bf16.bf16.f32 "
        "{%0,%1,%2,%3}, {%4,%5,%6,%7}, {%8,%9}, {%0,%1,%2,%3};"
        : "+f"(c[0]), "+f"(c[1]), "+f"(c[2]), "+f"(c[3])
        : "r"(a[0]), "r"(a[1]), "r"(a[2]), "r"(a[3]), "r"(b0), "r"(b1));
}
__device__ __forceinline__ unsigned pack2(bf16 a, bf16 b) {
    __nv_bfloat162 v; v.x = a; v.y = b;
    return *reinterpret_cast<unsigned*>(&v);
}
__device__ __forceinline__ void split1(float v, bf16& h, bf16& l) {
    h = __float2bfloat16(v);
    l = __float2bfloat16(v - __bfloat162float(h));
}
// vectorized: split 4 consecutive floats -> 2 packed uints (hi), 2 (lo)
__device__ __forceinline__ void split4(const float4 v, uint2& ho, uint2& lo) {
    bf16 h0, l0, h1, l1, h2, l2, h3, l3;
    split1(v.x, h0, l0); split1(v.y, h1, l1);
    split1(v.z, h2, l2); split1(v.w, h3, l3);
    ho.x = pack2(h0, h1); ho.y = pack2(h2, h3);
    lo.x = pack2(l0, l1); lo.y = pack2(l2, l3);
}

// ---------------- prep: vectorized splits ----------------
__global__ void split_xw(const float* __restrict__ x, const float* __restrict__ wqkv)
{
    const int n1 = (MROWS * DIM) / 4, n2 = (DIM * QKV3) / 4;
    const int total = n1 + n2;
    for (int i = blockIdx.x * blockDim.x + threadIdx.x; i < total;
         i += gridDim.x * blockDim.x) {
        float4 v; bf16 *hi, *lo; int off;
        if (i < n1) { off = i * 4; v = *reinterpret_cast<const float4*>(&x[off]);
                      hi = g_x_h; lo = g_x_l; }
        else        { off = (i - n1) * 4; v = *reinterpret_cast<const float4*>(&wqkv[off]);
                      hi = g_wqkv_h; lo = g_wqkv_l; }
        uint2 ho, lw; split4(v, ho, lw);
        *reinterpret_cast<uint2*>(&hi[off]) = ho;
        *reinterpret_cast<uint2*>(&lo[off]) = lw;
    }
}
__global__ void split_wout(const float* __restrict__ wout)
{
    const int total = (INNER * DIM) / 4;
    for (int i = blockIdx.x * blockDim.x + threadIdx.x; i < total;
         i += gridDim.x * blockDim.x) {
        int off = i * 4;
        float4 v = *reinterpret_cast<const float4*>(&wout[off]);
        uint2 ho, lw; split4(v, ho, lw);
        *reinterpret_cast<uint2*>(&g_wout_h[off]) = ho;
        *reinterpret_cast<uint2*>(&g_wout_l[off]) = lw;
    }
}

// ---------------- fused compactions (parallel scan); grid (2, BB) -----------
__global__ void build_both(const int* __restrict__ mnp, const int* __restrict__ mbert)
{
    const int b = blockIdx.y;
    const bool isQ = (blockIdx.x == 1);
    const int tid = threadIdx.x;
    __shared__ int scan[256];

    int flags[8];
    int local = 0;
#pragma unroll
    for (int k = 0; k < 8; k++) {
        int j = tid * 8 + k;
        int f;
        if (isQ) f = (mnp[b * NN + j] == 1);
        else     f = (mnp[b * NN + j] == 1) && (mbert[b * NN + j] == 0);
        flags[k] = f; local += f;
    }
    scan[tid] = local;
    __syncthreads();
#pragma unroll
    for (int off = 1; off < 256; off <<= 1) {
        int add = (tid >= off) ? scan[tid - off] : 0;
        __syncthreads();
        scan[tid] += add;
        __syncthreads();
    }
    const int tot = scan[255];
    int o = scan[tid] - local;
    if (isQ) {
        if (tid == 0) g_qcnt[b] = tot;
#pragma unroll
        for (int k = 0; k < 8; k++) {
            int j = tid * 8 + k;
            if (flags[k]) { g_qidx[b * NN + o] = j; g_qpos[b * NN + j] = o; o++; }
            else g_qpos[b * NN + j] = -1;
        }
        for (int i = tot + tid; i < NN; i += 256) g_qidx[b * NN + i] = 0;
    } else {
        if (tid == 0) g_cnt[b] = tot;
#pragma unroll
        for (int k = 0; k < 8; k++) {
            if (flags[k]) g_idx[b * NN + (o++)] = tid * 8 + k;
        }
        for (int i = tot + tid; i < NN; i += 256) g_idx[b * NN + i] = 0;
    }
}

// ---------------- partial sums of x rows: grid (DIM/64, BB, 8) --------------
__global__ void meanx_part(const float* __restrict__ x)
{
    const int b = blockIdx.y;
    const int z = blockIdx.z;
    const int d = blockIdx.x * 64 + threadIdx.x;
    const int yg = threadIdx.y;
    float s = 0.0f;
    const int r0 = z * 256;
    for (int j = yg; j < 256; j += 8)
        s += x[((size_t)(b * NN + r0 + j)) * DIM + d];
    __shared__ float red[8][64];
    red[yg][threadIdx.x] = s;
    __syncthreads();
    if (yg == 0) {
        float tot = 0.0f;
#pragma unroll
        for (int i = 0; i < 8; i++) tot += red[i][threadIdx.x];
        g_xpart[(b * 8 + z) * DIM + d] = tot;
    }
}

// ---------------- vmean partials: grid (INNER/64, BB, 8 d-chunks) -----------
__global__ void vmean_part(const float* __restrict__ Wqkv)
{
    const int b = blockIdx.y;
    const int z = blockIdx.z;
    const int col = blockIdx.x * 64 + threadIdx.x;
    const int yg = threadIdx.y;
    const int tid = yg * 64 + threadIdx.x;
    __shared__ float xm[64];
    if (tid < 64) {
        float s = 0.0f;
#pragma unroll
        for (int zz = 0; zz < 8; zz++) s += g_xpart[(b * 8 + zz) * DIM + z * 64 + tid];
        xm[tid] = s * (1.0f / NN);
    }
    __syncthreads();
    float s = 0.0f;
#pragma unroll
    for (int j = yg; j < 64; j += 8)
        s += xm[j] * Wqkv[(size_t)(z * 64 + j) * QKV3 + 2 * INNER + col];
    __shared__ float red[8][64];
    red[yg][threadIdx.x] = s;
    __syncthreads();
    if (yg == 0) {
        float tot = 0.0f;
#pragma unroll
        for (int i = 0; i < 8; i++) tot += red[i][threadIdx.x];
        g_vmpart[(b * 8 + z) * INNER + col] = tot;
    }
}

// ---------------- fused vmean combine + dead vector; grid (DIM/64, BB) ------
__global__ void deadvec_fused(const float* __restrict__ Wout,
                              const float* __restrict__ bias)
{
    const int b = blockIdx.y;
    const int col = blockIdx.x * 64 + threadIdx.x;
    const int yg = threadIdx.y;
    const int tid = yg * 64 + threadIdx.x;
    __shared__ float vm[INNER];
    if (tid < INNER) {
        float s = 0.0f;
#pragma unroll
        for (int z = 0; z < 8; z++) s += g_vmpart[(b * 8 + z) * INNER + tid];
        vm[tid] = s;
        if (blockIdx.x == 0) g_vmean[b * INNER + tid] = s;
    }
    __syncthreads();
    float s = 0.0f;
#pragma unroll 4
    for (int d = yg; d < INNER; d += 16)
        s += vm[d] * Wout[(size_t)d * DIM + col];
    __shared__ float red[16][64];
    red[yg][threadIdx.x] = s;
    __syncthreads();
    if (yg == 0) {
        float tot = bias[col];
#pragma unroll
        for (int i = 0; i < 16; i++) tot += red[i][threadIdx.x];
        g_dead[b * DIM + col] = tot;
    }
}

// ---------------- fill dead output rows -------------------------------------
__global__ void dead_fill(float* __restrict__ out)
{
    const int b = blockIdx.y;
    const int i = blockIdx.x;
    if (g_qpos[b * NN + i] >= 0) return;
    const int tid = threadIdx.x;
    *reinterpret_cast<float4*>(&out[((size_t)(b * NN + i)) * DIM + tid * 4]) =
        *reinterpret_cast<const float4*>(&g_dead[b * DIM + tid * 4]);
}

// ---------------------------------------------------------------------------
// bf16x3 GEMM body, 128x128 block, BK=32, 512 thr (16 warps; warp tile 32x32).
// ---------------------------------------------------------------------------
#define GALD 40
#define GBLD 136
#define G_SA(buf,hl) (sm + ((buf)*2 + (hl)) * (128*GALD))
#define G_SB(buf,hl) (sm + 4*128*GALD + ((buf)*2 + (hl)) * (32*GBLD))
#define GEMM_SMEM_BYTES ((4*128*GALD + 4*32*GBLD) * 2)

__device__ __forceinline__ void gemm_body(bf16* sm, int bm, int bn,
                                          const bf16* __restrict__ Ah,
                                          const bf16* __restrict__ Al,
                                          int lda,
                                          const int* __restrict__ ridx,
                                          const int* __restrict__ cntp,
                                          const bf16* __restrict__ Bh,
                                          const bf16* __restrict__ Bl,
                                          int ldb,
                                          const float* __restrict__ bias,
                                          float* __restrict__ outf,
                                          bf16* __restrict__ outh,
                                          bf16* __restrict__ outl,
                                          int ldo,
                                          const int* __restrict__ oidx,
                                          int K, int mode)
{
    const int b  = bm >> 11;                 // NN = 2048
    const int lm = bm & (NN - 1);
    const int bbase = b * NN;

    int cntv = NN;
    if (cntp) {
        cntv = cntp[b];
        if (lm >= ((cntv + 127) & ~127)) return;
    }

    const int tid = threadIdx.x;
    const int warp = tid >> 5;
    const int lane = tid & 31;
    const int g = lane >> 2;
    const int t = lane & 3;
    const int rowbase = (warp & 3) * 32;
    const int colbase = (warp >> 2) * 32;

    float acc[2][4][4];
#pragma unroll
    for (int mt = 0; mt < 2; mt++)
#pragma unroll
        for (int nt = 0; nt < 4; nt++)
#pragma unroll
            for (int i = 0; i < 4; i++) acc[mt][nt][i] = 0.0f;

    const int tile = lane >> 3;
    const int trow = lane & 7;

    const int arow = tid >> 2;
    const int akch = (tid & 3) * 8;
    int agrow;
    if (ridx) agrow = bbase + ridx[bbase + lm + arow];
    else      agrow = bm + arow;

    auto prefetch = [&](int buf, int k0) {
        {
            size_t go = (size_t)agrow * lda + k0 + akch;
            cp16(&G_SA(buf, 0)[arow * GALD + akch], &Ah[go]);
            cp16(&G_SA(buf, 1)[arow * GALD + akch], &Al[go]);
        }
        {
            int kr = tid >> 4, nch = (tid & 15) * 8;
            size_t go = (size_t)(k0 + kr) * ldb + bn + nch;
            cp16(&G_SB(buf, 0)[kr * GBLD + nch], &Bh[go]);
            cp16(&G_SB(buf, 1)[kr * GBLD + nch], &Bl[go]);
        }
    };

    prefetch(0, 0);
    cp_commit();

    const int NIT = K / 32;
    int buf = 0;
    for (int it = 0; it < NIT; it++) {
        if (it + 1 < NIT) { prefetch(buf ^ 1, (it + 1) * 32); cp_commit(); cp_wait<1>(); }
        else cp_wait<0>();
        __syncthreads();

        const bf16* As_h = G_SA(buf, 0);
        const bf16* As_l = G_SA(buf, 1);
        const bf16* Bs_h = G_SB(buf, 0);
        const bf16* Bs_l = G_SB(buf, 1);

#pragma unroll
        for (int kc = 0; kc < 2; kc++) {
            unsigned ah[2][4], al[2][4];
            const int amrow = (tile & 1) * 8 + trow;
            const int akoff = kc * 16 + (tile >> 1) * 8;
#pragma unroll
            for (int mt = 0; mt < 2; mt++) {
                ldsm4(ah[mt], &As_h[(rowbase + mt * 16 + amrow) * GALD + akoff]);
                ldsm4(al[mt], &As_l[(rowbase + mt * 16 + amrow) * GALD + akoff]);
            }
            const int bkrow = kc * 16 + (tile & 1) * 8 + trow;
            unsigned bh[2][4], bl[2][4];
#pragma unroll
            for (int ntp = 0; ntp < 2; ntp++) {
                const int bncol = colbase + ntp * 16 + (tile >> 1) * 8;
                ldsm4t(bh[ntp], &Bs_h[bkrow * GBLD + bncol]);
                ldsm4t(bl[ntp], &Bs_l[bkrow * GBLD + bncol]);
            }
#pragma unroll
            for (int mt = 0; mt < 2; mt++)
#pragma unroll
                for (int ntp = 0; ntp < 2; ntp++)
#pragma unroll
                    for (int q = 0; q < 2; q++)
                        mma_bf16(acc[mt][ntp * 2 + q], ah[mt], bh[ntp][q * 2], bh[ntp][q * 2 + 1]);
#pragma unroll
            for (int mt = 0; mt < 2; mt++)
#pragma unroll
                for (int ntp = 0; ntp < 2; ntp++)
#pragma unroll
                    for (int q = 0; q < 2; q++)
                        mma_bf16(acc[mt][ntp * 2 + q], ah[mt], bl[ntp][q * 2], bl[ntp][q * 2 + 1]);
#pragma unroll
            for (int mt = 0; mt < 2; mt++)
#pragma unroll
                for (int ntp = 0; ntp < 2; ntp++)
#pragma unroll
                    for (int q = 0; q < 2; q++)
                        mma_bf16(acc[mt][ntp * 2 + q], al[mt], bh[ntp][q * 2], bh[ntp][q * 2 + 1]);
        }
        __syncthreads();
        buf ^= 1;
    }

#pragma unroll
    for (int mt = 0; mt < 2; mt++) {
        const int lr0 = lm + rowbase + mt * 16 + g;
        const int lr1 = lr0 + 8;
#pragma unroll
        for (int nt = 0; nt < 4; nt++) {
            const int c0 = bn + colbase + nt * 8 + 2 * t;
            float v0 = acc[mt][nt][0], v1 = acc[mt][nt][1];
            float v2 = acc[mt][nt][2], v3 = acc[mt][nt][3];
            if (mode == 0) {
                float b0 = bias[c0], b1 = bias[c0 + 1];
                if (lr0 < cntv) {
                    int orow = bbase + oidx[bbase + lr0];
                    *reinterpret_cast<float2*>(&outf[(size_t)orow * ldo + c0]) =
                        make_float2(v0 + b0, v1 + b1);
                }
                if (lr1 < cntv) {
                    int orow = bbase + oidx[bbase + lr1];
                    *reinterpret_cast<float2*>(&outf[(size_t)orow * ldo + c0]) =
                        make_float2(v2 + b0, v3 + b1);
                }
            } else {
                bf16 h0, l0, h1, l1, h2, l2, h3, l3;
                split1(v0, h0, l0); split1(v1, h1, l1);
                split1(v2, h2, l2); split1(v3, h3, l3);
                const size_t r0o = (size_t)(bbase + lr0) * ldo + c0;
                const size_t r1o = (size_t)(bbase + lr1) * ldo + c0;
                *reinterpret_cast<unsigned*>(&outh[r0o]) = pack2(h0, h1);
                *reinterpret_cast<unsigned*>(&outl[r0o]) = pack2(l0, l1);
                *reinterpret_cast<unsigned*>(&outh[r1o]) = pack2(h2, h3);
                *reinterpret_cast<unsigned*>(&outl[r1o]) = pack2(l2, l3);
            }
        }
    }
}

// ---- fused projection GEMM: x<4 -> Q (alive rows), x>=4 -> K|V (key rows) --
__global__ __launch_bounds__(512, 1) void gemm_proj()
{
    extern __shared__ bf16 sm[];
    const int bm = blockIdx.y * 128;
    if (blockIdx.x < 4) {
        gemm_body(sm, bm, blockIdx.x * 128,
                  g_x_h, g_x_l, DIM, g_qidx, g_qcnt,
                  g_wqkv_h, g_wqkv_l, QKV3, nullptr,
                  nullptr, g_qc_h, g_qc_l, INNER, nullptr, DIM, 1);
    } else {
        gemm_body(sm, bm, (blockIdx.x - 4) * 128,
                  g_x_h, g_x_l, DIM, g_idx, g_cnt,
                  g_wqkv_h + INNER, g_wqkv_l + INNER, QKV3, nullptr,
                  nullptr, g_kvc_h, g_kvc_l, 1024, nullptr, DIM, 1);
    }
}

// ---- output GEMM: compacted att rows @ W_out + bias, scatter rows ----------
__global__ __launch_bounds__(512, 1) void gemm_out(const float* __restrict__ bias,
                                                   float* __restrict__ out)
{
    extern __shared__ bf16 sm[];
    gemm_body(sm, blockIdx.y * 128, blockIdx.x * 128,
              g_atc_h, g_atc_l, INNER, nullptr, g_qcnt,
              g_wout_h, g_wout_l, DIM, bias,
              out, nullptr, nullptr, DIM, g_qidx, INNER, 0);
}

// ---------------------------------------------------------------------------
// Attention over compacted Q rows and fused K|V buffer.
// 256 thr (8 warps), 128 q-rows/block, 64-key tiles. Q frags in registers.
// ---------------------------------------------------------------------------
#define ASLD 72
#define A_Q(hl)     (sm + (hl) * (128 * ASLD))
#define A_KV(buf,m) (sm + 2 * 128 * ASLD + ((buf) * 4 + (m)) * (64 * ASLD))
#define ATT_BF16_TOT (2 * 128 * ASLD + 8 * 64 * ASLD)
#define ATT_SMEM_BYTES (ATT_BF16_TOT * 2)

__global__ __launch_bounds__(256, 1) void attn_mma()
{
    extern __shared__ char smraw[];
    bf16* sm = reinterpret_cast<bf16*>(smraw);

    const int b  = blockIdx.y >> 3;
    const int h  = blockIdx.y & 7;
    const int q0 = blockIdx.x * 128;

    const int qcnt = g_qcnt[b];
    const int qpad = (qcnt + 127) & ~127;
    if (q0 >= qpad) return;

    const int cnt = g_cnt[b];
    const int ntiles = (cnt + 63) >> 6;

    const int tid = threadIdx.x;
    const int warp = tid >> 5;
    const int lane = tid & 31;
    const int g = lane >> 2;
    const int t = lane & 3;
    const int rb = warp * 16;
    const float scale = 0.125f;
    const int tile = lane >> 3;
    const int trow = lane & 7;

#pragma unroll
    for (int j = 0; j < 4; j++) {
        int c = tid * 4 + j;
        int row = c >> 3, dch = (c & 7) * 8;
        size_t base = (size_t)(b * NN + q0 + row) * INNER + h * 64 + dch;
        cp16(&A_Q(0)[row * ASLD + dch], &g_qc_h[base]);
        cp16(&A_Q(1)[row * ASLD + dch], &g_qc_l[base]);
    }
    cp_commit();

    auto pref = [&](int buf, int kt0) {
#pragma unroll
        for (int j = 0; j < 2; j++) {
            int c = tid * 2 + j;
            int row = c >> 3, dch = (c & 7) * 8;
            size_t base = ((size_t)(b * NN + kt0 + row)) * 1024 + h * 64 + dch;
            cp16(&A_KV(buf, 0)[row * ASLD + dch], &g_kvc_h[base]);
            cp16(&A_KV(buf, 1)[row * ASLD + dch], &g_kvc_l[base]);
            cp16(&A_KV(buf, 2)[row * ASLD + dch], &g_kvc_h[base + 512]);
            cp16(&A_KV(buf, 3)[row * ASLD + dch], &g_kvc_l[base + 512]);
        }
    };

    if (ntiles > 0) { pref(0, 0); }
    cp_commit();

    float O[8][4];
#pragma unroll
    for (int nt = 0; nt < 8; nt++)
#pragma unroll
        for (int i = 0; i < 4; i++) O[nt][i] = 0.0f;
    float lsum0 = 0.0f, lsum8 = 0.0f;

    unsigned aqh[4][4], aql[4][4];
    bool qloaded = false;
    const int qr = rb + (tile & 1) * 8 + trow;

    int buf = 0;
    for (int kt = 0; kt < ntiles; kt++) {
        const int kt0 = kt * 64;
        if (kt + 1 < ntiles) { pref(buf ^ 1, (kt + 1) * 64); cp_commit(); cp_wait<1>(); }
        else cp_wait<0>();
        __syncthreads();

        if (!qloaded) {
            qloaded = true;
#pragma unroll
            for (int kc = 0; kc < 4; kc++) {
                ldsm4(aqh[kc], &A_Q(0)[qr * ASLD + kc * 16 + (tile >> 1) * 8]);
                ldsm4(aql[kc], &A_Q(1)[qr * ASLD + kc * 16 + (tile >> 1) * 8]);
            }
        }

        const bf16* KHs = A_KV(buf, 0);
        const bf16* KLs = A_KV(buf, 1);
        const bf16* VHs = A_KV(buf, 2);
        const bf16* VLs = A_KV(buf, 3);

        unsigned pah[4][4], pal[4][4];

#pragma unroll
        for (int half = 0; half < 2; half++) {
            float sc[4][4];
#pragma unroll
            for (int nt = 0; nt < 4; nt++)
#pragma unroll
                for (int i = 0; i < 4; i++) sc[nt][i] = 0.0f;

#pragma unroll
            for (int kc = 0; kc < 4; kc++) {
                const int koff = kc * 16 + (tile & 1) * 8;
                unsigned kbh[2][4], kbl[2][4];
#pragma unroll
                for (int ntp = 0; ntp < 2; ntp++) {
                    const int nrow = (half * 2 + ntp) * 16 + (tile >> 1) * 8 + trow;
                    ldsm4(kbh[ntp], &KHs[nrow * ASLD + koff]);
                    ldsm4(kbl[ntp], &KLs[nrow * ASLD + koff]);
                }
#pragma unroll
                for (int ntp = 0; ntp < 2; ntp++)
#pragma unroll
                    for (int q = 0; q < 2; q++)
                        mma_bf16(sc[ntp * 2 + q], aqh[kc], kbh[ntp][q * 2], kbh[ntp][q * 2 + 1]);
#pragma unroll
                for (int ntp = 0; ntp < 2; ntp++)
#pragma unroll
                    for (int q = 0; q < 2; q++)
                        mma_bf16(sc[ntp * 2 + q], aqh[kc], kbl[ntp][q * 2], kbl[ntp][q * 2 + 1]);
#pragma unroll
                for (int ntp = 0; ntp < 2; ntp++)
#pragma unroll
                    for (int q = 0; q < 2; q++)
                        mma_bf16(sc[ntp * 2 + q], aql[kc], kbh[ntp][q * 2], kbh[ntp][q * 2 + 1]);
            }

#pragma unroll
            for (int ntl = 0; ntl < 4; ntl++) {
                const int nt = half * 4 + ntl;
                const int kch = nt >> 1, q = nt & 1;
                const int colg = kt0 + nt * 8 + 2 * t;
                const bool v0c = colg < cnt;
                const bool v1c = colg + 1 < cnt;
                float p0 = v0c ? __expf(sc[ntl][0] * scale) : 0.0f;
                float p1 = v1c ? __expf(sc[ntl][1] * scale) : 0.0f;
                float p2 = v0c ? __expf(sc[ntl][2] * scale) : 0.0f;
                float p3 = v1c ? __expf(sc[ntl][3] * scale) : 0.0f;
                lsum0 += p0 + p1;
                lsum8 += p2 + p3;
                bf16 h0, l0, h1, l1, h2, l2, h3, l3;
                split1(p0, h0, l0); split1(p1, h1, l1);
                split1(p2, h2, l2); split1(p3, h3, l3);
                pah[kch][q * 2 + 0] = pack2(h0, h1);
                pah[kch][q * 2 + 1] = pack2(h2, h3);
                pal[kch][q * 2 + 0] = pack2(l0, l1);
                pal[kch][q * 2 + 1] = pack2(l2, l3);
            }
        }

#pragma unroll
        for (int kch = 0; kch < 4; kch++) {
            const int keyrow = kch * 16 + (tile & 1) * 8 + trow;
            unsigned vh[4][4], vl[4][4];
#pragma unroll
            for (int dp = 0; dp < 4; dp++) {
                const int dcol = dp * 16 + (tile >> 1) * 8;
                ldsm4t(vh[dp], &VHs[keyrow * ASLD + dcol]);
                ldsm4t(vl[dp], &VLs[keyrow * ASLD + dcol]);
            }
#pragma unroll
            for (int dp = 0; dp < 4; dp++)
#pragma unroll
                for (int q = 0; q < 2; q++)
                    mma_bf16(O[dp * 2 + q], pah[kch], vh[dp][q * 2], vh[dp][q * 2 + 1]);
#pragma unroll
            for (int dp = 0; dp < 4; dp++)
#pragma unroll
                for (int q = 0; q < 2; q++)
                    mma_bf16(O[dp * 2 + q], pah[kch], vl[dp][q * 2], vl[dp][q * 2 + 1]);
#pragma unroll
            for (int dp = 0; dp < 4; dp++)
#pragma unroll
                for (int q = 0; q < 2; q++)
                    mma_bf16(O[dp * 2 + q], pal[kch], vh[dp][q * 2], vh[dp][q * 2 + 1]);
        }
        __syncthreads();
        buf ^= 1;
    }

    const size_t row0 = (size_t)(b * NN + q0 + rb + g);
    const size_t row8 = row0 + 8;
    if (cnt == 0) {
#pragma unroll
        for (int nt = 0; nt < 8; nt++) {
            const int d = h * 64 + nt * 8 + 2 * t;
            float m0 = g_vmean[b * INNER + d];
            float m1 = g_vmean[b * INNER + d + 1];
            bf16 h0, l0, h1, l1;
            split1(m0, h0, l0); split1(m1, h1, l1);
            unsigned ph = pack2(h0, h1), pl = pack2(l0, l1);
            *reinterpret_cast<unsigned*>(&g_atc_h[row0 * INNER + d]) = ph;
            *reinterpret_cast<unsigned*>(&g_atc_l[row0 * INNER + d]) = pl;
            *reinterpret_cast<unsigned*>(&g_atc_h[row8 * INNER + d]) = ph;
            *reinterpret_cast<unsigned*>(&g_atc_l[row8 * INNER + d]) = pl;
        }
        return;
    }
    lsum0 += __shfl_xor_sync(0xffffffffu, lsum0, 1);
    lsum0 += __shfl_xor_sync(0xffffffffu, lsum0, 2);
    lsum8 += __shfl_xor_sync(0xffffffffu, lsum8, 1);
    lsum8 += __shfl_xor_sync(0xffffffffu, lsum8, 2);
    const float inv0 = 1.0f / lsum0;
    const float inv8 = 1.0f / lsum8;

#pragma unroll
    for (int nt = 0; nt < 8; nt++) {
        const int d = h * 64 + nt * 8 + 2 * t;
        float v0 = O[nt][0] * inv0, v1 = O[nt][1] * inv0;
        float v2 = O[nt][2] * inv8, v3 = O[nt][3] * inv8;
        bf16 h0, l0, h1, l1, h2, l2, h3, l3;
        split1(v0, h0, l0); split1(v1, h1, l1);
        split1(v2, h2, l2); split1(v3, h3, l3);
        *reinterpret_cast<unsigned*>(&g_atc_h[row0 * INNER + d]) = pack2(h0, h1);
        *reinterpret_cast<unsigned*>(&g_atc_l[row0 * INNER + d]) = pack2(l0, l1);
        *reinterpret_cast<unsigned*>(&g_atc_h[row8 * INNER + d]) = pack2(h2, h3);
        *reinterpret_cast<unsigned*>(&g_atc_l[row8 * INNER + d]) = pack2(l2, l3);
    }
}

// ---------------------------------------------------------------------------
extern "C" void kernel_launch(void* const* d_in, const int* in_sizes, int n_in,
                              void* d_out, int out_size)
{
    const float* x     = (const float*)d_in[0];
    const int*   mnp   = (const int*)d_in[1];
    const int*   mbert = (const int*)d_in[2];
    const float* Wqkv  = (const float*)d_in[3];
    const float* Wout  = (const float*)d_in[4];
    const float* bout  = (const float*)d_in[5];
    float* out = (float*)d_out;

    cudaFuncSetAttribute(gemm_proj, cudaFuncAttributeMaxDynamicSharedMemorySize,
                         GEMM_SMEM_BYTES);
    cudaFuncSetAttribute(gemm_out, cudaFuncAttributeMaxDynamicSharedMemorySize,
                         GEMM_SMEM_BYTES);
    cudaFuncSetAttribute(attn_mma, cudaFuncAttributeMaxDynamicSharedMemorySize,
                         ATT_SMEM_BYTES);

    cudaStream_t s2;
    cudaStreamCreateWithFlags(&s2, cudaStreamNonBlocking);
    cudaEvent_t e0, e_bb, e_chain, e_wout, e_df;
    cudaEventCreateWithFlags(&e0,      cudaEventDisableTiming);
    cudaEventCreateWithFlags(&e_bb,    cudaEventDisableTiming);
    cudaEventCreateWithFlags(&e_chain, cudaEventDisableTiming);
    cudaEventCreateWithFlags(&e_wout,  cudaEventDisableTiming);
    cudaEventCreateWithFlags(&e_df,    cudaEventDisableTiming);

    // fork
    cudaEventRecord(e0, 0);
    cudaStreamWaitEvent(s2, e0, 0);

    // main stream: split x+Wqkv (vectorized)
    split_xw<<<1024, 256>>>(x, Wqkv);

    // side stream: compactions + mean chain + Wout split + dead fill
    build_both<<<dim3(2, BB), 256, 0, s2>>>(mnp, mbert);
    cudaEventRecord(e_bb, s2);
    meanx_part<<<dim3(DIM / 64, BB, 8), dim3(64, 8), 0, s2>>>(x);
    vmean_part<<<dim3(INNER / 64, BB, 8), dim3(64, 8), 0, s2>>>(Wqkv);
    deadvec_fused<<<dim3(DIM / 64, BB), dim3(64, 16), 0, s2>>>(Wout, bout);
    cudaEventRecord(e_chain, s2);
    split_wout<<<128, 256, 0, s2>>>(Wout);
    cudaEventRecord(e_wout, s2);
    dead_fill<<<dim3(NN, BB), 128, 0, s2>>>(out);
    cudaEventRecord(e_df, s2);

    // main stream: projections (needs compaction indices)
    cudaStreamWaitEvent(0, e_bb, 0);
    gemm_proj<<<dim3(12, MROWS / 128), 512, GEMM_SMEM_BYTES>>>();

    // attention (uses g_vmean in the cnt==0 path)
    cudaStreamWaitEvent(0, e_chain, 0);
    attn_mma<<<dim3(NN / 128, BB * HH), 256, ATT_SMEM_BYTES>>>();

    // output projection (needs Wout split)
    cudaStreamWaitEvent(0, e_wout, 0);
    gemm_out<<<dim3(DIM / 128, MROWS / 128), 512, GEMM_SMEM_BYTES>>>(bout, out);

    // join
    cudaStreamWaitEvent(0, e_df, 0);
}